// round 6
// baseline (speedup 1.0000x reference)
#include <cuda_runtime.h>
#include <cuda_bf16.h>
#include <cuda_fp16.h>
#include <cstdint>

#define BATCH 2
#define SEQ   2048
#define DIMSZ 1024
#define HEADS 16
#define DHEAD 64
#define INNER 1024
#define QKV3  3072
#define ROWS  (BATCH * SEQ)   // 4096

// ---------------- scratch (static device globals; no allocation) -------------
__device__ float g_qkv[ROWS * QKV3];              // 50.3 MB fp32
__device__ __nv_bfloat16 g_xnh[ROWS * DIMSZ];
__device__ __nv_bfloat16 g_xnl[ROWS * DIMSZ];
__device__ __nv_bfloat16 g_wqh[QKV3 * DIMSZ];     // Wqkv^T [3072][1024]
__device__ __nv_bfloat16 g_wql[QKV3 * DIMSZ];
__device__ __nv_bfloat16 g_woh[DIMSZ * INNER];    // Wout^T [1024][1024]
__device__ __nv_bfloat16 g_wol[DIMSZ * INNER];
__device__ __nv_bfloat16 g_aoh[ROWS * INNER];
__device__ __nv_bfloat16 g_aol[ROWS * INNER];

// ---------------- helpers ----------------------------------------------------
__device__ __forceinline__ uint32_t smem_u32(const void* p) {
    uint32_t a;
    asm("{ .reg .u64 t; cvta.to.shared.u64 t, %1; cvt.u32.u64 %0, t; }"
        : "=r"(a) : "l"(p));
    return a;
}
__device__ __forceinline__ void cp16(uint32_t dst, const void* src) {
    asm volatile("cp.async.cg.shared.global [%0], [%1], 16;"
                 :: "r"(dst), "l"(src) : "memory");
}
__device__ __forceinline__ void ldm4(uint32_t* r, uint32_t addr) {
    asm volatile("ldmatrix.sync.aligned.m8n8.x4.shared.b16 {%0,%1,%2,%3}, [%4];"
        : "=r"(r[0]), "=r"(r[1]), "=r"(r[2]), "=r"(r[3]) : "r"(addr));
}
__device__ __forceinline__ void ldm4t(uint32_t* r, uint32_t addr) {
    asm volatile("ldmatrix.sync.aligned.m8n8.x4.trans.shared.b16 {%0,%1,%2,%3}, [%4];"
        : "=r"(r[0]), "=r"(r[1]), "=r"(r[2]), "=r"(r[3]) : "r"(addr));
}
__device__ __forceinline__ void mma_bf16(float* d, const uint32_t* a,
                                         uint32_t b0, uint32_t b1) {
    asm volatile("mma.sync.aligned.m16n8k16.row.col.f32.bf16.bf16.f32 "
        "{%0,%1,%2,%3}, {%4,%5,%6,%7}, {%8,%9}, {%0,%1,%2,%3};"
        : "+f"(d[0]), "+f"(d[1]), "+f"(d[2]), "+f"(d[3])
        : "r"(a[0]), "r"(a[1]), "r"(a[2]), "r"(a[3]), "r"(b0), "r"(b1));
}
__device__ __forceinline__ void mma_f16(float* d, const uint32_t* a,
                                        uint32_t b0, uint32_t b1) {
    asm volatile("mma.sync.aligned.m16n8k16.row.col.f32.f16.f16.f32 "
        "{%0,%1,%2,%3}, {%4,%5,%6,%7}, {%8,%9}, {%0,%1,%2,%3};"
        : "+f"(d[0]), "+f"(d[1]), "+f"(d[2]), "+f"(d[3])
        : "r"(a[0]), "r"(a[1]), "r"(a[2]), "r"(a[3]), "r"(b0), "r"(b1));
}
__device__ __forceinline__ void mma_tf32(float* d, const uint32_t* a,
                                         uint32_t b0, uint32_t b1) {
    asm volatile("mma.sync.aligned.m16n8k8.row.col.f32.tf32.tf32.f32 "
        "{%0,%1,%2,%3}, {%4,%5,%6,%7}, {%8,%9}, {%0,%1,%2,%3};"
        : "+f"(d[0]), "+f"(d[1]), "+f"(d[2]), "+f"(d[3])
        : "r"(a[0]), "r"(a[1]), "r"(a[2]), "r"(a[3]), "r"(b0), "r"(b1));
}
__device__ __forceinline__ uint32_t to_tf32(float f) {
    uint32_t r; asm("cvt.rna.tf32.f32 %0, %1;" : "=r"(r) : "f"(f)); return r;
}
__device__ __forceinline__ uint32_t h2u(float a, float b) {
    __half2 h = __floats2half2_rn(a, b);
    return *reinterpret_cast<uint32_t*>(&h);
}
__device__ __forceinline__ void split_bf16(float v, __nv_bfloat16& h, __nv_bfloat16& l) {
    h = __float2bfloat16(v);
    l = __float2bfloat16(v - __bfloat162float(h));
}

// ---------------- LayerNorm -> split bf16 ------------------------------------
__global__ void __launch_bounds__(256) ln_split_kernel(
    const float* __restrict__ x, const float* __restrict__ gamma,
    const float* __restrict__ beta,
    __nv_bfloat16* __restrict__ oh, __nv_bfloat16* __restrict__ ol)
{
    int row = blockIdx.x;
    int t = threadIdx.x;
    const float4* xr = reinterpret_cast<const float4*>(x + (size_t)row * DIMSZ);
    float4 v = xr[t];
    float s  = v.x + v.y + v.z + v.w;
    float ss = v.x*v.x + v.y*v.y + v.z*v.z + v.w*v.w;
    #pragma unroll
    for (int o = 16; o; o >>= 1) {
        s  += __shfl_xor_sync(0xffffffffu, s,  o);
        ss += __shfl_xor_sync(0xffffffffu, ss, o);
    }
    __shared__ float sbuf[8], ssbuf[8];
    __shared__ float s_mu, s_rstd;
    int w = t >> 5, lane = t & 31;
    if (lane == 0) { sbuf[w] = s; ssbuf[w] = ss; }
    __syncthreads();
    if (t == 0) {
        float S = 0.f, SS = 0.f;
        #pragma unroll
        for (int i = 0; i < 8; i++) { S += sbuf[i]; SS += ssbuf[i]; }
        float mu = S * (1.0f / DIMSZ);
        float var = SS * (1.0f / DIMSZ) - mu * mu;
        s_mu = mu; s_rstd = rsqrtf(var + 1e-5f);
    }
    __syncthreads();
    float mu = s_mu, rstd = s_rstd;
    float4 g  = reinterpret_cast<const float4*>(gamma)[t];
    float4 bt = reinterpret_cast<const float4*>(beta)[t];
    float o0 = (v.x - mu) * rstd * g.x + bt.x;
    float o1 = (v.y - mu) * rstd * g.y + bt.y;
    float o2 = (v.z - mu) * rstd * g.z + bt.z;
    float o3 = (v.w - mu) * rstd * g.w + bt.w;
    __nv_bfloat16 h0,h1,h2,h3,l0,l1,l2,l3;
    split_bf16(o0,h0,l0); split_bf16(o1,h1,l1);
    split_bf16(o2,h2,l2); split_bf16(o3,h3,l3);
    size_t base = (size_t)row * DIMSZ + t * 4;
    __nv_bfloat162* oh2 = reinterpret_cast<__nv_bfloat162*>(oh + base);
    __nv_bfloat162* ol2 = reinterpret_cast<__nv_bfloat162*>(ol + base);
    oh2[0] = __nv_bfloat162(h0,h1); oh2[1] = __nv_bfloat162(h2,h3);
    ol2[0] = __nv_bfloat162(l0,l1); ol2[1] = __nv_bfloat162(l2,l3);
}

// ------------- weight transpose + split: in [K][N] fp32 -> out [N][K] bf16 ---
__global__ void __launch_bounds__(256) transpose_split_kernel(
    const float* __restrict__ in, __nv_bfloat16* __restrict__ oh,
    __nv_bfloat16* __restrict__ ol, int K, int N)
{
    __shared__ float t[32][33];
    int n0 = blockIdx.x * 32, k0 = blockIdx.y * 32;
    int tx = threadIdx.x, ty = threadIdx.y;  // 32 x 8
    #pragma unroll
    for (int i = 0; i < 4; i++)
        t[ty + i*8][tx] = in[(size_t)(k0 + ty + i*8) * N + n0 + tx];
    __syncthreads();
    #pragma unroll
    for (int i = 0; i < 4; i++) {
        float v = t[tx][ty + i*8];
        __nv_bfloat16 h, l;
        split_bf16(v, h, l);
        size_t o = (size_t)(n0 + ty + i*8) * K + k0 + tx;
        oh[o] = h; ol[o] = l;
    }
}

// ---------------- warp-mma split-bf16 GEMM -----------------------------------
// C[M,Ntot] = A[M,1024] @ B[Ntot,1024]^T, K=1024, split hi/lo, 3 MMA passes.
// CTA 128x128, BK=16, 8 warps (2m x 4n), warp tile 64x32.
// 48B-padded rows (conflict-free ldmatrix), 2-stage cp.async, 2 CTAs/SM.
// MMA passes ordered hh-all, lh-all, hl-all -> dep distance 16 per accumulator.
#define GS_ARR   6144                  // 128 rows * 48B
#define GS_STAGE (4 * GS_ARR)          // Ah,Al,Bh,Bl = 24576
#define GS_SMEM  (2 * GS_STAGE)        // 49152

__global__ void __launch_bounds__(256, 2) wm_gemm_kernel(
    const __nv_bfloat16* __restrict__ Ah, const __nv_bfloat16* __restrict__ Al,
    const __nv_bfloat16* __restrict__ Bh, const __nv_bfloat16* __restrict__ Bl,
    const float* __restrict__ bias, float* __restrict__ C, int Ntot)
{
    extern __shared__ char sm[];
    const int tid = threadIdx.x, lane = tid & 31, wid = tid >> 5;
    const int wm = wid >> 2, wn = wid & 3;
    const int c0 = blockIdx.x * 128, r0 = blockIdx.y * 128;
    uint32_t sbase = smem_u32(sm);

    auto issue = [&](int c, int st) {
        int k0 = c * 16;
        #pragma unroll
        for (int i = 0; i < 4; i++) {
            int arr = i;
            int row = tid >> 1, kc = tid & 1;
            const __nv_bfloat16* s;
            if (arr == 0)      s = Ah + (size_t)(r0 + row) * 1024 + k0 + kc * 8;
            else if (arr == 1) s = Al + (size_t)(r0 + row) * 1024 + k0 + kc * 8;
            else if (arr == 2) s = Bh + (size_t)(c0 + row) * 1024 + k0 + kc * 8;
            else               s = Bl + (size_t)(c0 + row) * 1024 + k0 + kc * 8;
            cp16(sbase + st * GS_STAGE + arr * GS_ARR + row * 48 + kc * 16, s);
        }
        asm volatile("cp.async.commit_group;" ::: "memory");
    };

    float acc[4][4][4];
    #pragma unroll
    for (int a = 0; a < 4; a++)
        #pragma unroll
        for (int b = 0; b < 4; b++)
            #pragma unroll
            for (int cc = 0; cc < 4; cc++) acc[a][b][cc] = 0.f;

    issue(0, 0);

    const int mat  = lane >> 3;
    const int roff = (mat & 1) * 8 + (lane & 7);
    const int cofs = (mat >> 1) * 16;

    const int NCHUNK = 1024 / 16;   // 64
    for (int c = 0; c < NCHUNK; c++) {
        if (c + 1 < NCHUNK) {
            issue(c + 1, (c + 1) & 1);
            asm volatile("cp.async.wait_group 1;" ::: "memory");
        } else {
            asm volatile("cp.async.wait_group 0;" ::: "memory");
        }
        __syncthreads();
        uint32_t base = sbase + (c & 1) * GS_STAGE;

        uint32_t ah[4][4], alr[4][4], bh[2][4], blr[2][4];
        #pragma unroll
        for (int nt2 = 0; nt2 < 2; nt2++) {
            uint32_t bd = base + 2*GS_ARR + (wn*32 + nt2*16 + roff) * 48 + cofs;
            ldm4(bh[nt2], bd);
            ldm4(blr[nt2], bd + GS_ARR);
        }
        #pragma unroll
        for (int mt = 0; mt < 4; mt++) {
            uint32_t ad = base + (wm*64 + mt*16 + roff) * 48 + cofs;
            ldm4(ah[mt], ad);
            ldm4(alr[mt], ad + GS_ARR);
        }
        // pass 1: hi*hi (16 independent accumulators)
        #pragma unroll
        for (int mt = 0; mt < 4; mt++)
            #pragma unroll
            for (int nt = 0; nt < 4; nt++) {
                int n2 = nt >> 1, hf = nt & 1;
                mma_bf16(acc[mt][nt], ah[mt], bh[n2][hf], bh[n2][2+hf]);
            }
        // pass 2: lo*hi
        #pragma unroll
        for (int mt = 0; mt < 4; mt++)
            #pragma unroll
            for (int nt = 0; nt < 4; nt++) {
                int n2 = nt >> 1, hf = nt & 1;
                mma_bf16(acc[mt][nt], alr[mt], bh[n2][hf], bh[n2][2+hf]);
            }
        // pass 3: hi*lo
        #pragma unroll
        for (int mt = 0; mt < 4; mt++)
            #pragma unroll
            for (int nt = 0; nt < 4; nt++) {
                int n2 = nt >> 1, hf = nt & 1;
                mma_bf16(acc[mt][nt], ah[mt], blr[n2][hf], blr[n2][2+hf]);
            }
        __syncthreads();
    }

    #pragma unroll
    for (int mt = 0; mt < 4; mt++) {
        int rbase = r0 + wm*64 + mt*16 + (lane >> 2);
        #pragma unroll
        for (int nt = 0; nt < 4; nt++) {
            int col = c0 + wn*32 + nt*8 + 2*(lane & 3);
            float b0v = bias ? bias[col] : 0.f;
            float b1v = bias ? bias[col + 1] : 0.f;
            float2 v0 = {acc[mt][nt][0] + b0v, acc[mt][nt][1] + b1v};
            float2 v1 = {acc[mt][nt][2] + b0v, acc[mt][nt][3] + b1v};
            *reinterpret_cast<float2*>(C + (size_t)rbase * Ntot + col) = v0;
            *reinterpret_cast<float2*>(C + (size_t)(rbase + 8) * Ntot + col) = v1;
        }
    }
}

// ---------------- flash attention: tf32 QK + fp16 PV -------------------------
// CTA: 128 q rows (8 warps x m16), kv-tile 64. Q prescaled by 0.125.
#define FA2_SMEM 34816   // max(Q 128*68*4, K 64*68*4 + V 64*128)

__global__ void __launch_bounds__(256, 1) fa_kernel(
    const float* __restrict__ qkv,
    __nv_bfloat16* __restrict__ outh, __nv_bfloat16* __restrict__ outl)
{
    extern __shared__ char sm[];
    uint32_t* Ks = reinterpret_cast<uint32_t*>(sm);       // [64][68] tf32
    char* Vs = sm + 64 * 68 * 4;                          // [64][128B] swizzled fp16
    uint32_t* Qs = reinterpret_cast<uint32_t*>(sm);       // [128][68] (init only)

    const int tid = threadIdx.x, lane = tid & 31, wid = tid >> 5;
    const int qt = blockIdx.x, hd = blockIdx.y, b = blockIdx.z;
    const int n0 = qt * 128;
    const int lr = lane >> 2, lc = lane & 3;

    const float* qb = qkv + (size_t)b * SEQ * QKV3 + hd * DHEAD;
    const float* kb = qb + 1024;
    const float* vb = qb + 2048;

    // stage Q (prescaled, tf32)
    #pragma unroll
    for (int i = 0; i < 8; i++) {
        int q = tid + i * 256;        // 2048 float4 chunks = 128 rows * 16
        int row = q >> 4, c4 = (q & 15) * 4;
        float4 v = *reinterpret_cast<const float4*>(qb + (size_t)(n0 + row) * QKV3 + c4);
        uint4 t;
        t.x = to_tf32(v.x * 0.125f); t.y = to_tf32(v.y * 0.125f);
        t.z = to_tf32(v.z * 0.125f); t.w = to_tf32(v.w * 0.125f);
        *reinterpret_cast<uint4*>(&Qs[row * 68 + c4]) = t;
    }
    __syncthreads();

    uint32_t qa[8][4];
    {
        int m0 = wid * 16;
        #pragma unroll
        for (int u = 0; u < 8; u++) {
            qa[u][0] = Qs[(m0 + lr)     * 68 + u*8 + lc];
            qa[u][1] = Qs[(m0 + 8 + lr) * 68 + u*8 + lc];
            qa[u][2] = Qs[(m0 + lr)     * 68 + u*8 + 4 + lc];
            qa[u][3] = Qs[(m0 + 8 + lr) * 68 + u*8 + 4 + lc];
        }
    }
    __syncthreads();

    float m_i[2] = {-1e30f, -1e30f}, l_i[2] = {0.f, 0.f};
    float o[8][4];
    #pragma unroll
    for (int v = 0; v < 8; v++)
        #pragma unroll
        for (int j = 0; j < 4; j++) o[v][j] = 0.f;

    const uint32_t vsb = smem_u32(Vs);

    for (int kt = 0; kt < SEQ / 64; kt++) {
        int s0 = kt * 64;
        #pragma unroll
        for (int i = 0; i < 4; i++) {
            int q = tid + i * 256;    // 1024 float4 chunks = 64 rows * 16
            int row = q >> 4, c4 = (q & 15) * 4;
            float4 kv = *reinterpret_cast<const float4*>(kb + (size_t)(s0 + row) * QKV3 + c4);
            uint4 t = {to_tf32(kv.x), to_tf32(kv.y), to_tf32(kv.z), to_tf32(kv.w)};
            *reinterpret_cast<uint4*>(&Ks[row * 68 + c4]) = t;
            float4 vv = *reinterpret_cast<const float4*>(vb + (size_t)(s0 + row) * QKV3 + c4);
            uint2 hp = {h2u(vv.x, vv.y), h2u(vv.z, vv.w)};
            uint32_t off = row * 128 + c4 * 2;
            off ^= ((off >> 7) & 7) << 4;
            *reinterpret_cast<uint2*>(Vs + off) = hp;
        }
        __syncthreads();

        // S = Q K^T  (tf32)
        float s[8][4];
        #pragma unroll
        for (int v = 0; v < 8; v++)
            #pragma unroll
            for (int j = 0; j < 4; j++) s[v][j] = 0.f;
        #pragma unroll
        for (int u = 0; u < 8; u++) {
            #pragma unroll
            for (int v = 0; v < 8; v++) {
                uint32_t kb0 = Ks[(v*8 + lr) * 68 + u*8 + lc];
                uint32_t kb1 = Ks[(v*8 + lr) * 68 + u*8 + 4 + lc];
                mma_tf32(s[v], qa[u], kb0, kb1);
            }
        }

        // online softmax (rows: lr and lr+8)
        #pragma unroll
        for (int h = 0; h < 2; h++) {
            float mx = -1e30f;
            #pragma unroll
            for (int v = 0; v < 8; v++)
                mx = fmaxf(mx, fmaxf(s[v][2*h], s[v][2*h+1]));
            mx = fmaxf(mx, __shfl_xor_sync(0xffffffffu, mx, 1));
            mx = fmaxf(mx, __shfl_xor_sync(0xffffffffu, mx, 2));
            float mnew = fmaxf(m_i[h], mx);
            float alpha = __expf(m_i[h] - mnew);
            m_i[h] = mnew;
            float rs = 0.f;
            #pragma unroll
            for (int v = 0; v < 8; v++) {
                s[v][2*h]   = __expf(s[v][2*h]   - mnew);
                s[v][2*h+1] = __expf(s[v][2*h+1] - mnew);
                rs += s[v][2*h] + s[v][2*h+1];
            }
            rs += __shfl_xor_sync(0xffffffffu, rs, 1);
            rs += __shfl_xor_sync(0xffffffffu, rs, 2);
            l_i[h] = l_i[h] * alpha + rs;
            #pragma unroll
            for (int v = 0; v < 8; v++) {
                o[v][2*h]   *= alpha;
                o[v][2*h+1] *= alpha;
            }
        }

        // pack P to fp16 A-fragments (k16 tiles over the 64 kv positions)
        uint32_t pa[4][4];
        #pragma unroll
        for (int u = 0; u < 4; u++) {
            pa[u][0] = h2u(s[2*u][0],   s[2*u][1]);
            pa[u][1] = h2u(s[2*u][2],   s[2*u][3]);
            pa[u][2] = h2u(s[2*u+1][0], s[2*u+1][1]);
            pa[u][3] = h2u(s[2*u+1][2], s[2*u+1][3]);
        }

        // O += P V  (fp16 MMA, fp32 accum)
        #pragma unroll
        for (int u = 0; u < 4; u++) {
            #pragma unroll
            for (int w2 = 0; w2 < 4; w2++) {
                int mt = lane >> 3;
                int row = u*16 + (mt & 1) * 8 + (lane & 7);
                int colb = w2*32 + (mt >> 1) * 16;
                uint32_t off = (uint32_t)(row * 128 + colb);
                off ^= ((off >> 7) & 7) << 4;
                uint32_t r[4];
                ldm4t(r, vsb + off);
                mma_f16(o[2*w2],     pa[u], r[0], r[1]);
                mma_f16(o[2*w2 + 1], pa[u], r[2], r[3]);
            }
        }
        __syncthreads();
    }

    // epilogue: normalize + split-bf16 store
    #pragma unroll
    for (int h = 0; h < 2; h++) {
        float inv = 1.f / l_i[h];
        int rowg = b * SEQ + n0 + wid*16 + h*8 + lr;
        #pragma unroll
        for (int v = 0; v < 8; v++) {
            int col = hd * 64 + v*8 + 2*lc;
            float f0 = o[v][2*h]   * inv;
            float f1 = o[v][2*h+1] * inv;
            __nv_bfloat16 h0, l0, h1, l1;
            split_bf16(f0, h0, l0);
            split_bf16(f1, h1, l1);
            *reinterpret_cast<__nv_bfloat162*>(outh + (size_t)rowg * INNER + col) =
                __nv_bfloat162(h0, h1);
            *reinterpret_cast<__nv_bfloat162*>(outl + (size_t)rowg * INNER + col) =
                __nv_bfloat162(l0, l1);
        }
    }
}

// ---------------- launcher ---------------------------------------------------
extern "C" void kernel_launch(void* const* d_in, const int* in_sizes, int n_in,
                              void* d_out, int out_size)
{
    const float* x     = (const float*)d_in[0];
    const float* gamma = (const float*)d_in[1];
    const float* beta  = (const float*)d_in[2];
    const float* Wqkv  = (const float*)d_in[3];
    const float* Wout  = (const float*)d_in[4];
    const float* bout  = (const float*)d_in[5];
    float* out = (float*)d_out;

    float* qkvbuf;
    __nv_bfloat16 *xnh, *xnl, *wqh, *wql, *woh, *wol, *aoh, *aol;
    cudaGetSymbolAddress((void**)&qkvbuf, g_qkv);
    cudaGetSymbolAddress((void**)&xnh, g_xnh);
    cudaGetSymbolAddress((void**)&xnl, g_xnl);
    cudaGetSymbolAddress((void**)&wqh, g_wqh);
    cudaGetSymbolAddress((void**)&wql, g_wql);
    cudaGetSymbolAddress((void**)&woh, g_woh);
    cudaGetSymbolAddress((void**)&wol, g_wol);
    cudaGetSymbolAddress((void**)&aoh, g_aoh);
    cudaGetSymbolAddress((void**)&aol, g_aol);

    cudaFuncSetAttribute(wm_gemm_kernel,
                         cudaFuncAttributeMaxDynamicSharedMemorySize, GS_SMEM);

    ln_split_kernel<<<ROWS, 256>>>(x, gamma, beta, xnh, xnl);

    transpose_split_kernel<<<dim3(QKV3 / 32, DIMSZ / 32), dim3(32, 8)>>>(
        Wqkv, wqh, wql, DIMSZ, QKV3);
    transpose_split_kernel<<<dim3(DIMSZ / 32, DIMSZ / 32), dim3(32, 8)>>>(
        Wout, woh, wol, INNER, DIMSZ);

    wm_gemm_kernel<<<dim3(QKV3 / 128, ROWS / 128), 256, GS_SMEM>>>(
        xnh, xnl, wqh, wql, nullptr, qkvbuf, QKV3);

    fa_kernel<<<dim3(SEQ / 128, HEADS, BATCH), 256, FA2_SMEM>>>(qkvbuf, aoh, aol);

    wm_gemm_kernel<<<dim3(DIMSZ / 128, ROWS / 128), 256, GS_SMEM>>>(
        aoh, aol, woh, wol, bout, out, DIMSZ);
}

// round 7
// speedup vs baseline: 1.0180x; 1.0180x over previous
#include <cuda_runtime.h>
#include <cuda_bf16.h>
#include <cuda_fp16.h>
#include <cstdint>

#define BATCH 2
#define SEQ   2048
#define DIMSZ 1024
#define HEADS 16
#define DHEAD 64
#define INNER 1024
#define QKV3  3072
#define ROWS  (BATCH * SEQ)   // 4096

// ---------------- scratch (static device globals; no allocation) -------------
__device__ float g_qkv[ROWS * QKV3];              // 50.3 MB fp32
__device__ __nv_bfloat16 g_xnh[ROWS * DIMSZ];
__device__ __nv_bfloat16 g_xnl[ROWS * DIMSZ];
__device__ __nv_bfloat16 g_wqh[QKV3 * DIMSZ];     // Wqkv^T [3072][1024]
__device__ __nv_bfloat16 g_wql[QKV3 * DIMSZ];
__device__ __nv_bfloat16 g_woh[DIMSZ * INNER];    // Wout^T [1024][1024]
__device__ __nv_bfloat16 g_wol[DIMSZ * INNER];
__device__ __nv_bfloat16 g_aoh[ROWS * INNER];
__device__ __nv_bfloat16 g_aol[ROWS * INNER];

// ---------------- helpers ----------------------------------------------------
__device__ __forceinline__ uint32_t smem_u32(const void* p) {
    uint32_t a;
    asm("{ .reg .u64 t; cvta.to.shared.u64 t, %1; cvt.u32.u64 %0, t; }"
        : "=r"(a) : "l"(p));
    return a;
}
__device__ __forceinline__ void cp16(uint32_t dst, const void* src) {
    asm volatile("cp.async.cg.shared.global [%0], [%1], 16;"
                 :: "r"(dst), "l"(src) : "memory");
}
__device__ __forceinline__ void ldm4(uint32_t* r, uint32_t addr) {
    asm volatile("ldmatrix.sync.aligned.m8n8.x4.shared.b16 {%0,%1,%2,%3}, [%4];"
        : "=r"(r[0]), "=r"(r[1]), "=r"(r[2]), "=r"(r[3]) : "r"(addr));
}
__device__ __forceinline__ void ldm4t(uint32_t* r, uint32_t addr) {
    asm volatile("ldmatrix.sync.aligned.m8n8.x4.trans.shared.b16 {%0,%1,%2,%3}, [%4];"
        : "=r"(r[0]), "=r"(r[1]), "=r"(r[2]), "=r"(r[3]) : "r"(addr));
}
__device__ __forceinline__ void mma_bf16(float* d, const uint32_t* a,
                                         uint32_t b0, uint32_t b1) {
    asm volatile("mma.sync.aligned.m16n8k16.row.col.f32.bf16.bf16.f32 "
        "{%0,%1,%2,%3}, {%4,%5,%6,%7}, {%8,%9}, {%0,%1,%2,%3};"
        : "+f"(d[0]), "+f"(d[1]), "+f"(d[2]), "+f"(d[3])
        : "r"(a[0]), "r"(a[1]), "r"(a[2]), "r"(a[3]), "r"(b0), "r"(b1));
}
__device__ __forceinline__ void mma_f16(float* d, const uint32_t* a,
                                        uint32_t b0, uint32_t b1) {
    asm volatile("mma.sync.aligned.m16n8k16.row.col.f32.f16.f16.f32 "
        "{%0,%1,%2,%3}, {%4,%5,%6,%7}, {%8,%9}, {%0,%1,%2,%3};"
        : "+f"(d[0]), "+f"(d[1]), "+f"(d[2]), "+f"(d[3])
        : "r"(a[0]), "r"(a[1]), "r"(a[2]), "r"(a[3]), "r"(b0), "r"(b1));
}
__device__ __forceinline__ void mma_tf32(float* d, const uint32_t* a,
                                         uint32_t b0, uint32_t b1) {
    asm volatile("mma.sync.aligned.m16n8k8.row.col.f32.tf32.tf32.f32 "
        "{%0,%1,%2,%3}, {%4,%5,%6,%7}, {%8,%9}, {%0,%1,%2,%3};"
        : "+f"(d[0]), "+f"(d[1]), "+f"(d[2]), "+f"(d[3])
        : "r"(a[0]), "r"(a[1]), "r"(a[2]), "r"(a[3]), "r"(b0), "r"(b1));
}
__device__ __forceinline__ uint32_t to_tf32(float f) {
    uint32_t r; asm("cvt.rna.tf32.f32 %0, %1;" : "=r"(r) : "f"(f)); return r;
}
__device__ __forceinline__ uint32_t h2u(float a, float b) {
    __half2 h = __floats2half2_rn(a, b);
    return *reinterpret_cast<uint32_t*>(&h);
}
__device__ __forceinline__ void split_bf16(float v, __nv_bfloat16& h, __nv_bfloat16& l) {
    h = __float2bfloat16(v);
    l = __float2bfloat16(v - __bfloat162float(h));
}

// ---------------- LayerNorm -> split bf16 ------------------------------------
__global__ void __launch_bounds__(256) ln_split_kernel(
    const float* __restrict__ x, const float* __restrict__ gamma,
    const float* __restrict__ beta,
    __nv_bfloat16* __restrict__ oh, __nv_bfloat16* __restrict__ ol)
{
    int row = blockIdx.x;
    int t = threadIdx.x;
    const float4* xr = reinterpret_cast<const float4*>(x + (size_t)row * DIMSZ);
    float4 v = xr[t];
    float s  = v.x + v.y + v.z + v.w;
    float ss = v.x*v.x + v.y*v.y + v.z*v.z + v.w*v.w;
    #pragma unroll
    for (int o = 16; o; o >>= 1) {
        s  += __shfl_xor_sync(0xffffffffu, s,  o);
        ss += __shfl_xor_sync(0xffffffffu, ss, o);
    }
    __shared__ float sbuf[8], ssbuf[8];
    __shared__ float s_mu, s_rstd;
    int w = t >> 5, lane = t & 31;
    if (lane == 0) { sbuf[w] = s; ssbuf[w] = ss; }
    __syncthreads();
    if (t == 0) {
        float S = 0.f, SS = 0.f;
        #pragma unroll
        for (int i = 0; i < 8; i++) { S += sbuf[i]; SS += ssbuf[i]; }
        float mu = S * (1.0f / DIMSZ);
        float var = SS * (1.0f / DIMSZ) - mu * mu;
        s_mu = mu; s_rstd = rsqrtf(var + 1e-5f);
    }
    __syncthreads();
    float mu = s_mu, rstd = s_rstd;
    float4 g  = reinterpret_cast<const float4*>(gamma)[t];
    float4 bt = reinterpret_cast<const float4*>(beta)[t];
    float o0 = (v.x - mu) * rstd * g.x + bt.x;
    float o1 = (v.y - mu) * rstd * g.y + bt.y;
    float o2 = (v.z - mu) * rstd * g.z + bt.z;
    float o3 = (v.w - mu) * rstd * g.w + bt.w;
    __nv_bfloat16 h0,h1,h2,h3,l0,l1,l2,l3;
    split_bf16(o0,h0,l0); split_bf16(o1,h1,l1);
    split_bf16(o2,h2,l2); split_bf16(o3,h3,l3);
    size_t base = (size_t)row * DIMSZ + t * 4;
    __nv_bfloat162* oh2 = reinterpret_cast<__nv_bfloat162*>(oh + base);
    __nv_bfloat162* ol2 = reinterpret_cast<__nv_bfloat162*>(ol + base);
    oh2[0] = __nv_bfloat162(h0,h1); oh2[1] = __nv_bfloat162(h2,h3);
    ol2[0] = __nv_bfloat162(l0,l1); ol2[1] = __nv_bfloat162(l2,l3);
}

// ------------- weight transpose + split: in [K][N] fp32 -> out [N][K] bf16 ---
__global__ void __launch_bounds__(256) transpose_split_kernel(
    const float* __restrict__ in, __nv_bfloat16* __restrict__ oh,
    __nv_bfloat16* __restrict__ ol, int K, int N)
{
    __shared__ float t[32][33];
    int n0 = blockIdx.x * 32, k0 = blockIdx.y * 32;
    int tx = threadIdx.x, ty = threadIdx.y;  // 32 x 8
    #pragma unroll
    for (int i = 0; i < 4; i++)
        t[ty + i*8][tx] = in[(size_t)(k0 + ty + i*8) * N + n0 + tx];
    __syncthreads();
    #pragma unroll
    for (int i = 0; i < 4; i++) {
        float v = t[tx][ty + i*8];
        __nv_bfloat16 h, l;
        split_bf16(v, h, l);
        size_t o = (size_t)(n0 + ty + i*8) * K + k0 + tx;
        oh[o] = h; ol[o] = l;
    }
}

// ---------------- warp-mma split-bf16 GEMM -----------------------------------
// C[M,Ntot] = A[M,1024] @ B[Ntot,1024]^T, K=1024, split hi/lo, 3 MMA passes.
// CTA 128x128, BK=16, 8 warps (2m x 4n), warp tile 64x32.
// 48B-padded rows (conflict-free ldmatrix), 4-stage cp.async ring,
// wait_group 2 (3 chunks of latency tolerance), ONE sync/iteration, 2 CTAs/SM.
#define GS_ARR    6144                 // 128 rows * 48B
#define GS_STAGE  (4 * GS_ARR)         // Ah,Al,Bh,Bl = 24576
#define GS_NSTAGE 4
#define GS_SMEM   (GS_NSTAGE * GS_STAGE)   // 98304

__global__ void __launch_bounds__(256, 2) wm_gemm_kernel(
    const __nv_bfloat16* __restrict__ Ah, const __nv_bfloat16* __restrict__ Al,
    const __nv_bfloat16* __restrict__ Bh, const __nv_bfloat16* __restrict__ Bl,
    const float* __restrict__ bias, float* __restrict__ C, int Ntot)
{
    extern __shared__ char sm[];
    const int tid = threadIdx.x, lane = tid & 31, wid = tid >> 5;
    const int wm = wid >> 2, wn = wid & 3;
    const int c0 = blockIdx.x * 128, r0 = blockIdx.y * 128;
    uint32_t sbase = smem_u32(sm);

    auto issue = [&](int c, int st) {
        int k0 = c * 16;
        #pragma unroll
        for (int i = 0; i < 4; i++) {
            int arr = i;
            int row = tid >> 1, kc = tid & 1;
            const __nv_bfloat16* s;
            if (arr == 0)      s = Ah + (size_t)(r0 + row) * 1024 + k0 + kc * 8;
            else if (arr == 1) s = Al + (size_t)(r0 + row) * 1024 + k0 + kc * 8;
            else if (arr == 2) s = Bh + (size_t)(c0 + row) * 1024 + k0 + kc * 8;
            else               s = Bl + (size_t)(c0 + row) * 1024 + k0 + kc * 8;
            cp16(sbase + st * GS_STAGE + arr * GS_ARR + row * 48 + kc * 16, s);
        }
        asm volatile("cp.async.commit_group;" ::: "memory");
    };

    float acc[4][4][4];
    #pragma unroll
    for (int a = 0; a < 4; a++)
        #pragma unroll
        for (int b = 0; b < 4; b++)
            #pragma unroll
            for (int cc = 0; cc < 4; cc++) acc[a][b][cc] = 0.f;

    // prologue: stages 0..2
    issue(0, 0);
    issue(1, 1);
    issue(2, 2);

    const int mat  = lane >> 3;
    const int roff = (mat & 1) * 8 + (lane & 7);
    const int cofs = (mat >> 1) * 16;

    const int NCHUNK = 1024 / 16;   // 64
    for (int c = 0; c < NCHUNK; c++) {
        // chunk c resident when <= 2 newer groups pending
        asm volatile("cp.async.wait_group 2;" ::: "memory");
        __syncthreads();   // all warps done reading stage (c-1)%4 -> safe to refill

        if (c + 3 < NCHUNK) issue(c + 3, (c + 3) & 3);
        else asm volatile("cp.async.commit_group;" ::: "memory");  // empty group keeps count uniform

        uint32_t base = sbase + (c & 3) * GS_STAGE;

        uint32_t ah[4][4], alr[4][4], bh[2][4], blr[2][4];
        #pragma unroll
        for (int nt2 = 0; nt2 < 2; nt2++) {
            uint32_t bd = base + 2*GS_ARR + (wn*32 + nt2*16 + roff) * 48 + cofs;
            ldm4(bh[nt2], bd);
            ldm4(blr[nt2], bd + GS_ARR);
        }
        #pragma unroll
        for (int mt = 0; mt < 4; mt++) {
            uint32_t ad = base + (wm*64 + mt*16 + roff) * 48 + cofs;
            ldm4(ah[mt], ad);
            ldm4(alr[mt], ad + GS_ARR);
        }
        #pragma unroll
        for (int mt = 0; mt < 4; mt++)
            #pragma unroll
            for (int nt = 0; nt < 4; nt++) {
                int n2 = nt >> 1, hf = nt & 1;
                mma_bf16(acc[mt][nt], ah[mt], bh[n2][hf], bh[n2][2+hf]);
            }
        #pragma unroll
        for (int mt = 0; mt < 4; mt++)
            #pragma unroll
            for (int nt = 0; nt < 4; nt++) {
                int n2 = nt >> 1, hf = nt & 1;
                mma_bf16(acc[mt][nt], alr[mt], bh[n2][hf], bh[n2][2+hf]);
            }
        #pragma unroll
        for (int mt = 0; mt < 4; mt++)
            #pragma unroll
            for (int nt = 0; nt < 4; nt++) {
                int n2 = nt >> 1, hf = nt & 1;
                mma_bf16(acc[mt][nt], ah[mt], blr[n2][hf], blr[n2][2+hf]);
            }
    }

    #pragma unroll
    for (int mt = 0; mt < 4; mt++) {
        int rbase = r0 + wm*64 + mt*16 + (lane >> 2);
        #pragma unroll
        for (int nt = 0; nt < 4; nt++) {
            int col = c0 + wn*32 + nt*8 + 2*(lane & 3);
            float b0v = bias ? bias[col] : 0.f;
            float b1v = bias ? bias[col + 1] : 0.f;
            float2 v0 = {acc[mt][nt][0] + b0v, acc[mt][nt][1] + b1v};
            float2 v1 = {acc[mt][nt][2] + b0v, acc[mt][nt][3] + b1v};
            *reinterpret_cast<float2*>(C + (size_t)rbase * Ntot + col) = v0;
            *reinterpret_cast<float2*>(C + (size_t)(rbase + 8) * Ntot + col) = v1;
        }
    }
}

// ---------------- flash attention: tf32 QK + fp16 PV -------------------------
// CTA: 128 q rows (8 warps x m16), kv-tile 64. Q prescaled by 0.125.
#define FA2_SMEM 34816   // max(Q 128*68*4, K 64*68*4 + V 64*128)

__global__ void __launch_bounds__(256, 1) fa_kernel(
    const float* __restrict__ qkv,
    __nv_bfloat16* __restrict__ outh, __nv_bfloat16* __restrict__ outl)
{
    extern __shared__ char sm[];
    uint32_t* Ks = reinterpret_cast<uint32_t*>(sm);       // [64][68] tf32
    char* Vs = sm + 64 * 68 * 4;                          // [64][128B] swizzled fp16
    uint32_t* Qs = reinterpret_cast<uint32_t*>(sm);       // [128][68] (init only)

    const int tid = threadIdx.x, lane = tid & 31, wid = tid >> 5;
    const int qt = blockIdx.x, hd = blockIdx.y, b = blockIdx.z;
    const int n0 = qt * 128;
    const int lr = lane >> 2, lc = lane & 3;

    const float* qb = qkv + (size_t)b * SEQ * QKV3 + hd * DHEAD;
    const float* kb = qb + 1024;
    const float* vb = qb + 2048;

    // stage Q (prescaled, tf32)
    #pragma unroll
    for (int i = 0; i < 8; i++) {
        int q = tid + i * 256;        // 2048 float4 chunks = 128 rows * 16
        int row = q >> 4, c4 = (q & 15) * 4;
        float4 v = *reinterpret_cast<const float4*>(qb + (size_t)(n0 + row) * QKV3 + c4);
        uint4 t;
        t.x = to_tf32(v.x * 0.125f); t.y = to_tf32(v.y * 0.125f);
        t.z = to_tf32(v.z * 0.125f); t.w = to_tf32(v.w * 0.125f);
        *reinterpret_cast<uint4*>(&Qs[row * 68 + c4]) = t;
    }
    __syncthreads();

    uint32_t qa[8][4];
    {
        int m0 = wid * 16;
        #pragma unroll
        for (int u = 0; u < 8; u++) {
            qa[u][0] = Qs[(m0 + lr)     * 68 + u*8 + lc];
            qa[u][1] = Qs[(m0 + 8 + lr) * 68 + u*8 + lc];
            qa[u][2] = Qs[(m0 + lr)     * 68 + u*8 + 4 + lc];
            qa[u][3] = Qs[(m0 + 8 + lr) * 68 + u*8 + 4 + lc];
        }
    }
    __syncthreads();

    float m_i[2] = {-1e30f, -1e30f}, l_i[2] = {0.f, 0.f};
    float o[8][4];
    #pragma unroll
    for (int v = 0; v < 8; v++)
        #pragma unroll
        for (int j = 0; j < 4; j++) o[v][j] = 0.f;

    const uint32_t vsb = smem_u32(Vs);

    for (int kt = 0; kt < SEQ / 64; kt++) {
        int s0 = kt * 64;
        #pragma unroll
        for (int i = 0; i < 4; i++) {
            int q = tid + i * 256;    // 1024 float4 chunks = 64 rows * 16
            int row = q >> 4, c4 = (q & 15) * 4;
            float4 kv = *reinterpret_cast<const float4*>(kb + (size_t)(s0 + row) * QKV3 + c4);
            uint4 t = {to_tf32(kv.x), to_tf32(kv.y), to_tf32(kv.z), to_tf32(kv.w)};
            *reinterpret_cast<uint4*>(&Ks[row * 68 + c4]) = t;
            float4 vv = *reinterpret_cast<const float4*>(vb + (size_t)(s0 + row) * QKV3 + c4);
            uint2 hp = {h2u(vv.x, vv.y), h2u(vv.z, vv.w)};
            uint32_t off = row * 128 + c4 * 2;
            off ^= ((off >> 7) & 7) << 4;
            *reinterpret_cast<uint2*>(Vs + off) = hp;
        }
        __syncthreads();

        // S = Q K^T  (tf32)
        float s[8][4];
        #pragma unroll
        for (int v = 0; v < 8; v++)
            #pragma unroll
            for (int j = 0; j < 4; j++) s[v][j] = 0.f;
        #pragma unroll
        for (int u = 0; u < 8; u++) {
            #pragma unroll
            for (int v = 0; v < 8; v++) {
                uint32_t kb0 = Ks[(v*8 + lr) * 68 + u*8 + lc];
                uint32_t kb1 = Ks[(v*8 + lr) * 68 + u*8 + 4 + lc];
                mma_tf32(s[v], qa[u], kb0, kb1);
            }
        }

        // online softmax (rows: lr and lr+8)
        #pragma unroll
        for (int h = 0; h < 2; h++) {
            float mx = -1e30f;
            #pragma unroll
            for (int v = 0; v < 8; v++)
                mx = fmaxf(mx, fmaxf(s[v][2*h], s[v][2*h+1]));
            mx = fmaxf(mx, __shfl_xor_sync(0xffffffffu, mx, 1));
            mx = fmaxf(mx, __shfl_xor_sync(0xffffffffu, mx, 2));
            float mnew = fmaxf(m_i[h], mx);
            float alpha = __expf(m_i[h] - mnew);
            m_i[h] = mnew;
            float rs = 0.f;
            #pragma unroll
            for (int v = 0; v < 8; v++) {
                s[v][2*h]   = __expf(s[v][2*h]   - mnew);
                s[v][2*h+1] = __expf(s[v][2*h+1] - mnew);
                rs += s[v][2*h] + s[v][2*h+1];
            }
            rs += __shfl_xor_sync(0xffffffffu, rs, 1);
            rs += __shfl_xor_sync(0xffffffffu, rs, 2);
            l_i[h] = l_i[h] * alpha + rs;
            #pragma unroll
            for (int v = 0; v < 8; v++) {
                o[v][2*h]   *= alpha;
                o[v][2*h+1] *= alpha;
            }
        }

        // pack P to fp16 A-fragments (k16 tiles over the 64 kv positions)
        uint32_t pa[4][4];
        #pragma unroll
        for (int u = 0; u < 4; u++) {
            pa[u][0] = h2u(s[2*u][0],   s[2*u][1]);
            pa[u][1] = h2u(s[2*u][2],   s[2*u][3]);
            pa[u][2] = h2u(s[2*u+1][0], s[2*u+1][1]);
            pa[u][3] = h2u(s[2*u+1][2], s[2*u+1][3]);
        }

        // O += P V  (fp16 MMA, fp32 accum)
        #pragma unroll
        for (int u = 0; u < 4; u++) {
            #pragma unroll
            for (int w2 = 0; w2 < 4; w2++) {
                int mt = lane >> 3;
                int row = u*16 + (mt & 1) * 8 + (lane & 7);
                int colb = w2*32 + (mt >> 1) * 16;
                uint32_t off = (uint32_t)(row * 128 + colb);
                off ^= ((off >> 7) & 7) << 4;
                uint32_t r[4];
                ldm4t(r, vsb + off);
                mma_f16(o[2*w2],     pa[u], r[0], r[1]);
                mma_f16(o[2*w2 + 1], pa[u], r[2], r[3]);
            }
        }
        __syncthreads();
    }

    // epilogue: normalize + split-bf16 store
    #pragma unroll
    for (int h = 0; h < 2; h++) {
        float inv = 1.f / l_i[h];
        int rowg = b * SEQ + n0 + wid*16 + h*8 + lr;
        #pragma unroll
        for (int v = 0; v < 8; v++) {
            int col = hd * 64 + v*8 + 2*lc;
            float f0 = o[v][2*h]   * inv;
            float f1 = o[v][2*h+1] * inv;
            __nv_bfloat16 h0, l0, h1, l1;
            split_bf16(f0, h0, l0);
            split_bf16(f1, h1, l1);
            *reinterpret_cast<__nv_bfloat162*>(outh + (size_t)rowg * INNER + col) =
                __nv_bfloat162(h0, h1);
            *reinterpret_cast<__nv_bfloat162*>(outl + (size_t)rowg * INNER + col) =
                __nv_bfloat162(l0, l1);
        }
    }
}

// ---------------- launcher ---------------------------------------------------
extern "C" void kernel_launch(void* const* d_in, const int* in_sizes, int n_in,
                              void* d_out, int out_size)
{
    const float* x     = (const float*)d_in[0];
    const float* gamma = (const float*)d_in[1];
    const float* beta  = (const float*)d_in[2];
    const float* Wqkv  = (const float*)d_in[3];
    const float* Wout  = (const float*)d_in[4];
    const float* bout  = (const float*)d_in[5];
    float* out = (float*)d_out;

    float* qkvbuf;
    __nv_bfloat16 *xnh, *xnl, *wqh, *wql, *woh, *wol, *aoh, *aol;
    cudaGetSymbolAddress((void**)&qkvbuf, g_qkv);
    cudaGetSymbolAddress((void**)&xnh, g_xnh);
    cudaGetSymbolAddress((void**)&xnl, g_xnl);
    cudaGetSymbolAddress((void**)&wqh, g_wqh);
    cudaGetSymbolAddress((void**)&wql, g_wql);
    cudaGetSymbolAddress((void**)&woh, g_woh);
    cudaGetSymbolAddress((void**)&wol, g_wol);
    cudaGetSymbolAddress((void**)&aoh, g_aoh);
    cudaGetSymbolAddress((void**)&aol, g_aol);

    cudaFuncSetAttribute(wm_gemm_kernel,
                         cudaFuncAttributeMaxDynamicSharedMemorySize, GS_SMEM);

    ln_split_kernel<<<ROWS, 256>>>(x, gamma, beta, xnh, xnl);

    transpose_split_kernel<<<dim3(QKV3 / 32, DIMSZ / 32), dim3(32, 8)>>>(
        Wqkv, wqh, wql, DIMSZ, QKV3);
    transpose_split_kernel<<<dim3(DIMSZ / 32, DIMSZ / 32), dim3(32, 8)>>>(
        Wout, woh, wol, INNER, DIMSZ);

    wm_gemm_kernel<<<dim3(QKV3 / 128, ROWS / 128), 256, GS_SMEM>>>(
        xnh, xnl, wqh, wql, nullptr, qkvbuf, QKV3);

    fa_kernel<<<dim3(SEQ / 128, HEADS, BATCH), 256, FA2_SMEM>>>(qkvbuf, aoh, aol);

    wm_gemm_kernel<<<dim3(DIMSZ / 128, ROWS / 128), 256, GS_SMEM>>>(
        aoh, aol, woh, wol, bout, out, DIMSZ);
}

// round 8
// speedup vs baseline: 1.2942x; 1.2713x over previous
#include <cuda_runtime.h>
#include <cuda_bf16.h>
#include <cuda_fp16.h>
#include <cstdint>

#define BATCH 2
#define SEQ   2048
#define DIMSZ 1024
#define HEADS 16
#define DHEAD 64
#define INNER 1024
#define QKV3  3072
#define ROWS  (BATCH * SEQ)   // 4096

// ---------------- scratch (static device globals; no allocation) -------------
__device__ float g_qkv[ROWS * QKV3];     // 50.3 MB fp32
__device__ float g_xnf[ROWS * DIMSZ];    // LN out, tf32-rounded fp32
__device__ float g_wqt[QKV3 * DIMSZ];    // Wqkv^T [3072][1024], tf32-rounded
__device__ float g_wot[DIMSZ * INNER];   // Wout^T [1024][1024], tf32-rounded
__device__ float g_aof[ROWS * INNER];    // attention out, tf32-rounded

// ---------------- helpers ----------------------------------------------------
__device__ __forceinline__ uint32_t smem_u32(const void* p) {
    uint32_t a;
    asm("{ .reg .u64 t; cvta.to.shared.u64 t, %1; cvt.u32.u64 %0, t; }"
        : "=r"(a) : "l"(p));
    return a;
}
__device__ __forceinline__ void cp16(uint32_t dst, const void* src) {
    asm volatile("cp.async.cg.shared.global [%0], [%1], 16;"
                 :: "r"(dst), "l"(src) : "memory");
}
__device__ __forceinline__ void ldm4t(uint32_t* r, uint32_t addr) {
    asm volatile("ldmatrix.sync.aligned.m8n8.x4.trans.shared.b16 {%0,%1,%2,%3}, [%4];"
        : "=r"(r[0]), "=r"(r[1]), "=r"(r[2]), "=r"(r[3]) : "r"(addr));
}
__device__ __forceinline__ void mma_f16(float* d, const uint32_t* a,
                                        uint32_t b0, uint32_t b1) {
    asm volatile("mma.sync.aligned.m16n8k16.row.col.f32.f16.f16.f32 "
        "{%0,%1,%2,%3}, {%4,%5,%6,%7}, {%8,%9}, {%0,%1,%2,%3};"
        : "+f"(d[0]), "+f"(d[1]), "+f"(d[2]), "+f"(d[3])
        : "r"(a[0]), "r"(a[1]), "r"(a[2]), "r"(a[3]), "r"(b0), "r"(b1));
}
__device__ __forceinline__ void mma_tf32(float* d, const uint32_t* a,
                                         uint32_t b0, uint32_t b1) {
    asm volatile("mma.sync.aligned.m16n8k8.row.col.f32.tf32.tf32.f32 "
        "{%0,%1,%2,%3}, {%4,%5,%6,%7}, {%8,%9}, {%0,%1,%2,%3};"
        : "+f"(d[0]), "+f"(d[1]), "+f"(d[2]), "+f"(d[3])
        : "r"(a[0]), "r"(a[1]), "r"(a[2]), "r"(a[3]), "r"(b0), "r"(b1));
}
__device__ __forceinline__ uint32_t to_tf32(float f) {
    uint32_t r; asm("cvt.rna.tf32.f32 %0, %1;" : "=r"(r) : "f"(f)); return r;
}
__device__ __forceinline__ float tf32f(float f) {
    return __uint_as_float(to_tf32(f));
}
__device__ __forceinline__ uint32_t h2u(float a, float b) {
    __half2 h = __floats2half2_rn(a, b);
    return *reinterpret_cast<uint32_t*>(&h);
}

// ---------------- LayerNorm -> tf32-rounded fp32 ------------------------------
__global__ void __launch_bounds__(256) ln_kernel(
    const float* __restrict__ x, const float* __restrict__ gamma,
    const float* __restrict__ beta, float* __restrict__ o)
{
    int row = blockIdx.x;
    int t = threadIdx.x;
    const float4* xr = reinterpret_cast<const float4*>(x + (size_t)row * DIMSZ);
    float4 v = xr[t];
    float s  = v.x + v.y + v.z + v.w;
    float ss = v.x*v.x + v.y*v.y + v.z*v.z + v.w*v.w;
    #pragma unroll
    for (int off = 16; off; off >>= 1) {
        s  += __shfl_xor_sync(0xffffffffu, s,  off);
        ss += __shfl_xor_sync(0xffffffffu, ss, off);
    }
    __shared__ float sbuf[8], ssbuf[8];
    __shared__ float s_mu, s_rstd;
    int w = t >> 5, lane = t & 31;
    if (lane == 0) { sbuf[w] = s; ssbuf[w] = ss; }
    __syncthreads();
    if (t == 0) {
        float S = 0.f, SS = 0.f;
        #pragma unroll
        for (int i = 0; i < 8; i++) { S += sbuf[i]; SS += ssbuf[i]; }
        float mu = S * (1.0f / DIMSZ);
        float var = SS * (1.0f / DIMSZ) - mu * mu;
        s_mu = mu; s_rstd = rsqrtf(var + 1e-5f);
    }
    __syncthreads();
    float mu = s_mu, rstd = s_rstd;
    float4 g  = reinterpret_cast<const float4*>(gamma)[t];
    float4 bt = reinterpret_cast<const float4*>(beta)[t];
    float4 r;
    r.x = tf32f((v.x - mu) * rstd * g.x + bt.x);
    r.y = tf32f((v.y - mu) * rstd * g.y + bt.y);
    r.z = tf32f((v.z - mu) * rstd * g.z + bt.z);
    r.w = tf32f((v.w - mu) * rstd * g.w + bt.w);
    reinterpret_cast<float4*>(o + (size_t)row * DIMSZ)[t] = r;
}

// ------------- weight transpose: in [K][N] fp32 -> out [N][K] tf32-rounded ---
__global__ void __launch_bounds__(256) transpose_kernel(
    const float* __restrict__ in, float* __restrict__ o, int K, int N)
{
    __shared__ float t[32][33];
    int n0 = blockIdx.x * 32, k0 = blockIdx.y * 32;
    int tx = threadIdx.x, ty = threadIdx.y;  // 32 x 8
    #pragma unroll
    for (int i = 0; i < 4; i++)
        t[ty + i*8][tx] = in[(size_t)(k0 + ty + i*8) * N + n0 + tx];
    __syncthreads();
    #pragma unroll
    for (int i = 0; i < 4; i++)
        o[(size_t)(n0 + ty + i*8) * K + k0 + tx] = tf32f(t[tx][ty + i*8]);
}

// ---------------- tf32 single-pass warp-mma GEMM -----------------------------
// C[M,Ntot] = A[M,1024] @ B[Ntot,1024]^T, K=1024, tf32 inputs (pre-rounded).
// CTA 128x128, BK=16, 8 warps (2m x 4n), warp tile 64x32, 2 MMAs per k16 tile.
// 80B-stride rows (20 banks/row -> conflict-free scalar frag loads),
// 4-stage cp.async ring, wait_group 2, one sync/iter, 2 CTAs/SM.
#define TS_ROWB   80
#define TS_ARR    (128 * TS_ROWB)      // 10240
#define TS_STAGE  (2 * TS_ARR)         // 20480 (A, B)
#define TS_NSTAGE 4
#define TS_SMEM   (TS_NSTAGE * TS_STAGE)   // 81920

__global__ void __launch_bounds__(256, 2) tf_gemm_kernel(
    const float* __restrict__ A, const float* __restrict__ B,
    const float* __restrict__ bias, float* __restrict__ C, int Ntot)
{
    extern __shared__ char sm[];
    const int tid = threadIdx.x, lane = tid & 31, wid = tid >> 5;
    const int wm = wid >> 2, wn = wid & 3;
    const int c0 = blockIdx.x * 128, r0 = blockIdx.y * 128;
    const int lr = lane >> 2, lc = lane & 3;
    uint32_t sbase = smem_u32(sm);

    // per stage: 2 arrays * 128 rows * 16 floats (64B) -> 1024 cp16, 4/thread
    auto issue = [&](int c, int st) {
        int k0 = c * 16;
        #pragma unroll
        for (int arr = 0; arr < 2; arr++) {
            #pragma unroll
            for (int i = 0; i < 2; i++) {
                int idx = tid + i * 256;          // 0..511
                int row = idx >> 2, seg = idx & 3;
                const float* s = (arr == 0)
                    ? A + (size_t)(r0 + row) * 1024 + k0 + seg * 4
                    : B + (size_t)(c0 + row) * 1024 + k0 + seg * 4;
                cp16(sbase + st * TS_STAGE + arr * TS_ARR + row * TS_ROWB + seg * 16, s);
            }
        }
        asm volatile("cp.async.commit_group;" ::: "memory");
    };

    float acc[4][4][4];
    #pragma unroll
    for (int a = 0; a < 4; a++)
        #pragma unroll
        for (int b = 0; b < 4; b++)
            #pragma unroll
            for (int cc = 0; cc < 4; cc++) acc[a][b][cc] = 0.f;

    issue(0, 0);
    issue(1, 1);
    issue(2, 2);

    const float* smf = reinterpret_cast<const float*>(sm);

    const int NCHUNK = 1024 / 16;   // 64
    for (int c = 0; c < NCHUNK; c++) {
        asm volatile("cp.async.wait_group 2;" ::: "memory");
        __syncthreads();

        if (c + 3 < NCHUNK) issue(c + 3, (c + 3) & 3);
        else asm volatile("cp.async.commit_group;" ::: "memory");

        const float* base  = smf + (c & 3) * (TS_STAGE / 4);   // float index
        const float* baseB = base + (TS_ARR / 4);
        const int RW = TS_ROWB / 4;   // 20 floats per row stride

        // B fragments: b0 = Bt[n0+lr][ks*8+lc], b1 = Bt[n0+lr][ks*8+lc+4]
        uint32_t bf[4][2][2];
        #pragma unroll
        for (int nt = 0; nt < 4; nt++) {
            const float* bp = baseB + (wn*32 + nt*8 + lr) * RW;
            #pragma unroll
            for (int ks = 0; ks < 2; ks++) {
                bf[nt][ks][0] = __float_as_uint(bp[ks*8 + lc]);
                bf[nt][ks][1] = __float_as_uint(bp[ks*8 + lc + 4]);
            }
        }
        // A fragments: a0=A[r][k], a1=A[r+8][k], a2=A[r][k+4], a3=A[r+8][k+4]
        uint32_t af[4][2][4];
        #pragma unroll
        for (int mt = 0; mt < 4; mt++) {
            const float* ap0 = base + (wm*64 + mt*16 + lr) * RW;
            const float* ap1 = ap0 + 8 * RW;
            #pragma unroll
            for (int ks = 0; ks < 2; ks++) {
                af[mt][ks][0] = __float_as_uint(ap0[ks*8 + lc]);
                af[mt][ks][1] = __float_as_uint(ap1[ks*8 + lc]);
                af[mt][ks][2] = __float_as_uint(ap0[ks*8 + lc + 4]);
                af[mt][ks][3] = __float_as_uint(ap1[ks*8 + lc + 4]);
            }
        }
        // two passes of 16 independent MMAs (dep distance 16 per accumulator)
        #pragma unroll
        for (int ks = 0; ks < 2; ks++)
            #pragma unroll
            for (int mt = 0; mt < 4; mt++)
                #pragma unroll
                for (int nt = 0; nt < 4; nt++)
                    mma_tf32(acc[mt][nt], af[mt][ks], bf[nt][ks][0], bf[nt][ks][1]);
    }

    #pragma unroll
    for (int mt = 0; mt < 4; mt++) {
        int rbase = r0 + wm*64 + mt*16 + lr;
        #pragma unroll
        for (int nt = 0; nt < 4; nt++) {
            int col = c0 + wn*32 + nt*8 + 2*lc;
            float b0v = bias ? bias[col] : 0.f;
            float b1v = bias ? bias[col + 1] : 0.f;
            float2 v0 = {acc[mt][nt][0] + b0v, acc[mt][nt][1] + b1v};
            float2 v1 = {acc[mt][nt][2] + b0v, acc[mt][nt][3] + b1v};
            *reinterpret_cast<float2*>(C + (size_t)rbase * Ntot + col) = v0;
            *reinterpret_cast<float2*>(C + (size_t)(rbase + 8) * Ntot + col) = v1;
        }
    }
}

// ---------------- flash attention: tf32 QK + fp16 PV -------------------------
// CTA: 128 q rows (8 warps x m16), kv-tile 64. Q prescaled by 0.125.
#define FA2_SMEM 34816   // max(Q 128*68*4, K 64*68*4 + V 64*128)

__global__ void __launch_bounds__(256, 1) fa_kernel(
    const float* __restrict__ qkv, float* __restrict__ outf)
{
    extern __shared__ char sm[];
    uint32_t* Ks = reinterpret_cast<uint32_t*>(sm);       // [64][68] tf32
    char* Vs = sm + 64 * 68 * 4;                          // [64][128B] swizzled fp16
    uint32_t* Qs = reinterpret_cast<uint32_t*>(sm);       // [128][68] (init only)

    const int tid = threadIdx.x, lane = tid & 31, wid = tid >> 5;
    const int qt = blockIdx.x, hd = blockIdx.y, b = blockIdx.z;
    const int n0 = qt * 128;
    const int lr = lane >> 2, lc = lane & 3;

    const float* qb = qkv + (size_t)b * SEQ * QKV3 + hd * DHEAD;
    const float* kb = qb + 1024;
    const float* vb = qb + 2048;

    // stage Q (prescaled, tf32)
    #pragma unroll
    for (int i = 0; i < 8; i++) {
        int q = tid + i * 256;
        int row = q >> 4, c4 = (q & 15) * 4;
        float4 v = *reinterpret_cast<const float4*>(qb + (size_t)(n0 + row) * QKV3 + c4);
        uint4 t;
        t.x = to_tf32(v.x * 0.125f); t.y = to_tf32(v.y * 0.125f);
        t.z = to_tf32(v.z * 0.125f); t.w = to_tf32(v.w * 0.125f);
        *reinterpret_cast<uint4*>(&Qs[row * 68 + c4]) = t;
    }
    __syncthreads();

    uint32_t qa[8][4];
    {
        int m0 = wid * 16;
        #pragma unroll
        for (int u = 0; u < 8; u++) {
            qa[u][0] = Qs[(m0 + lr)     * 68 + u*8 + lc];
            qa[u][1] = Qs[(m0 + 8 + lr) * 68 + u*8 + lc];
            qa[u][2] = Qs[(m0 + lr)     * 68 + u*8 + 4 + lc];
            qa[u][3] = Qs[(m0 + 8 + lr) * 68 + u*8 + 4 + lc];
        }
    }
    __syncthreads();

    float m_i[2] = {-1e30f, -1e30f}, l_i[2] = {0.f, 0.f};
    float o[8][4];
    #pragma unroll
    for (int v = 0; v < 8; v++)
        #pragma unroll
        for (int j = 0; j < 4; j++) o[v][j] = 0.f;

    const uint32_t vsb = smem_u32(Vs);

    for (int kt = 0; kt < SEQ / 64; kt++) {
        int s0 = kt * 64;
        #pragma unroll
        for (int i = 0; i < 4; i++) {
            int q = tid + i * 256;
            int row = q >> 4, c4 = (q & 15) * 4;
            float4 kv = *reinterpret_cast<const float4*>(kb + (size_t)(s0 + row) * QKV3 + c4);
            uint4 t = {to_tf32(kv.x), to_tf32(kv.y), to_tf32(kv.z), to_tf32(kv.w)};
            *reinterpret_cast<uint4*>(&Ks[row * 68 + c4]) = t;
            float4 vv = *reinterpret_cast<const float4*>(vb + (size_t)(s0 + row) * QKV3 + c4);
            uint2 hp = {h2u(vv.x, vv.y), h2u(vv.z, vv.w)};
            uint32_t off = row * 128 + c4 * 2;
            off ^= ((off >> 7) & 7) << 4;
            *reinterpret_cast<uint2*>(Vs + off) = hp;
        }
        __syncthreads();

        // S = Q K^T  (tf32)
        float s[8][4];
        #pragma unroll
        for (int v = 0; v < 8; v++)
            #pragma unroll
            for (int j = 0; j < 4; j++) s[v][j] = 0.f;
        #pragma unroll
        for (int u = 0; u < 8; u++) {
            #pragma unroll
            for (int v = 0; v < 8; v++) {
                uint32_t kb0 = Ks[(v*8 + lr) * 68 + u*8 + lc];
                uint32_t kb1 = Ks[(v*8 + lr) * 68 + u*8 + 4 + lc];
                mma_tf32(s[v], qa[u], kb0, kb1);
            }
        }

        // online softmax (rows: lr and lr+8)
        #pragma unroll
        for (int h = 0; h < 2; h++) {
            float mx = -1e30f;
            #pragma unroll
            for (int v = 0; v < 8; v++)
                mx = fmaxf(mx, fmaxf(s[v][2*h], s[v][2*h+1]));
            mx = fmaxf(mx, __shfl_xor_sync(0xffffffffu, mx, 1));
            mx = fmaxf(mx, __shfl_xor_sync(0xffffffffu, mx, 2));
            float mnew = fmaxf(m_i[h], mx);
            float alpha = __expf(m_i[h] - mnew);
            m_i[h] = mnew;
            float rs = 0.f;
            #pragma unroll
            for (int v = 0; v < 8; v++) {
                s[v][2*h]   = __expf(s[v][2*h]   - mnew);
                s[v][2*h+1] = __expf(s[v][2*h+1] - mnew);
                rs += s[v][2*h] + s[v][2*h+1];
            }
            rs += __shfl_xor_sync(0xffffffffu, rs, 1);
            rs += __shfl_xor_sync(0xffffffffu, rs, 2);
            l_i[h] = l_i[h] * alpha + rs;
            #pragma unroll
            for (int v = 0; v < 8; v++) {
                o[v][2*h]   *= alpha;
                o[v][2*h+1] *= alpha;
            }
        }

        // pack P to fp16 A-fragments
        uint32_t pa[4][4];
        #pragma unroll
        for (int u = 0; u < 4; u++) {
            pa[u][0] = h2u(s[2*u][0],   s[2*u][1]);
            pa[u][1] = h2u(s[2*u][2],   s[2*u][3]);
            pa[u][2] = h2u(s[2*u+1][0], s[2*u+1][1]);
            pa[u][3] = h2u(s[2*u+1][2], s[2*u+1][3]);
        }

        // O += P V  (fp16 MMA, fp32 accum)
        #pragma unroll
        for (int u = 0; u < 4; u++) {
            #pragma unroll
            for (int w2 = 0; w2 < 4; w2++) {
                int mt = lane >> 3;
                int row = u*16 + (mt & 1) * 8 + (lane & 7);
                int colb = w2*32 + (mt >> 1) * 16;
                uint32_t off = (uint32_t)(row * 128 + colb);
                off ^= ((off >> 7) & 7) << 4;
                uint32_t r[4];
                ldm4t(r, vsb + off);
                mma_f16(o[2*w2],     pa[u], r[0], r[1]);
                mma_f16(o[2*w2 + 1], pa[u], r[2], r[3]);
            }
        }
        __syncthreads();
    }

    // epilogue: normalize + tf32-rounded fp32 store
    #pragma unroll
    for (int h = 0; h < 2; h++) {
        float inv = 1.f / l_i[h];
        int rowg = b * SEQ + n0 + wid*16 + h*8 + lr;
        #pragma unroll
        for (int v = 0; v < 8; v++) {
            int col = hd * 64 + v*8 + 2*lc;
            float2 r;
            r.x = tf32f(o[v][2*h]   * inv);
            r.y = tf32f(o[v][2*h+1] * inv);
            *reinterpret_cast<float2*>(outf + (size_t)rowg * INNER + col) = r;
        }
    }
}

// ---------------- launcher ---------------------------------------------------
extern "C" void kernel_launch(void* const* d_in, const int* in_sizes, int n_in,
                              void* d_out, int out_size)
{
    const float* x     = (const float*)d_in[0];
    const float* gamma = (const float*)d_in[1];
    const float* beta  = (const float*)d_in[2];
    const float* Wqkv  = (const float*)d_in[3];
    const float* Wout  = (const float*)d_in[4];
    const float* bout  = (const float*)d_in[5];
    float* out = (float*)d_out;

    float *qkvbuf, *xnf, *wqt, *wot, *aof;
    cudaGetSymbolAddress((void**)&qkvbuf, g_qkv);
    cudaGetSymbolAddress((void**)&xnf, g_xnf);
    cudaGetSymbolAddress((void**)&wqt, g_wqt);
    cudaGetSymbolAddress((void**)&wot, g_wot);
    cudaGetSymbolAddress((void**)&aof, g_aof);

    cudaFuncSetAttribute(tf_gemm_kernel,
                         cudaFuncAttributeMaxDynamicSharedMemorySize, TS_SMEM);

    ln_kernel<<<ROWS, 256>>>(x, gamma, beta, xnf);

    transpose_kernel<<<dim3(QKV3 / 32, DIMSZ / 32), dim3(32, 8)>>>(
        Wqkv, wqt, DIMSZ, QKV3);
    transpose_kernel<<<dim3(DIMSZ / 32, DIMSZ / 32), dim3(32, 8)>>>(
        Wout, wot, INNER, DIMSZ);

    tf_gemm_kernel<<<dim3(QKV3 / 128, ROWS / 128), 256, TS_SMEM>>>(
        xnf, wqt, nullptr, qkvbuf, QKV3);

    fa_kernel<<<dim3(SEQ / 128, HEADS, BATCH), 256, FA2_SMEM>>>(qkvbuf, aof);

    tf_gemm_kernel<<<dim3(DIMSZ / 128, ROWS / 128), 256, TS_SMEM>>>(
        aof, wot, bout, out, DIMSZ);
}

// round 9
// speedup vs baseline: 1.6356x; 1.2638x over previous
#include <cuda_runtime.h>
#include <cuda_bf16.h>
#include <cuda_fp16.h>
#include <cstdint>

#define BATCH 2
#define SEQ   2048
#define DIMSZ 1024
#define HEADS 16
#define DHEAD 64
#define INNER 1024
#define QKV3  3072
#define ROWS  (BATCH * SEQ)   // 4096

// ---------------- scratch (static device globals; no allocation) -------------
__device__ float  g_qkv[ROWS * QKV3];     // 50.3 MB fp32
__device__ __half g_xnh[ROWS * DIMSZ];    // LN out fp16
__device__ __half g_wqt[QKV3 * DIMSZ];    // Wqkv^T [3072][1024] fp16
__device__ __half g_wot[DIMSZ * INNER];   // Wout^T [1024][1024] fp16
__device__ __half g_aoh[ROWS * INNER];    // attention out fp16

// ---------------- helpers ----------------------------------------------------
__device__ __forceinline__ uint32_t smem_u32(const void* p) {
    uint32_t a;
    asm("{ .reg .u64 t; cvta.to.shared.u64 t, %1; cvt.u32.u64 %0, t; }"
        : "=r"(a) : "l"(p));
    return a;
}
__device__ __forceinline__ void cp16(uint32_t dst, const void* src) {
    asm volatile("cp.async.cg.shared.global [%0], [%1], 16;"
                 :: "r"(dst), "l"(src) : "memory");
}
__device__ __forceinline__ void ldm4t(uint32_t* r, uint32_t addr) {
    asm volatile("ldmatrix.sync.aligned.m8n8.x4.trans.shared.b16 {%0,%1,%2,%3}, [%4];"
        : "=r"(r[0]), "=r"(r[1]), "=r"(r[2]), "=r"(r[3]) : "r"(addr));
}
__device__ __forceinline__ void mma_f16(float* d, const uint32_t* a,
                                        uint32_t b0, uint32_t b1) {
    asm volatile("mma.sync.aligned.m16n8k16.row.col.f32.f16.f16.f32 "
        "{%0,%1,%2,%3}, {%4,%5,%6,%7}, {%8,%9}, {%0,%1,%2,%3};"
        : "+f"(d[0]), "+f"(d[1]), "+f"(d[2]), "+f"(d[3])
        : "r"(a[0]), "r"(a[1]), "r"(a[2]), "r"(a[3]), "r"(b0), "r"(b1));
}
__device__ __forceinline__ void mma_tf32(float* d, const uint32_t* a,
                                         uint32_t b0, uint32_t b1) {
    asm volatile("mma.sync.aligned.m16n8k8.row.col.f32.tf32.tf32.f32 "
        "{%0,%1,%2,%3}, {%4,%5,%6,%7}, {%8,%9}, {%0,%1,%2,%3};"
        : "+f"(d[0]), "+f"(d[1]), "+f"(d[2]), "+f"(d[3])
        : "r"(a[0]), "r"(a[1]), "r"(a[2]), "r"(a[3]), "r"(b0), "r"(b1));
}
__device__ __forceinline__ uint32_t to_tf32(float f) {
    uint32_t r; asm("cvt.rna.tf32.f32 %0, %1;" : "=r"(r) : "f"(f)); return r;
}
__device__ __forceinline__ uint32_t h2u(float a, float b) {
    __half2 h = __floats2half2_rn(a, b);
    return *reinterpret_cast<uint32_t*>(&h);
}

// ---------------- LayerNorm -> fp16 -------------------------------------------
__global__ void __launch_bounds__(256) ln_kernel(
    const float* __restrict__ x, const float* __restrict__ gamma,
    const float* __restrict__ beta, __half* __restrict__ o)
{
    int row = blockIdx.x;
    int t = threadIdx.x;
    const float4* xr = reinterpret_cast<const float4*>(x + (size_t)row * DIMSZ);
    float4 v = xr[t];
    float s  = v.x + v.y + v.z + v.w;
    float ss = v.x*v.x + v.y*v.y + v.z*v.z + v.w*v.w;
    #pragma unroll
    for (int off = 16; off; off >>= 1) {
        s  += __shfl_xor_sync(0xffffffffu, s,  off);
        ss += __shfl_xor_sync(0xffffffffu, ss, off);
    }
    __shared__ float sbuf[8], ssbuf[8];
    __shared__ float s_mu, s_rstd;
    int w = t >> 5, lane = t & 31;
    if (lane == 0) { sbuf[w] = s; ssbuf[w] = ss; }
    __syncthreads();
    if (t == 0) {
        float S = 0.f, SS = 0.f;
        #pragma unroll
        for (int i = 0; i < 8; i++) { S += sbuf[i]; SS += ssbuf[i]; }
        float mu = S * (1.0f / DIMSZ);
        float var = SS * (1.0f / DIMSZ) - mu * mu;
        s_mu = mu; s_rstd = rsqrtf(var + 1e-5f);
    }
    __syncthreads();
    float mu = s_mu, rstd = s_rstd;
    float4 g  = reinterpret_cast<const float4*>(gamma)[t];
    float4 bt = reinterpret_cast<const float4*>(beta)[t];
    float o0 = (v.x - mu) * rstd * g.x + bt.x;
    float o1 = (v.y - mu) * rstd * g.y + bt.y;
    float o2 = (v.z - mu) * rstd * g.z + bt.z;
    float o3 = (v.w - mu) * rstd * g.w + bt.w;
    uint2 pk = {h2u(o0, o1), h2u(o2, o3)};
    *reinterpret_cast<uint2*>(o + (size_t)row * DIMSZ + t * 4) = pk;
}

// ------------- weight transpose: in [K][N] fp32 -> out [N][K] fp16 -----------
__global__ void __launch_bounds__(256) transpose_kernel(
    const float* __restrict__ in, __half* __restrict__ o, int K, int N)
{
    __shared__ float t[32][33];
    int n0 = blockIdx.x * 32, k0 = blockIdx.y * 32;
    int tx = threadIdx.x, ty = threadIdx.y;  // 32 x 8
    #pragma unroll
    for (int i = 0; i < 4; i++)
        t[ty + i*8][tx] = in[(size_t)(k0 + ty + i*8) * N + n0 + tx];
    __syncthreads();
    #pragma unroll
    for (int i = 0; i < 4; i++)
        o[(size_t)(n0 + ty + i*8) * K + k0 + tx] = __float2half_rn(t[tx][ty + i*8]);
}

// ---------------- fp16 single-pass warp-mma GEMM -----------------------------
// C[M,Ntot] = A[M,1024] @ B[Ntot,1024]^T, K=1024, fp16 inputs, fp32 accum.
// CTA 128x128, BK=16 (ONE m16n8k16 per warp-tile per chunk), 8 warps (2m x 4n),
// warp tile 64x32. 48B-stride rows -> banks (12*lr+lc) all distinct.
// 4-stage cp.async ring, wait_group 2, one sync/iter, 2 CTAs/SM.
#define HS_ROWB   48                   // bytes per row (32 data + 16 pad)
#define HS_ARR    (128 * HS_ROWB)      // 6144
#define HS_STAGE  (2 * HS_ARR)         // 12288 (A, B)
#define HS_NSTAGE 4
#define HS_SMEM   (HS_NSTAGE * HS_STAGE)   // 49152

__global__ void __launch_bounds__(256, 2) hf_gemm_kernel(
    const __half* __restrict__ A, const __half* __restrict__ B,
    const float* __restrict__ bias, float* __restrict__ C, int Ntot)
{
    extern __shared__ char sm[];
    const int tid = threadIdx.x, lane = tid & 31, wid = tid >> 5;
    const int wm = wid >> 2, wn = wid & 3;
    const int c0 = blockIdx.x * 128, r0 = blockIdx.y * 128;
    const int lr = lane >> 2, lc = lane & 3;
    uint32_t sbase = smem_u32(sm);

    // per stage: 2 arrays * 128 rows * 32B -> 512 cp16, 2/thread
    auto issue = [&](int c, int st) {
        int k0 = c * 16;
        #pragma unroll
        for (int i = 0; i < 2; i++) {
            int q = tid + i * 256;           // 0..511
            int arr = q >> 8, rem = q & 255;
            int row = rem >> 1, seg = rem & 1;
            const __half* s = (arr == 0)
                ? A + (size_t)(r0 + row) * 1024 + k0 + seg * 8
                : B + (size_t)(c0 + row) * 1024 + k0 + seg * 8;
            cp16(sbase + st * HS_STAGE + arr * HS_ARR + row * HS_ROWB + seg * 16, s);
        }
        asm volatile("cp.async.commit_group;" ::: "memory");
    };

    float acc[4][4][4];
    #pragma unroll
    for (int a = 0; a < 4; a++)
        #pragma unroll
        for (int b = 0; b < 4; b++)
            #pragma unroll
            for (int cc = 0; cc < 4; cc++) acc[a][b][cc] = 0.f;

    issue(0, 0);
    issue(1, 1);
    issue(2, 2);

    const uint32_t* smu = reinterpret_cast<const uint32_t*>(sm);
    const int RW = HS_ROWB / 4;   // 12 u32 per row

    const int NCHUNK = 1024 / 16;   // 64
    for (int c = 0; c < NCHUNK; c++) {
        asm volatile("cp.async.wait_group 2;" ::: "memory");
        __syncthreads();

        if (c + 3 < NCHUNK) issue(c + 3, (c + 3) & 3);
        else asm volatile("cp.async.commit_group;" ::: "memory");

        const uint32_t* base  = smu + (c & 3) * (HS_STAGE / 4);
        const uint32_t* baseB = base + (HS_ARR / 4);

        // B fragments: b0 = (n=lr, k=2lc..2lc+1), b1 = (n=lr, k=2lc+8..9)
        uint32_t bf[4][2];
        #pragma unroll
        for (int nt = 0; nt < 4; nt++) {
            const uint32_t* bp = baseB + (wn*32 + nt*8 + lr) * RW;
            bf[nt][0] = bp[lc];
            bf[nt][1] = bp[lc + 4];
        }
        // A fragments: a0=(r,2lc) a1=(r+8,2lc) a2=(r,2lc+8) a3=(r+8,2lc+8)
        uint32_t af[4][4];
        #pragma unroll
        for (int mt = 0; mt < 4; mt++) {
            const uint32_t* ap0 = base + (wm*64 + mt*16 + lr) * RW;
            const uint32_t* ap1 = ap0 + 8 * RW;
            af[mt][0] = ap0[lc];
            af[mt][1] = ap1[lc];
            af[mt][2] = ap0[lc + 4];
            af[mt][3] = ap1[lc + 4];
        }
        // one pass of 16 independent MMAs
        #pragma unroll
        for (int mt = 0; mt < 4; mt++)
            #pragma unroll
            for (int nt = 0; nt < 4; nt++)
                mma_f16(acc[mt][nt], af[mt], bf[nt][0], bf[nt][1]);
    }

    #pragma unroll
    for (int mt = 0; mt < 4; mt++) {
        int rbase = r0 + wm*64 + mt*16 + lr;
        #pragma unroll
        for (int nt = 0; nt < 4; nt++) {
            int col = c0 + wn*32 + nt*8 + 2*lc;
            float b0v = bias ? bias[col] : 0.f;
            float b1v = bias ? bias[col + 1] : 0.f;
            float2 v0 = {acc[mt][nt][0] + b0v, acc[mt][nt][1] + b1v};
            float2 v1 = {acc[mt][nt][2] + b0v, acc[mt][nt][3] + b1v};
            *reinterpret_cast<float2*>(C + (size_t)rbase * Ntot + col) = v0;
            *reinterpret_cast<float2*>(C + (size_t)(rbase + 8) * Ntot + col) = v1;
        }
    }
}

// ---------------- flash attention: tf32 QK + fp16 PV -------------------------
// CTA: 128 q rows (8 warps x m16), kv-tile 64. Q prescaled by 0.125.
#define FA2_SMEM 34816   // max(Q 128*68*4, K 64*68*4 + V 64*128)

__global__ void __launch_bounds__(256, 1) fa_kernel(
    const float* __restrict__ qkv, __half* __restrict__ outh)
{
    extern __shared__ char sm[];
    uint32_t* Ks = reinterpret_cast<uint32_t*>(sm);       // [64][68] tf32
    char* Vs = sm + 64 * 68 * 4;                          // [64][128B] swizzled fp16
    uint32_t* Qs = reinterpret_cast<uint32_t*>(sm);       // [128][68] (init only)

    const int tid = threadIdx.x, lane = tid & 31, wid = tid >> 5;
    const int qt = blockIdx.x, hd = blockIdx.y, b = blockIdx.z;
    const int n0 = qt * 128;
    const int lr = lane >> 2, lc = lane & 3;

    const float* qb = qkv + (size_t)b * SEQ * QKV3 + hd * DHEAD;
    const float* kb = qb + 1024;
    const float* vb = qb + 2048;

    // stage Q (prescaled, tf32)
    #pragma unroll
    for (int i = 0; i < 8; i++) {
        int q = tid + i * 256;
        int row = q >> 4, c4 = (q & 15) * 4;
        float4 v = *reinterpret_cast<const float4*>(qb + (size_t)(n0 + row) * QKV3 + c4);
        uint4 t;
        t.x = to_tf32(v.x * 0.125f); t.y = to_tf32(v.y * 0.125f);
        t.z = to_tf32(v.z * 0.125f); t.w = to_tf32(v.w * 0.125f);
        *reinterpret_cast<uint4*>(&Qs[row * 68 + c4]) = t;
    }
    __syncthreads();

    uint32_t qa[8][4];
    {
        int m0 = wid * 16;
        #pragma unroll
        for (int u = 0; u < 8; u++) {
            qa[u][0] = Qs[(m0 + lr)     * 68 + u*8 + lc];
            qa[u][1] = Qs[(m0 + 8 + lr) * 68 + u*8 + lc];
            qa[u][2] = Qs[(m0 + lr)     * 68 + u*8 + 4 + lc];
            qa[u][3] = Qs[(m0 + 8 + lr) * 68 + u*8 + 4 + lc];
        }
    }
    __syncthreads();

    float m_i[2] = {-1e30f, -1e30f}, l_i[2] = {0.f, 0.f};
    float o[8][4];
    #pragma unroll
    for (int v = 0; v < 8; v++)
        #pragma unroll
        for (int j = 0; j < 4; j++) o[v][j] = 0.f;

    const uint32_t vsb = smem_u32(Vs);

    for (int kt = 0; kt < SEQ / 64; kt++) {
        int s0 = kt * 64;
        #pragma unroll
        for (int i = 0; i < 4; i++) {
            int q = tid + i * 256;
            int row = q >> 4, c4 = (q & 15) * 4;
            float4 kv = *reinterpret_cast<const float4*>(kb + (size_t)(s0 + row) * QKV3 + c4);
            uint4 t = {to_tf32(kv.x), to_tf32(kv.y), to_tf32(kv.z), to_tf32(kv.w)};
            *reinterpret_cast<uint4*>(&Ks[row * 68 + c4]) = t;
            float4 vv = *reinterpret_cast<const float4*>(vb + (size_t)(s0 + row) * QKV3 + c4);
            uint2 hp = {h2u(vv.x, vv.y), h2u(vv.z, vv.w)};
            uint32_t off = row * 128 + c4 * 2;
            off ^= ((off >> 7) & 7) << 4;
            *reinterpret_cast<uint2*>(Vs + off) = hp;
        }
        __syncthreads();

        // S = Q K^T  (tf32)
        float s[8][4];
        #pragma unroll
        for (int v = 0; v < 8; v++)
            #pragma unroll
            for (int j = 0; j < 4; j++) s[v][j] = 0.f;
        #pragma unroll
        for (int u = 0; u < 8; u++) {
            #pragma unroll
            for (int v = 0; v < 8; v++) {
                uint32_t kb0 = Ks[(v*8 + lr) * 68 + u*8 + lc];
                uint32_t kb1 = Ks[(v*8 + lr) * 68 + u*8 + 4 + lc];
                mma_tf32(s[v], qa[u], kb0, kb1);
            }
        }

        // online softmax (rows: lr and lr+8)
        #pragma unroll
        for (int h = 0; h < 2; h++) {
            float mx = -1e30f;
            #pragma unroll
            for (int v = 0; v < 8; v++)
                mx = fmaxf(mx, fmaxf(s[v][2*h], s[v][2*h+1]));
            mx = fmaxf(mx, __shfl_xor_sync(0xffffffffu, mx, 1));
            mx = fmaxf(mx, __shfl_xor_sync(0xffffffffu, mx, 2));
            float mnew = fmaxf(m_i[h], mx);
            float alpha = __expf(m_i[h] - mnew);
            m_i[h] = mnew;
            float rs = 0.f;
            #pragma unroll
            for (int v = 0; v < 8; v++) {
                s[v][2*h]   = __expf(s[v][2*h]   - mnew);
                s[v][2*h+1] = __expf(s[v][2*h+1] - mnew);
                rs += s[v][2*h] + s[v][2*h+1];
            }
            rs += __shfl_xor_sync(0xffffffffu, rs, 1);
            rs += __shfl_xor_sync(0xffffffffu, rs, 2);
            l_i[h] = l_i[h] * alpha + rs;
            #pragma unroll
            for (int v = 0; v < 8; v++) {
                o[v][2*h]   *= alpha;
                o[v][2*h+1] *= alpha;
            }
        }

        // pack P to fp16 A-fragments
        uint32_t pa[4][4];
        #pragma unroll
        for (int u = 0; u < 4; u++) {
            pa[u][0] = h2u(s[2*u][0],   s[2*u][1]);
            pa[u][1] = h2u(s[2*u][2],   s[2*u][3]);
            pa[u][2] = h2u(s[2*u+1][0], s[2*u+1][1]);
            pa[u][3] = h2u(s[2*u+1][2], s[2*u+1][3]);
        }

        // O += P V  (fp16 MMA, fp32 accum)
        #pragma unroll
        for (int u = 0; u < 4; u++) {
            #pragma unroll
            for (int w2 = 0; w2 < 4; w2++) {
                int mt = lane >> 3;
                int row = u*16 + (mt & 1) * 8 + (lane & 7);
                int colb = w2*32 + (mt >> 1) * 16;
                uint32_t off = (uint32_t)(row * 128 + colb);
                off ^= ((off >> 7) & 7) << 4;
                uint32_t r[4];
                ldm4t(r, vsb + off);
                mma_f16(o[2*w2],     pa[u], r[0], r[1]);
                mma_f16(o[2*w2 + 1], pa[u], r[2], r[3]);
            }
        }
        __syncthreads();
    }

    // epilogue: normalize + fp16 store
    #pragma unroll
    for (int h = 0; h < 2; h++) {
        float inv = 1.f / l_i[h];
        int rowg = b * SEQ + n0 + wid*16 + h*8 + lr;
        #pragma unroll
        for (int v = 0; v < 8; v++) {
            int col = hd * 64 + v*8 + 2*lc;
            uint32_t pk = h2u(o[v][2*h] * inv, o[v][2*h+1] * inv);
            *reinterpret_cast<uint32_t*>(outh + (size_t)rowg * INNER + col) = pk;
        }
    }
}

// ---------------- launcher ---------------------------------------------------
extern "C" void kernel_launch(void* const* d_in, const int* in_sizes, int n_in,
                              void* d_out, int out_size)
{
    const float* x     = (const float*)d_in[0];
    const float* gamma = (const float*)d_in[1];
    const float* beta  = (const float*)d_in[2];
    const float* Wqkv  = (const float*)d_in[3];
    const float* Wout  = (const float*)d_in[4];
    const float* bout  = (const float*)d_in[5];
    float* out = (float*)d_out;

    float* qkvbuf;
    __half *xnh, *wqt, *wot, *aoh;
    cudaGetSymbolAddress((void**)&qkvbuf, g_qkv);
    cudaGetSymbolAddress((void**)&xnh, g_xnh);
    cudaGetSymbolAddress((void**)&wqt, g_wqt);
    cudaGetSymbolAddress((void**)&wot, g_wot);
    cudaGetSymbolAddress((void**)&aoh, g_aoh);

    cudaFuncSetAttribute(hf_gemm_kernel,
                         cudaFuncAttributeMaxDynamicSharedMemorySize, HS_SMEM);

    ln_kernel<<<ROWS, 256>>>(x, gamma, beta, xnh);

    transpose_kernel<<<dim3(QKV3 / 32, DIMSZ / 32), dim3(32, 8)>>>(
        Wqkv, wqt, DIMSZ, QKV3);
    transpose_kernel<<<dim3(DIMSZ / 32, DIMSZ / 32), dim3(32, 8)>>>(
        Wout, wot, INNER, DIMSZ);

    hf_gemm_kernel<<<dim3(QKV3 / 128, ROWS / 128), 256, HS_SMEM>>>(
        xnh, wqt, nullptr, qkvbuf, QKV3);

    fa_kernel<<<dim3(SEQ / 128, HEADS, BATCH), 256, FA2_SMEM>>>(qkvbuf, aoh);

    hf_gemm_kernel<<<dim3(DIMSZ / 128, ROWS / 128), 256, HS_SMEM>>>(
        aoh, wot, bout, out, DIMSZ);
}

// round 10
// speedup vs baseline: 1.9485x; 1.1913x over previous
#include <cuda_runtime.h>
#include <cuda_bf16.h>
#include <cuda_fp16.h>
#include <cstdint>

#define BATCH 2
#define SEQ   2048
#define DIMSZ 1024
#define HEADS 16
#define DHEAD 64
#define INNER 1024
#define QKV3  3072
#define ROWS  (BATCH * SEQ)   // 4096

// ---------------- scratch (static device globals; no allocation) -------------
__device__ float  g_qkv[ROWS * QKV3];     // 50.3 MB fp32
__device__ __half g_xnh[ROWS * DIMSZ];    // LN out fp16
__device__ __half g_wqt[QKV3 * DIMSZ];    // Wqkv^T [3072][1024] fp16
__device__ __half g_wot[DIMSZ * INNER];   // Wout^T [1024][1024] fp16
__device__ __half g_aoh[ROWS * INNER];    // attention out fp16

// ---------------- helpers ----------------------------------------------------
__device__ __forceinline__ uint32_t smem_u32(const void* p) {
    uint32_t a;
    asm("{ .reg .u64 t; cvta.to.shared.u64 t, %1; cvt.u32.u64 %0, t; }"
        : "=r"(a) : "l"(p));
    return a;
}
__device__ __forceinline__ void cp16(uint32_t dst, const void* src) {
    asm volatile("cp.async.cg.shared.global [%0], [%1], 16;"
                 :: "r"(dst), "l"(src) : "memory");
}
__device__ __forceinline__ void ldm4(uint32_t* r, uint32_t addr) {
    asm volatile("ldmatrix.sync.aligned.m8n8.x4.shared.b16 {%0,%1,%2,%3}, [%4];"
        : "=r"(r[0]), "=r"(r[1]), "=r"(r[2]), "=r"(r[3]) : "r"(addr));
}
__device__ __forceinline__ void ldm4t(uint32_t* r, uint32_t addr) {
    asm volatile("ldmatrix.sync.aligned.m8n8.x4.trans.shared.b16 {%0,%1,%2,%3}, [%4];"
        : "=r"(r[0]), "=r"(r[1]), "=r"(r[2]), "=r"(r[3]) : "r"(addr));
}
__device__ __forceinline__ void mma_f16(float* d, const uint32_t* a,
                                        uint32_t b0, uint32_t b1) {
    asm volatile("mma.sync.aligned.m16n8k16.row.col.f32.f16.f16.f32 "
        "{%0,%1,%2,%3}, {%4,%5,%6,%7}, {%8,%9}, {%0,%1,%2,%3};"
        : "+f"(d[0]), "+f"(d[1]), "+f"(d[2]), "+f"(d[3])
        : "r"(a[0]), "r"(a[1]), "r"(a[2]), "r"(a[3]), "r"(b0), "r"(b1));
}
__device__ __forceinline__ uint32_t h2u(float a, float b) {
    __half2 h = __floats2half2_rn(a, b);
    return *reinterpret_cast<uint32_t*>(&h);
}

// ---------------- LayerNorm -> fp16 -------------------------------------------
__global__ void __launch_bounds__(256) ln_kernel(
    const float* __restrict__ x, const float* __restrict__ gamma,
    const float* __restrict__ beta, __half* __restrict__ o)
{
    int row = blockIdx.x;
    int t = threadIdx.x;
    const float4* xr = reinterpret_cast<const float4*>(x + (size_t)row * DIMSZ);
    float4 v = xr[t];
    float s  = v.x + v.y + v.z + v.w;
    float ss = v.x*v.x + v.y*v.y + v.z*v.z + v.w*v.w;
    #pragma unroll
    for (int off = 16; off; off >>= 1) {
        s  += __shfl_xor_sync(0xffffffffu, s,  off);
        ss += __shfl_xor_sync(0xffffffffu, ss, off);
    }
    __shared__ float sbuf[8], ssbuf[8];
    __shared__ float s_mu, s_rstd;
    int w = t >> 5, lane = t & 31;
    if (lane == 0) { sbuf[w] = s; ssbuf[w] = ss; }
    __syncthreads();
    if (t == 0) {
        float S = 0.f, SS = 0.f;
        #pragma unroll
        for (int i = 0; i < 8; i++) { S += sbuf[i]; SS += ssbuf[i]; }
        float mu = S * (1.0f / DIMSZ);
        float var = SS * (1.0f / DIMSZ) - mu * mu;
        s_mu = mu; s_rstd = rsqrtf(var + 1e-5f);
    }
    __syncthreads();
    float mu = s_mu, rstd = s_rstd;
    float4 g  = reinterpret_cast<const float4*>(gamma)[t];
    float4 bt = reinterpret_cast<const float4*>(beta)[t];
    float o0 = (v.x - mu) * rstd * g.x + bt.x;
    float o1 = (v.y - mu) * rstd * g.y + bt.y;
    float o2 = (v.z - mu) * rstd * g.z + bt.z;
    float o3 = (v.w - mu) * rstd * g.w + bt.w;
    uint2 pk = {h2u(o0, o1), h2u(o2, o3)};
    *reinterpret_cast<uint2*>(o + (size_t)row * DIMSZ + t * 4) = pk;
}

// ------------- weight transpose: in [K][N] fp32 -> out [N][K] fp16 -----------
__global__ void __launch_bounds__(256) transpose_kernel(
    const float* __restrict__ in, __half* __restrict__ o, int K, int N)
{
    __shared__ float t[32][33];
    int n0 = blockIdx.x * 32, k0 = blockIdx.y * 32;
    int tx = threadIdx.x, ty = threadIdx.y;  // 32 x 8
    #pragma unroll
    for (int i = 0; i < 4; i++)
        t[ty + i*8][tx] = in[(size_t)(k0 + ty + i*8) * N + n0 + tx];
    __syncthreads();
    #pragma unroll
    for (int i = 0; i < 4; i++)
        o[(size_t)(n0 + ty + i*8) * K + k0 + tx] = __float2half_rn(t[tx][ty + i*8]);
}

// ---------------- fp16 warp-mma GEMM (ldmatrix fragments) --------------------
// C[M,Ntot] = A[M,1024] @ B[Ntot,1024]^T, K=1024, fp16 inputs, fp32 accum.
// CTA 128x128, BK=16, 8 warps (2m x 4n), warp tile 64x32.
// 48B-stride rows, 6 ldmatrix.x4 + 16 HMMA per chunk.
// 4-stage cp.async ring, wait_group 2, one sync/iter, 2 CTAs/SM.
#define HS_ROWB   48
#define HS_ARR    (128 * HS_ROWB)      // 6144
#define HS_STAGE  (2 * HS_ARR)         // 12288 (A, B)
#define HS_NSTAGE 4
#define HS_SMEM   (HS_NSTAGE * HS_STAGE)   // 49152

__global__ void __launch_bounds__(256, 2) hf_gemm_kernel(
    const __half* __restrict__ A, const __half* __restrict__ B,
    const float* __restrict__ bias, float* __restrict__ C, int Ntot)
{
    extern __shared__ char sm[];
    const int tid = threadIdx.x, lane = tid & 31, wid = tid >> 5;
    const int wm = wid >> 2, wn = wid & 3;
    const int c0 = blockIdx.x * 128, r0 = blockIdx.y * 128;
    const int lr = lane >> 2, lc = lane & 3;
    uint32_t sbase = smem_u32(sm);

    auto issue = [&](int c, int st) {
        int k0 = c * 16;
        #pragma unroll
        for (int i = 0; i < 2; i++) {
            int q = tid + i * 256;           // 0..511
            int arr = q >> 8, rem = q & 255;
            int row = rem >> 1, seg = rem & 1;
            const __half* s = (arr == 0)
                ? A + (size_t)(r0 + row) * 1024 + k0 + seg * 8
                : B + (size_t)(c0 + row) * 1024 + k0 + seg * 8;
            cp16(sbase + st * HS_STAGE + arr * HS_ARR + row * HS_ROWB + seg * 16, s);
        }
        asm volatile("cp.async.commit_group;" ::: "memory");
    };

    float acc[4][4][4];
    #pragma unroll
    for (int a = 0; a < 4; a++)
        #pragma unroll
        for (int b = 0; b < 4; b++)
            #pragma unroll
            for (int cc = 0; cc < 4; cc++) acc[a][b][cc] = 0.f;

    issue(0, 0);
    issue(1, 1);
    issue(2, 2);

    const int mat  = lane >> 3;
    const int roff = (mat & 1) * 8 + (lane & 7);
    const int cofs = (mat >> 1) * 16;

    const int NCHUNK = 1024 / 16;   // 64
    for (int c = 0; c < NCHUNK; c++) {
        asm volatile("cp.async.wait_group 2;" ::: "memory");
        __syncthreads();

        if (c + 3 < NCHUNK) issue(c + 3, (c + 3) & 3);
        else asm volatile("cp.async.commit_group;" ::: "memory");

        uint32_t base = sbase + (c & 3) * HS_STAGE;

        uint32_t ah[4][4], bh[2][4];
        #pragma unroll
        for (int nt2 = 0; nt2 < 2; nt2++)
            ldm4(bh[nt2], base + HS_ARR + (wn*32 + nt2*16 + roff) * HS_ROWB + cofs);
        #pragma unroll
        for (int mt = 0; mt < 4; mt++)
            ldm4(ah[mt], base + (wm*64 + mt*16 + roff) * HS_ROWB + cofs);

        #pragma unroll
        for (int mt = 0; mt < 4; mt++)
            #pragma unroll
            for (int nt = 0; nt < 4; nt++) {
                int n2 = nt >> 1, hf = nt & 1;
                mma_f16(acc[mt][nt], ah[mt], bh[n2][hf], bh[n2][2+hf]);
            }
    }

    #pragma unroll
    for (int mt = 0; mt < 4; mt++) {
        int rbase = r0 + wm*64 + mt*16 + lr;
        #pragma unroll
        for (int nt = 0; nt < 4; nt++) {
            int col = c0 + wn*32 + nt*8 + 2*lc;
            float b0v = bias ? bias[col] : 0.f;
            float b1v = bias ? bias[col + 1] : 0.f;
            float2 v0 = {acc[mt][nt][0] + b0v, acc[mt][nt][1] + b1v};
            float2 v1 = {acc[mt][nt][2] + b0v, acc[mt][nt][3] + b1v};
            *reinterpret_cast<float2*>(C + (size_t)rbase * Ntot + col) = v0;
            *reinterpret_cast<float2*>(C + (size_t)(rbase + 8) * Ntot + col) = v1;
        }
    }
}

// ---------------- flash attention: fp16 QK + fp16 PV -------------------------
// CTA: 128 q rows (8 warps x m16), kv-tile 64. Q prescaled by 0.125, fp16.
// K rows: 36-u32 stride (banks 4lr+lc distinct). V: swizzled fp16 rows.
#define FAH_SMEM 18432   // max(Q stage 128*36*4, K 64*36*4 + V 64*128 = 17408)

__global__ void __launch_bounds__(256, 1) fa_kernel(
    const float* __restrict__ qkv, __half* __restrict__ outh)
{
    extern __shared__ char sm[];
    uint32_t* Ks = reinterpret_cast<uint32_t*>(sm);       // [64][36] u32 (fp16 x2)
    char* Vs = sm + 64 * 36 * 4;                          // [64][128B] swizzled fp16
    uint32_t* Qs = reinterpret_cast<uint32_t*>(sm);       // [128][36] (init only)

    const int tid = threadIdx.x, lane = tid & 31, wid = tid >> 5;
    const int qt = blockIdx.x, hd = blockIdx.y, b = blockIdx.z;
    const int n0 = qt * 128;
    const int lr = lane >> 2, lc = lane & 3;

    const float* qb = qkv + (size_t)b * SEQ * QKV3 + hd * DHEAD;
    const float* kb = qb + 1024;
    const float* vb = qb + 2048;

    // stage Q (prescaled, fp16)
    #pragma unroll
    for (int i = 0; i < 8; i++) {
        int q = tid + i * 256;
        int row = q >> 4, c4 = (q & 15) * 4;
        float4 v = *reinterpret_cast<const float4*>(qb + (size_t)(n0 + row) * QKV3 + c4);
        uint2 pk = {h2u(v.x * 0.125f, v.y * 0.125f), h2u(v.z * 0.125f, v.w * 0.125f)};
        *reinterpret_cast<uint2*>(&Qs[row * 36 + (q & 15) * 2]) = pk;
    }
    __syncthreads();

    // Q fragments: 4 k16-steps x 4 regs (fp16 A layout)
    uint32_t qa[4][4];
    {
        int m0 = wid * 16;
        #pragma unroll
        for (int u = 0; u < 4; u++) {
            qa[u][0] = Qs[(m0 + lr)     * 36 + u*8 + lc];
            qa[u][1] = Qs[(m0 + 8 + lr) * 36 + u*8 + lc];
            qa[u][2] = Qs[(m0 + lr)     * 36 + u*8 + lc + 4];
            qa[u][3] = Qs[(m0 + 8 + lr) * 36 + u*8 + lc + 4];
        }
    }
    __syncthreads();

    float m_i[2] = {-1e30f, -1e30f}, l_i[2] = {0.f, 0.f};
    float o[8][4];
    #pragma unroll
    for (int v = 0; v < 8; v++)
        #pragma unroll
        for (int j = 0; j < 4; j++) o[v][j] = 0.f;

    const uint32_t vsb = smem_u32(Vs);

    for (int kt = 0; kt < SEQ / 64; kt++) {
        int s0 = kt * 64;
        #pragma unroll
        for (int i = 0; i < 4; i++) {
            int q = tid + i * 256;
            int row = q >> 4, c4 = (q & 15) * 4;
            float4 kv = *reinterpret_cast<const float4*>(kb + (size_t)(s0 + row) * QKV3 + c4);
            uint2 kp = {h2u(kv.x, kv.y), h2u(kv.z, kv.w)};
            *reinterpret_cast<uint2*>(&Ks[row * 36 + (q & 15) * 2]) = kp;
            float4 vv = *reinterpret_cast<const float4*>(vb + (size_t)(s0 + row) * QKV3 + c4);
            uint2 hp = {h2u(vv.x, vv.y), h2u(vv.z, vv.w)};
            uint32_t off = row * 128 + c4 * 2;
            off ^= ((off >> 7) & 7) << 4;
            *reinterpret_cast<uint2*>(Vs + off) = hp;
        }
        __syncthreads();

        // S = Q K^T  (fp16, fp32 accum): 32 MMAs
        float s[8][4];
        #pragma unroll
        for (int v = 0; v < 8; v++)
            #pragma unroll
            for (int j = 0; j < 4; j++) s[v][j] = 0.f;
        #pragma unroll
        for (int u = 0; u < 4; u++) {
            #pragma unroll
            for (int v = 0; v < 8; v++) {
                uint32_t kb0 = Ks[(v*8 + lr) * 36 + u*8 + lc];
                uint32_t kb1 = Ks[(v*8 + lr) * 36 + u*8 + lc + 4];
                mma_f16(s[v], qa[u], kb0, kb1);
            }
        }

        // online softmax (rows: lr and lr+8)
        #pragma unroll
        for (int h = 0; h < 2; h++) {
            float mx = -1e30f;
            #pragma unroll
            for (int v = 0; v < 8; v++)
                mx = fmaxf(mx, fmaxf(s[v][2*h], s[v][2*h+1]));
            mx = fmaxf(mx, __shfl_xor_sync(0xffffffffu, mx, 1));
            mx = fmaxf(mx, __shfl_xor_sync(0xffffffffu, mx, 2));
            float mnew = fmaxf(m_i[h], mx);
            float alpha = __expf(m_i[h] - mnew);
            m_i[h] = mnew;
            float rs = 0.f;
            #pragma unroll
            for (int v = 0; v < 8; v++) {
                s[v][2*h]   = __expf(s[v][2*h]   - mnew);
                s[v][2*h+1] = __expf(s[v][2*h+1] - mnew);
                rs += s[v][2*h] + s[v][2*h+1];
            }
            rs += __shfl_xor_sync(0xffffffffu, rs, 1);
            rs += __shfl_xor_sync(0xffffffffu, rs, 2);
            l_i[h] = l_i[h] * alpha + rs;
            #pragma unroll
            for (int v = 0; v < 8; v++) {
                o[v][2*h]   *= alpha;
                o[v][2*h+1] *= alpha;
            }
        }

        // pack P to fp16 A-fragments
        uint32_t pa[4][4];
        #pragma unroll
        for (int u = 0; u < 4; u++) {
            pa[u][0] = h2u(s[2*u][0],   s[2*u][1]);
            pa[u][1] = h2u(s[2*u][2],   s[2*u][3]);
            pa[u][2] = h2u(s[2*u+1][0], s[2*u+1][1]);
            pa[u][3] = h2u(s[2*u+1][2], s[2*u+1][3]);
        }

        // O += P V  (fp16 MMA, fp32 accum)
        #pragma unroll
        for (int u = 0; u < 4; u++) {
            #pragma unroll
            for (int w2 = 0; w2 < 4; w2++) {
                int mt = lane >> 3;
                int row = u*16 + (mt & 1) * 8 + (lane & 7);
                int colb = w2*32 + (mt >> 1) * 16;
                uint32_t off = (uint32_t)(row * 128 + colb);
                off ^= ((off >> 7) & 7) << 4;
                uint32_t r[4];
                ldm4t(r, vsb + off);
                mma_f16(o[2*w2],     pa[u], r[0], r[1]);
                mma_f16(o[2*w2 + 1], pa[u], r[2], r[3]);
            }
        }
        __syncthreads();
    }

    // epilogue: normalize + fp16 store
    #pragma unroll
    for (int h = 0; h < 2; h++) {
        float inv = 1.f / l_i[h];
        int rowg = b * SEQ + n0 + wid*16 + h*8 + lr;
        #pragma unroll
        for (int v = 0; v < 8; v++) {
            int col = hd * 64 + v*8 + 2*lc;
            uint32_t pk = h2u(o[v][2*h] * inv, o[v][2*h+1] * inv);
            *reinterpret_cast<uint32_t*>(outh + (size_t)rowg * INNER + col) = pk;
        }
    }
}

// ---------------- launcher ---------------------------------------------------
extern "C" void kernel_launch(void* const* d_in, const int* in_sizes, int n_in,
                              void* d_out, int out_size)
{
    const float* x     = (const float*)d_in[0];
    const float* gamma = (const float*)d_in[1];
    const float* beta  = (const float*)d_in[2];
    const float* Wqkv  = (const float*)d_in[3];
    const float* Wout  = (const float*)d_in[4];
    const float* bout  = (const float*)d_in[5];
    float* out = (float*)d_out;

    float* qkvbuf;
    __half *xnh, *wqt, *wot, *aoh;
    cudaGetSymbolAddress((void**)&qkvbuf, g_qkv);
    cudaGetSymbolAddress((void**)&xnh, g_xnh);
    cudaGetSymbolAddress((void**)&wqt, g_wqt);
    cudaGetSymbolAddress((void**)&wot, g_wot);
    cudaGetSymbolAddress((void**)&aoh, g_aoh);

    cudaFuncSetAttribute(hf_gemm_kernel,
                         cudaFuncAttributeMaxDynamicSharedMemorySize, HS_SMEM);

    ln_kernel<<<ROWS, 256>>>(x, gamma, beta, xnh);

    transpose_kernel<<<dim3(QKV3 / 32, DIMSZ / 32), dim3(32, 8)>>>(
        Wqkv, wqt, DIMSZ, QKV3);
    transpose_kernel<<<dim3(DIMSZ / 32, DIMSZ / 32), dim3(32, 8)>>>(
        Wout, wot, INNER, DIMSZ);

    hf_gemm_kernel<<<dim3(QKV3 / 128, ROWS / 128), 256, HS_SMEM>>>(
        xnh, wqt, nullptr, qkvbuf, QKV3);

    fa_kernel<<<dim3(SEQ / 128, HEADS, BATCH), 256, FAH_SMEM>>>(qkvbuf, aoh);

    hf_gemm_kernel<<<dim3(DIMSZ / 128, ROWS / 128), 256, HS_SMEM>>>(
        aoh, wot, bout, out, DIMSZ);
}

// round 11
// speedup vs baseline: 2.4037x; 1.2336x over previous
#include <cuda_runtime.h>
#include <cuda_bf16.h>
#include <cuda_fp16.h>
#include <cstdint>

#define BATCH 2
#define SEQ   2048
#define DIMSZ 1024
#define HEADS 16
#define DHEAD 64
#define INNER 1024
#define QKV3  3072
#define ROWS  (BATCH * SEQ)   // 4096

// ---------------- scratch (static device globals; no allocation) -------------
__device__ __half g_qkvh[ROWS * QKV3];    // 25 MB fp16 (Q prescaled by 0.125)
__device__ __half g_xnh[ROWS * DIMSZ];    // LN out fp16
__device__ __half g_wqt[QKV3 * DIMSZ];    // Wqkv^T [3072][1024] fp16
__device__ __half g_wot[DIMSZ * INNER];   // Wout^T [1024][1024] fp16
__device__ __half g_aoh[ROWS * INNER];    // attention out fp16

// ---------------- helpers ----------------------------------------------------
__device__ __forceinline__ uint32_t smem_u32(const void* p) {
    uint32_t a;
    asm("{ .reg .u64 t; cvta.to.shared.u64 t, %1; cvt.u32.u64 %0, t; }"
        : "=r"(a) : "l"(p));
    return a;
}
__device__ __forceinline__ void cp16(uint32_t dst, const void* src) {
    asm volatile("cp.async.cg.shared.global [%0], [%1], 16;"
                 :: "r"(dst), "l"(src) : "memory");
}
__device__ __forceinline__ void ldm4(uint32_t* r, uint32_t addr) {
    asm volatile("ldmatrix.sync.aligned.m8n8.x4.shared.b16 {%0,%1,%2,%3}, [%4];"
        : "=r"(r[0]), "=r"(r[1]), "=r"(r[2]), "=r"(r[3]) : "r"(addr));
}
__device__ __forceinline__ void ldm4t(uint32_t* r, uint32_t addr) {
    asm volatile("ldmatrix.sync.aligned.m8n8.x4.trans.shared.b16 {%0,%1,%2,%3}, [%4];"
        : "=r"(r[0]), "=r"(r[1]), "=r"(r[2]), "=r"(r[3]) : "r"(addr));
}
__device__ __forceinline__ void mma_f16(float* d, const uint32_t* a,
                                        uint32_t b0, uint32_t b1) {
    asm volatile("mma.sync.aligned.m16n8k16.row.col.f32.f16.f16.f32 "
        "{%0,%1,%2,%3}, {%4,%5,%6,%7}, {%8,%9}, {%0,%1,%2,%3};"
        : "+f"(d[0]), "+f"(d[1]), "+f"(d[2]), "+f"(d[3])
        : "r"(a[0]), "r"(a[1]), "r"(a[2]), "r"(a[3]), "r"(b0), "r"(b1));
}
__device__ __forceinline__ uint32_t h2u(float a, float b) {
    __half2 h = __floats2half2_rn(a, b);
    return *reinterpret_cast<uint32_t*>(&h);
}

// ---------------- LayerNorm -> fp16 -------------------------------------------
__global__ void __launch_bounds__(256) ln_kernel(
    const float* __restrict__ x, const float* __restrict__ gamma,
    const float* __restrict__ beta, __half* __restrict__ o)
{
    int row = blockIdx.x;
    int t = threadIdx.x;
    const float4* xr = reinterpret_cast<const float4*>(x + (size_t)row * DIMSZ);
    float4 v = xr[t];
    float s  = v.x + v.y + v.z + v.w;
    float ss = v.x*v.x + v.y*v.y + v.z*v.z + v.w*v.w;
    #pragma unroll
    for (int off = 16; off; off >>= 1) {
        s  += __shfl_xor_sync(0xffffffffu, s,  off);
        ss += __shfl_xor_sync(0xffffffffu, ss, off);
    }
    __shared__ float sbuf[8], ssbuf[8];
    __shared__ float s_mu, s_rstd;
    int w = t >> 5, lane = t & 31;
    if (lane == 0) { sbuf[w] = s; ssbuf[w] = ss; }
    __syncthreads();
    if (t == 0) {
        float S = 0.f, SS = 0.f;
        #pragma unroll
        for (int i = 0; i < 8; i++) { S += sbuf[i]; SS += ssbuf[i]; }
        float mu = S * (1.0f / DIMSZ);
        float var = SS * (1.0f / DIMSZ) - mu * mu;
        s_mu = mu; s_rstd = rsqrtf(var + 1e-5f);
    }
    __syncthreads();
    float mu = s_mu, rstd = s_rstd;
    float4 g  = reinterpret_cast<const float4*>(gamma)[t];
    float4 bt = reinterpret_cast<const float4*>(beta)[t];
    float o0 = (v.x - mu) * rstd * g.x + bt.x;
    float o1 = (v.y - mu) * rstd * g.y + bt.y;
    float o2 = (v.z - mu) * rstd * g.z + bt.z;
    float o3 = (v.w - mu) * rstd * g.w + bt.w;
    uint2 pk = {h2u(o0, o1), h2u(o2, o3)};
    *reinterpret_cast<uint2*>(o + (size_t)row * DIMSZ + t * 4) = pk;
}

// ------------- weight transpose: in [K][N] fp32 -> out [N][K] fp16 -----------
__global__ void __launch_bounds__(256) transpose_kernel(
    const float* __restrict__ in, __half* __restrict__ o, int K, int N)
{
    __shared__ float t[32][33];
    int n0 = blockIdx.x * 32, k0 = blockIdx.y * 32;
    int tx = threadIdx.x, ty = threadIdx.y;  // 32 x 8
    #pragma unroll
    for (int i = 0; i < 4; i++)
        t[ty + i*8][tx] = in[(size_t)(k0 + ty + i*8) * N + n0 + tx];
    __syncthreads();
    #pragma unroll
    for (int i = 0; i < 4; i++)
        o[(size_t)(n0 + ty + i*8) * K + k0 + tx] = __float2half_rn(t[tx][ty + i*8]);
}

// ---------------- fp16 warp-mma GEMM, BK=32 ----------------------------------
// C[M,Ntot] = A[M,1024] @ B[Ntot,1024]^T, fp16 in, fp32 accum.
// CTA 128x128, BK=32, 8 warps (2m x 4n), warp tile 64x32.
// 80B-stride rows (phases {0,80,32,112,64,16,96,48} conflict-free ldmatrix).
// 4-stage cp.async ring, wait_group 2, one sync/iter, 2 CTAs/SM.
// HALF_OUT: store fp16 with per-column scale (0.125 for cols<1024: Q prescale).
#define HS_ROWB   80
#define HS_ARR    (128 * HS_ROWB)      // 10240
#define HS_STAGE  (2 * HS_ARR)         // 20480 (A, B)
#define HS_NSTAGE 4
#define HS_SMEM   (HS_NSTAGE * HS_STAGE)   // 81920

template <bool HALF_OUT>
__global__ void __launch_bounds__(256, 2) hf_gemm_kernel(
    const __half* __restrict__ A, const __half* __restrict__ B,
    const float* __restrict__ bias, void* __restrict__ Cv, int Ntot)
{
    extern __shared__ char sm[];
    const int tid = threadIdx.x, lane = tid & 31, wid = tid >> 5;
    const int wm = wid >> 2, wn = wid & 3;
    const int c0 = blockIdx.x * 128, r0 = blockIdx.y * 128;
    const int lr = lane >> 2, lc = lane & 3;
    uint32_t sbase = smem_u32(sm);

    // per stage: 2 arrays * 128 rows * 64B -> 1024 cp16, 4/thread
    auto issue = [&](int c, int st) {
        int k0 = c * 32;
        #pragma unroll
        for (int i = 0; i < 4; i++) {
            int q = tid + i * 256;           // 0..1023
            int arr = q >> 9, rem = q & 511;
            int row = rem >> 2, seg = rem & 3;
            const __half* s = (arr == 0)
                ? A + (size_t)(r0 + row) * 1024 + k0 + seg * 8
                : B + (size_t)(c0 + row) * 1024 + k0 + seg * 8;
            cp16(sbase + st * HS_STAGE + arr * HS_ARR + row * HS_ROWB + seg * 16, s);
        }
        asm volatile("cp.async.commit_group;" ::: "memory");
    };

    float acc[4][4][4];
    #pragma unroll
    for (int a = 0; a < 4; a++)
        #pragma unroll
        for (int b = 0; b < 4; b++)
            #pragma unroll
            for (int cc = 0; cc < 4; cc++) acc[a][b][cc] = 0.f;

    issue(0, 0);
    issue(1, 1);
    issue(2, 2);

    const int mat  = lane >> 3;
    const int roff = (mat & 1) * 8 + (lane & 7);
    const int cofs = (mat >> 1) * 16;

    const int NCHUNK = 1024 / 32;   // 32
    for (int c = 0; c < NCHUNK; c++) {
        asm volatile("cp.async.wait_group 2;" ::: "memory");
        __syncthreads();

        if (c + 3 < NCHUNK) issue(c + 3, (c + 3) & 3);
        else asm volatile("cp.async.commit_group;" ::: "memory");

        uint32_t base = sbase + (c & 3) * HS_STAGE;

        #pragma unroll
        for (int ks = 0; ks < 2; ks++) {
            uint32_t ah[4][4], bh[2][4];
            #pragma unroll
            for (int nt2 = 0; nt2 < 2; nt2++)
                ldm4(bh[nt2], base + HS_ARR + (wn*32 + nt2*16 + roff) * HS_ROWB
                               + ks*32 + cofs);
            #pragma unroll
            for (int mt = 0; mt < 4; mt++)
                ldm4(ah[mt], base + (wm*64 + mt*16 + roff) * HS_ROWB + ks*32 + cofs);

            #pragma unroll
            for (int mt = 0; mt < 4; mt++)
                #pragma unroll
                for (int nt = 0; nt < 4; nt++) {
                    int n2 = nt >> 1, hf = nt & 1;
                    mma_f16(acc[mt][nt], ah[mt], bh[n2][hf], bh[n2][2+hf]);
                }
        }
    }

    #pragma unroll
    for (int mt = 0; mt < 4; mt++) {
        int rbase = r0 + wm*64 + mt*16 + lr;
        #pragma unroll
        for (int nt = 0; nt < 4; nt++) {
            int col = c0 + wn*32 + nt*8 + 2*lc;
            if (HALF_OUT) {
                __half* C = (__half*)Cv;
                float sc = (col < 1024) ? 0.125f : 1.0f;   // Q prescale
                *reinterpret_cast<uint32_t*>(C + (size_t)rbase * Ntot + col) =
                    h2u(acc[mt][nt][0] * sc, acc[mt][nt][1] * sc);
                *reinterpret_cast<uint32_t*>(C + (size_t)(rbase + 8) * Ntot + col) =
                    h2u(acc[mt][nt][2] * sc, acc[mt][nt][3] * sc);
            } else {
                float* C = (float*)Cv;
                float b0v = bias ? bias[col] : 0.f;
                float b1v = bias ? bias[col + 1] : 0.f;
                float2 v0 = {acc[mt][nt][0] + b0v, acc[mt][nt][1] + b1v};
                float2 v1 = {acc[mt][nt][2] + b0v, acc[mt][nt][3] + b1v};
                *reinterpret_cast<float2*>(C + (size_t)rbase * Ntot + col) = v0;
                *reinterpret_cast<float2*>(C + (size_t)(rbase + 8) * Ntot + col) = v1;
            }
        }
    }
}

// ---------------- flash attention: fp16 QK + fp16 PV, cp.async staged --------
// CTA: 128 q rows (8 warps x m16), kv-tile 64, double-buffered K/V prefetch.
// qkv is fp16, Q already prescaled. K rows 144B stride; V swizzled 128B rows.
#define FA_QS    18432                    // Q: 128 * 144
#define FA_KB    9216                     // K stage: 64 * 144
#define FA_VB    8192                     // V stage: 64 * 128
#define FA_STAGE (FA_KB + FA_VB)          // 17408
#define FAH_SMEM (FA_QS + 2 * FA_STAGE)   // 53248

__global__ void __launch_bounds__(256, 2) fa_kernel(
    const __half* __restrict__ qkv, __half* __restrict__ outh)
{
    extern __shared__ char sm[];
    const int tid = threadIdx.x, lane = tid & 31, wid = tid >> 5;
    const int qt = blockIdx.x, hd = blockIdx.y, b = blockIdx.z;
    const int n0 = qt * 128;
    const int lr = lane >> 2, lc = lane & 3;
    uint32_t sbase = smem_u32(sm);

    const __half* qb = qkv + (size_t)b * SEQ * QKV3 + hd * DHEAD;
    const __half* kb = qb + 1024;
    const __half* vb = qb + 2048;

    // stage Q via cp.async: 128 rows * 128B = 1024 chunks, 4/thread
    #pragma unroll
    for (int i = 0; i < 4; i++) {
        int q = tid + i * 256;
        int row = q >> 3, ch = q & 7;
        cp16(sbase + row * 144 + ch * 16,
             qb + (size_t)(n0 + row) * QKV3 + ch * 8);
    }
    asm volatile("cp.async.commit_group;" ::: "memory");

    // issue K/V tile kt into stage st: 512+512 chunks, 4/thread
    auto issueKV = [&](int kt, int st) {
        int s0 = kt * 64;
        uint32_t kbase = sbase + FA_QS + st * FA_STAGE;
        uint32_t vbase = kbase + FA_KB;
        #pragma unroll
        for (int i = 0; i < 4; i++) {
            int q = tid + i * 256;
            int arr = q >> 9, rem = q & 511;
            int row = rem >> 3, ch = rem & 7;
            if (arr == 0) {
                cp16(kbase + row * 144 + ch * 16,
                     kb + (size_t)(s0 + row) * QKV3 + ch * 8);
            } else {
                uint32_t off = (uint32_t)(row * 128 + ch * 16);
                off ^= ((off >> 7) & 7) << 4;
                cp16(vbase + off, vb + (size_t)(s0 + row) * QKV3 + ch * 8);
            }
        }
        asm volatile("cp.async.commit_group;" ::: "memory");
    };

    issueKV(0, 0);
    asm volatile("cp.async.wait_group 0;" ::: "memory");
    __syncthreads();

    // Q fragments from smem (u32 view, stride 36 u32 = 144B)
    const uint32_t* Qs = reinterpret_cast<const uint32_t*>(sm);
    uint32_t qa[4][4];
    {
        int m0 = wid * 16;
        #pragma unroll
        for (int u = 0; u < 4; u++) {
            qa[u][0] = Qs[(m0 + lr)     * 36 + u*8 + lc];
            qa[u][1] = Qs[(m0 + 8 + lr) * 36 + u*8 + lc];
            qa[u][2] = Qs[(m0 + lr)     * 36 + u*8 + lc + 4];
            qa[u][3] = Qs[(m0 + 8 + lr) * 36 + u*8 + lc + 4];
        }
    }

    float m_i[2] = {-1e30f, -1e30f}, l_i[2] = {0.f, 0.f};
    float o[8][4];
    #pragma unroll
    for (int v = 0; v < 8; v++)
        #pragma unroll
        for (int j = 0; j < 4; j++) o[v][j] = 0.f;

    const int NT = SEQ / 64;   // 32
    for (int kt = 0; kt < NT; kt++) {
        if (kt > 0) {
            asm volatile("cp.async.wait_group 0;" ::: "memory");
            __syncthreads();
        }
        if (kt + 1 < NT) issueKV(kt + 1, (kt + 1) & 1);

        int st = kt & 1;
        const uint32_t* Ks = reinterpret_cast<const uint32_t*>(
            sm + FA_QS + st * FA_STAGE);
        const uint32_t vsb = sbase + FA_QS + st * FA_STAGE + FA_KB;

        // S = Q K^T  (fp16, fp32 accum): 32 MMAs
        float s[8][4];
        #pragma unroll
        for (int v = 0; v < 8; v++)
            #pragma unroll
            for (int j = 0; j < 4; j++) s[v][j] = 0.f;
        #pragma unroll
        for (int u = 0; u < 4; u++) {
            #pragma unroll
            for (int v = 0; v < 8; v++) {
                uint32_t kb0 = Ks[(v*8 + lr) * 36 + u*8 + lc];
                uint32_t kb1 = Ks[(v*8 + lr) * 36 + u*8 + lc + 4];
                mma_f16(s[v], qa[u], kb0, kb1);
            }
        }

        // online softmax (rows: lr and lr+8)
        #pragma unroll
        for (int h = 0; h < 2; h++) {
            float mx = -1e30f;
            #pragma unroll
            for (int v = 0; v < 8; v++)
                mx = fmaxf(mx, fmaxf(s[v][2*h], s[v][2*h+1]));
            mx = fmaxf(mx, __shfl_xor_sync(0xffffffffu, mx, 1));
            mx = fmaxf(mx, __shfl_xor_sync(0xffffffffu, mx, 2));
            float mnew = fmaxf(m_i[h], mx);
            float alpha = __expf(m_i[h] - mnew);
            m_i[h] = mnew;
            float rs = 0.f;
            #pragma unroll
            for (int v = 0; v < 8; v++) {
                s[v][2*h]   = __expf(s[v][2*h]   - mnew);
                s[v][2*h+1] = __expf(s[v][2*h+1] - mnew);
                rs += s[v][2*h] + s[v][2*h+1];
            }
            rs += __shfl_xor_sync(0xffffffffu, rs, 1);
            rs += __shfl_xor_sync(0xffffffffu, rs, 2);
            l_i[h] = l_i[h] * alpha + rs;
            #pragma unroll
            for (int v = 0; v < 8; v++) {
                o[v][2*h]   *= alpha;
                o[v][2*h+1] *= alpha;
            }
        }

        // pack P to fp16 A-fragments
        uint32_t pa[4][4];
        #pragma unroll
        for (int u = 0; u < 4; u++) {
            pa[u][0] = h2u(s[2*u][0],   s[2*u][1]);
            pa[u][1] = h2u(s[2*u][2],   s[2*u][3]);
            pa[u][2] = h2u(s[2*u+1][0], s[2*u+1][1]);
            pa[u][3] = h2u(s[2*u+1][2], s[2*u+1][3]);
        }

        // O += P V  (fp16 MMA, fp32 accum)
        #pragma unroll
        for (int u = 0; u < 4; u++) {
            #pragma unroll
            for (int w2 = 0; w2 < 4; w2++) {
                int mt = lane >> 3;
                int row = u*16 + (mt & 1) * 8 + (lane & 7);
                int colb = w2*32 + (mt >> 1) * 16;
                uint32_t off = (uint32_t)(row * 128 + colb);
                off ^= ((off >> 7) & 7) << 4;
                uint32_t r[4];
                ldm4t(r, vsb + off);
                mma_f16(o[2*w2],     pa[u], r[0], r[1]);
                mma_f16(o[2*w2 + 1], pa[u], r[2], r[3]);
            }
        }
    }

    // epilogue: normalize + fp16 store
    #pragma unroll
    for (int h = 0; h < 2; h++) {
        float inv = 1.f / l_i[h];
        int rowg = b * SEQ + n0 + wid*16 + h*8 + lr;
        #pragma unroll
        for (int v = 0; v < 8; v++) {
            int col = hd * 64 + v*8 + 2*lc;
            uint32_t pk = h2u(o[v][2*h] * inv, o[v][2*h+1] * inv);
            *reinterpret_cast<uint32_t*>(outh + (size_t)rowg * INNER + col) = pk;
        }
    }
}

// ---------------- launcher ---------------------------------------------------
extern "C" void kernel_launch(void* const* d_in, const int* in_sizes, int n_in,
                              void* d_out, int out_size)
{
    const float* x     = (const float*)d_in[0];
    const float* gamma = (const float*)d_in[1];
    const float* beta  = (const float*)d_in[2];
    const float* Wqkv  = (const float*)d_in[3];
    const float* Wout  = (const float*)d_in[4];
    const float* bout  = (const float*)d_in[5];
    float* out = (float*)d_out;

    __half *qkvh, *xnh, *wqt, *wot, *aoh;
    cudaGetSymbolAddress((void**)&qkvh, g_qkvh);
    cudaGetSymbolAddress((void**)&xnh, g_xnh);
    cudaGetSymbolAddress((void**)&wqt, g_wqt);
    cudaGetSymbolAddress((void**)&wot, g_wot);
    cudaGetSymbolAddress((void**)&aoh, g_aoh);

    cudaFuncSetAttribute(hf_gemm_kernel<true>,
                         cudaFuncAttributeMaxDynamicSharedMemorySize, HS_SMEM);
    cudaFuncSetAttribute(hf_gemm_kernel<false>,
                         cudaFuncAttributeMaxDynamicSharedMemorySize, HS_SMEM);
    cudaFuncSetAttribute(fa_kernel,
                         cudaFuncAttributeMaxDynamicSharedMemorySize, FAH_SMEM);

    ln_kernel<<<ROWS, 256>>>(x, gamma, beta, xnh);

    transpose_kernel<<<dim3(QKV3 / 32, DIMSZ / 32), dim3(32, 8)>>>(
        Wqkv, wqt, DIMSZ, QKV3);
    transpose_kernel<<<dim3(DIMSZ / 32, DIMSZ / 32), dim3(32, 8)>>>(
        Wout, wot, INNER, DIMSZ);

    hf_gemm_kernel<true><<<dim3(QKV3 / 128, ROWS / 128), 256, HS_SMEM>>>(
        xnh, wqt, nullptr, qkvh, QKV3);

    fa_kernel<<<dim3(SEQ / 128, HEADS, BATCH), 256, FAH_SMEM>>>(qkvh, aoh);

    hf_gemm_kernel<false><<<dim3(DIMSZ / 128, ROWS / 128), 256, HS_SMEM>>>(
        aoh, wot, bout, out, DIMSZ);
}

// round 12
// speedup vs baseline: 2.4720x; 1.0284x over previous
#include <cuda_runtime.h>
#include <cuda_bf16.h>
#include <cuda_fp16.h>
#include <cstdint>

#define BATCH 2
#define SEQ   2048
#define DIMSZ 1024
#define HEADS 16
#define DHEAD 64
#define INNER 1024
#define QKV3  3072
#define ROWS  (BATCH * SEQ)   // 4096

// ---------------- scratch (static device globals; no allocation) -------------
__device__ __half g_qkvh[ROWS * QKV3];    // 25 MB fp16 (Q prescaled by 0.125)
__device__ __half g_xnh[ROWS * DIMSZ];    // LN out fp16
__device__ __half g_wqt[QKV3 * DIMSZ];    // Wqkv^T [3072][1024] fp16
__device__ __half g_wot[DIMSZ * INNER];   // Wout^T [1024][1024] fp16
__device__ __half g_aoh[ROWS * INNER];    // attention out fp16

// ---------------- helpers ----------------------------------------------------
__device__ __forceinline__ uint32_t smem_u32(const void* p) {
    uint32_t a;
    asm("{ .reg .u64 t; cvta.to.shared.u64 t, %1; cvt.u32.u64 %0, t; }"
        : "=r"(a) : "l"(p));
    return a;
}
__device__ __forceinline__ void cp16(uint32_t dst, const void* src) {
    asm volatile("cp.async.cg.shared.global [%0], [%1], 16;"
                 :: "r"(dst), "l"(src) : "memory");
}
__device__ __forceinline__ void ldm4(uint32_t* r, uint32_t addr) {
    asm volatile("ldmatrix.sync.aligned.m8n8.x4.shared.b16 {%0,%1,%2,%3}, [%4];"
        : "=r"(r[0]), "=r"(r[1]), "=r"(r[2]), "=r"(r[3]) : "r"(addr));
}
__device__ __forceinline__ void ldm4t(uint32_t* r, uint32_t addr) {
    asm volatile("ldmatrix.sync.aligned.m8n8.x4.trans.shared.b16 {%0,%1,%2,%3}, [%4];"
        : "=r"(r[0]), "=r"(r[1]), "=r"(r[2]), "=r"(r[3]) : "r"(addr));
}
__device__ __forceinline__ void mma_f16(float* d, const uint32_t* a,
                                        uint32_t b0, uint32_t b1) {
    asm volatile("mma.sync.aligned.m16n8k16.row.col.f32.f16.f16.f32 "
        "{%0,%1,%2,%3}, {%4,%5,%6,%7}, {%8,%9}, {%0,%1,%2,%3};"
        : "+f"(d[0]), "+f"(d[1]), "+f"(d[2]), "+f"(d[3])
        : "r"(a[0]), "r"(a[1]), "r"(a[2]), "r"(a[3]), "r"(b0), "r"(b1));
}
__device__ __forceinline__ uint32_t h2u(float a, float b) {
    __half2 h = __floats2half2_rn(a, b);
    return *reinterpret_cast<uint32_t*>(&h);
}
__device__ __forceinline__ uint32_t ex2_h2(uint32_t packed) {
    uint32_t r;
    asm("ex2.approx.f16x2 %0, %1;" : "=r"(r) : "r"(packed));
    return r;
}

// ---------------- LayerNorm -> fp16 -------------------------------------------
__global__ void __launch_bounds__(256) ln_kernel(
    const float* __restrict__ x, const float* __restrict__ gamma,
    const float* __restrict__ beta, __half* __restrict__ o)
{
    int row = blockIdx.x;
    int t = threadIdx.x;
    const float4* xr = reinterpret_cast<const float4*>(x + (size_t)row * DIMSZ);
    float4 v = xr[t];
    float s  = v.x + v.y + v.z + v.w;
    float ss = v.x*v.x + v.y*v.y + v.z*v.z + v.w*v.w;
    #pragma unroll
    for (int off = 16; off; off >>= 1) {
        s  += __shfl_xor_sync(0xffffffffu, s,  off);
        ss += __shfl_xor_sync(0xffffffffu, ss, off);
    }
    __shared__ float sbuf[8], ssbuf[8];
    __shared__ float s_mu, s_rstd;
    int w = t >> 5, lane = t & 31;
    if (lane == 0) { sbuf[w] = s; ssbuf[w] = ss; }
    __syncthreads();
    if (t == 0) {
        float S = 0.f, SS = 0.f;
        #pragma unroll
        for (int i = 0; i < 8; i++) { S += sbuf[i]; SS += ssbuf[i]; }
        float mu = S * (1.0f / DIMSZ);
        float var = SS * (1.0f / DIMSZ) - mu * mu;
        s_mu = mu; s_rstd = rsqrtf(var + 1e-5f);
    }
    __syncthreads();
    float mu = s_mu, rstd = s_rstd;
    float4 g  = reinterpret_cast<const float4*>(gamma)[t];
    float4 bt = reinterpret_cast<const float4*>(beta)[t];
    float o0 = (v.x - mu) * rstd * g.x + bt.x;
    float o1 = (v.y - mu) * rstd * g.y + bt.y;
    float o2 = (v.z - mu) * rstd * g.z + bt.z;
    float o3 = (v.w - mu) * rstd * g.w + bt.w;
    uint2 pk = {h2u(o0, o1), h2u(o2, o3)};
    *reinterpret_cast<uint2*>(o + (size_t)row * DIMSZ + t * 4) = pk;
}

// ------------- weight transpose: in [K][N] fp32 -> out [N][K] fp16 -----------
__global__ void __launch_bounds__(256) transpose_kernel(
    const float* __restrict__ in, __half* __restrict__ o, int K, int N)
{
    __shared__ float t[32][33];
    int n0 = blockIdx.x * 32, k0 = blockIdx.y * 32;
    int tx = threadIdx.x, ty = threadIdx.y;  // 32 x 8
    #pragma unroll
    for (int i = 0; i < 4; i++)
        t[ty + i*8][tx] = in[(size_t)(k0 + ty + i*8) * N + n0 + tx];
    __syncthreads();
    #pragma unroll
    for (int i = 0; i < 4; i++)
        o[(size_t)(n0 + ty + i*8) * K + k0 + tx] = __float2half_rn(t[tx][ty + i*8]);
}

// ---------------- fp16 warp-mma GEMM, BK=32 ----------------------------------
#define HS_ROWB   80
#define HS_ARR    (128 * HS_ROWB)      // 10240
#define HS_STAGE  (2 * HS_ARR)         // 20480 (A, B)
#define HS_NSTAGE 4
#define HS_SMEM   (HS_NSTAGE * HS_STAGE)   // 81920

template <bool HALF_OUT>
__global__ void __launch_bounds__(256, 2) hf_gemm_kernel(
    const __half* __restrict__ A, const __half* __restrict__ B,
    const float* __restrict__ bias, void* __restrict__ Cv, int Ntot)
{
    extern __shared__ char sm[];
    const int tid = threadIdx.x, lane = tid & 31, wid = tid >> 5;
    const int wm = wid >> 2, wn = wid & 3;
    const int c0 = blockIdx.x * 128, r0 = blockIdx.y * 128;
    const int lr = lane >> 2, lc = lane & 3;
    uint32_t sbase = smem_u32(sm);

    auto issue = [&](int c, int st) {
        int k0 = c * 32;
        #pragma unroll
        for (int i = 0; i < 4; i++) {
            int q = tid + i * 256;           // 0..1023
            int arr = q >> 9, rem = q & 511;
            int row = rem >> 2, seg = rem & 3;
            const __half* s = (arr == 0)
                ? A + (size_t)(r0 + row) * 1024 + k0 + seg * 8
                : B + (size_t)(c0 + row) * 1024 + k0 + seg * 8;
            cp16(sbase + st * HS_STAGE + arr * HS_ARR + row * HS_ROWB + seg * 16, s);
        }
        asm volatile("cp.async.commit_group;" ::: "memory");
    };

    float acc[4][4][4];
    #pragma unroll
    for (int a = 0; a < 4; a++)
        #pragma unroll
        for (int b = 0; b < 4; b++)
            #pragma unroll
            for (int cc = 0; cc < 4; cc++) acc[a][b][cc] = 0.f;

    issue(0, 0);
    issue(1, 1);
    issue(2, 2);

    const int mat  = lane >> 3;
    const int roff = (mat & 1) * 8 + (lane & 7);
    const int cofs = (mat >> 1) * 16;

    const int NCHUNK = 1024 / 32;   // 32
    for (int c = 0; c < NCHUNK; c++) {
        asm volatile("cp.async.wait_group 2;" ::: "memory");
        __syncthreads();

        if (c + 3 < NCHUNK) issue(c + 3, (c + 3) & 3);
        else asm volatile("cp.async.commit_group;" ::: "memory");

        uint32_t base = sbase + (c & 3) * HS_STAGE;

        #pragma unroll
        for (int ks = 0; ks < 2; ks++) {
            uint32_t ah[4][4], bh[2][4];
            #pragma unroll
            for (int nt2 = 0; nt2 < 2; nt2++)
                ldm4(bh[nt2], base + HS_ARR + (wn*32 + nt2*16 + roff) * HS_ROWB
                               + ks*32 + cofs);
            #pragma unroll
            for (int mt = 0; mt < 4; mt++)
                ldm4(ah[mt], base + (wm*64 + mt*16 + roff) * HS_ROWB + ks*32 + cofs);

            #pragma unroll
            for (int mt = 0; mt < 4; mt++)
                #pragma unroll
                for (int nt = 0; nt < 4; nt++) {
                    int n2 = nt >> 1, hf = nt & 1;
                    mma_f16(acc[mt][nt], ah[mt], bh[n2][hf], bh[n2][2+hf]);
                }
        }
    }

    #pragma unroll
    for (int mt = 0; mt < 4; mt++) {
        int rbase = r0 + wm*64 + mt*16 + lr;
        #pragma unroll
        for (int nt = 0; nt < 4; nt++) {
            int col = c0 + wn*32 + nt*8 + 2*lc;
            if (HALF_OUT) {
                __half* C = (__half*)Cv;
                float sc = (col < 1024) ? 0.125f : 1.0f;   // Q prescale
                *reinterpret_cast<uint32_t*>(C + (size_t)rbase * Ntot + col) =
                    h2u(acc[mt][nt][0] * sc, acc[mt][nt][1] * sc);
                *reinterpret_cast<uint32_t*>(C + (size_t)(rbase + 8) * Ntot + col) =
                    h2u(acc[mt][nt][2] * sc, acc[mt][nt][3] * sc);
            } else {
                float* C = (float*)Cv;
                float b0v = bias ? bias[col] : 0.f;
                float b1v = bias ? bias[col + 1] : 0.f;
                float2 v0 = {acc[mt][nt][0] + b0v, acc[mt][nt][1] + b1v};
                float2 v1 = {acc[mt][nt][2] + b0v, acc[mt][nt][3] + b1v};
                *reinterpret_cast<float2*>(C + (size_t)rbase * Ntot + col) = v0;
                *reinterpret_cast<float2*>(C + (size_t)(rbase + 8) * Ntot + col) = v1;
            }
        }
    }
}

// ---------------- flash attention: fp16 QK (ldmatrix K) + f16x2 softmax ------
// CTA: 128 q rows (8 warps x m16), kv-tile 64, double-buffered K/V prefetch.
// K rows 144B stride (16B/row phase walk -> conflict-free ldmatrix).
#define FA_QS    18432                    // Q: 128 * 144
#define FA_KB    9216                     // K stage: 64 * 144
#define FA_VB    8192                     // V stage: 64 * 128
#define FA_STAGE (FA_KB + FA_VB)          // 17408
#define FAH_SMEM (FA_QS + 2 * FA_STAGE)   // 53248

__global__ void __launch_bounds__(256, 2) fa_kernel(
    const __half* __restrict__ qkv, __half* __restrict__ outh)
{
    extern __shared__ char sm[];
    const int tid = threadIdx.x, lane = tid & 31, wid = tid >> 5;
    const int qt = blockIdx.x, hd = blockIdx.y, b = blockIdx.z;
    const int n0 = qt * 128;
    const int lr = lane >> 2, lc = lane & 3;
    uint32_t sbase = smem_u32(sm);

    const __half* qb = qkv + (size_t)b * SEQ * QKV3 + hd * DHEAD;
    const __half* kb = qb + 1024;
    const __half* vb = qb + 2048;

    // stage Q via cp.async
    #pragma unroll
    for (int i = 0; i < 4; i++) {
        int q = tid + i * 256;
        int row = q >> 3, ch = q & 7;
        cp16(sbase + row * 144 + ch * 16,
             qb + (size_t)(n0 + row) * QKV3 + ch * 8);
    }
    asm volatile("cp.async.commit_group;" ::: "memory");

    auto issueKV = [&](int kt, int st) {
        int s0 = kt * 64;
        uint32_t kbase = sbase + FA_QS + st * FA_STAGE;
        uint32_t vbase = kbase + FA_KB;
        #pragma unroll
        for (int i = 0; i < 4; i++) {
            int q = tid + i * 256;
            int arr = q >> 9, rem = q & 511;
            int row = rem >> 3, ch = rem & 7;
            if (arr == 0) {
                cp16(kbase + row * 144 + ch * 16,
                     kb + (size_t)(s0 + row) * QKV3 + ch * 8);
            } else {
                uint32_t off = (uint32_t)(row * 128 + ch * 16);
                off ^= ((off >> 7) & 7) << 4;
                cp16(vbase + off, vb + (size_t)(s0 + row) * QKV3 + ch * 8);
            }
        }
        asm volatile("cp.async.commit_group;" ::: "memory");
    };

    issueKV(0, 0);
    asm volatile("cp.async.wait_group 0;" ::: "memory");
    __syncthreads();

    // Q fragments from smem (u32 view, stride 36 u32 = 144B)
    const uint32_t* Qs = reinterpret_cast<const uint32_t*>(sm);
    uint32_t qa[4][4];
    {
        int m0 = wid * 16;
        #pragma unroll
        for (int u = 0; u < 4; u++) {
            qa[u][0] = Qs[(m0 + lr)     * 36 + u*8 + lc];
            qa[u][1] = Qs[(m0 + 8 + lr) * 36 + u*8 + lc];
            qa[u][2] = Qs[(m0 + lr)     * 36 + u*8 + lc + 4];
            qa[u][3] = Qs[(m0 + 8 + lr) * 36 + u*8 + lc + 4];
        }
    }

    const int mat  = lane >> 3;
    const int roff = (mat & 1) * 8 + (lane & 7);
    const int cofs = (mat >> 1) * 16;
    const float LOG2E = 1.44269504f;

    float m_i[2] = {-1e30f, -1e30f}, l_i[2] = {0.f, 0.f};
    float o[8][4];
    #pragma unroll
    for (int v = 0; v < 8; v++)
        #pragma unroll
        for (int j = 0; j < 4; j++) o[v][j] = 0.f;

    const int NT = SEQ / 64;   // 32
    for (int kt = 0; kt < NT; kt++) {
        if (kt > 0) {
            asm volatile("cp.async.wait_group 0;" ::: "memory");
            __syncthreads();
        }
        if (kt + 1 < NT) issueKV(kt + 1, (kt + 1) & 1);

        int st = kt & 1;
        uint32_t kbase = sbase + FA_QS + st * FA_STAGE;
        const uint32_t vsb = kbase + FA_KB;

        // S = Q K^T  (fp16, fp32 accum): 16 ldm4 + 32 MMAs
        float s[8][4];
        #pragma unroll
        for (int v = 0; v < 8; v++)
            #pragma unroll
            for (int j = 0; j < 4; j++) s[v][j] = 0.f;
        #pragma unroll
        for (int u = 0; u < 4; u++) {
            uint32_t bh[4][4];
            #pragma unroll
            for (int g = 0; g < 4; g++)
                ldm4(bh[g], kbase + (g*16 + roff) * 144 + u*32 + cofs);
            #pragma unroll
            for (int v = 0; v < 8; v++) {
                int g = v >> 1, hf = v & 1;
                mma_f16(s[v], qa[u], bh[g][hf], bh[g][2+hf]);
            }
        }

        // online softmax: f16x2 ex2, rows lr (h=0) and lr+8 (h=1)
        uint32_t ph[8][2];
        #pragma unroll
        for (int h = 0; h < 2; h++) {
            float mx = -1e30f;
            #pragma unroll
            for (int v = 0; v < 8; v++)
                mx = fmaxf(mx, fmaxf(s[v][2*h], s[v][2*h+1]));
            mx = fmaxf(mx, __shfl_xor_sync(0xffffffffu, mx, 1));
            mx = fmaxf(mx, __shfl_xor_sync(0xffffffffu, mx, 2));
            float mnew = fmaxf(m_i[h], mx);
            float alpha = __expf(m_i[h] - mnew);
            m_i[h] = mnew;
            float cbias = mnew * LOG2E;
            float rs = 0.f;
            #pragma unroll
            for (int v = 0; v < 8; v++) {
                uint32_t arg = h2u(fmaf(s[v][2*h],   LOG2E, -cbias),
                                   fmaf(s[v][2*h+1], LOG2E, -cbias));
                uint32_t pe = ex2_h2(arg);
                ph[v][h] = pe;
                float2 pf = __half22float2(*reinterpret_cast<__half2*>(&pe));
                rs += pf.x + pf.y;
            }
            rs += __shfl_xor_sync(0xffffffffu, rs, 1);
            rs += __shfl_xor_sync(0xffffffffu, rs, 2);
            l_i[h] = l_i[h] * alpha + rs;
            #pragma unroll
            for (int v = 0; v < 8; v++) {
                o[v][2*h]   *= alpha;
                o[v][2*h+1] *= alpha;
            }
        }

        // O += P V  (fp16 MMA, fp32 accum); pa fragments come straight from ph
        #pragma unroll
        for (int u = 0; u < 4; u++) {
            uint32_t pa[4] = {ph[2*u][0], ph[2*u][1], ph[2*u+1][0], ph[2*u+1][1]};
            #pragma unroll
            for (int w2 = 0; w2 < 4; w2++) {
                int row = u*16 + (mat & 1) * 8 + (lane & 7);
                int colb = w2*32 + (mat >> 1) * 16;
                uint32_t off = (uint32_t)(row * 128 + colb);
                off ^= ((off >> 7) & 7) << 4;
                uint32_t r[4];
                ldm4t(r, vsb + off);
                mma_f16(o[2*w2],     pa, r[0], r[1]);
                mma_f16(o[2*w2 + 1], pa, r[2], r[3]);
            }
        }
    }

    // epilogue: normalize + fp16 store
    #pragma unroll
    for (int h = 0; h < 2; h++) {
        float inv = 1.f / l_i[h];
        int rowg = b * SEQ + n0 + wid*16 + h*8 + lr;
        #pragma unroll
        for (int v = 0; v < 8; v++) {
            int col = hd * 64 + v*8 + 2*lc;
            uint32_t pk = h2u(o[v][2*h] * inv, o[v][2*h+1] * inv);
            *reinterpret_cast<uint32_t*>(outh + (size_t)rowg * INNER + col) = pk;
        }
    }
}

// ---------------- launcher ---------------------------------------------------
extern "C" void kernel_launch(void* const* d_in, const int* in_sizes, int n_in,
                              void* d_out, int out_size)
{
    const float* x     = (const float*)d_in[0];
    const float* gamma = (const float*)d_in[1];
    const float* beta  = (const float*)d_in[2];
    const float* Wqkv  = (const float*)d_in[3];
    const float* Wout  = (const float*)d_in[4];
    const float* bout  = (const float*)d_in[5];
    float* out = (float*)d_out;

    __half *qkvh, *xnh, *wqt, *wot, *aoh;
    cudaGetSymbolAddress((void**)&qkvh, g_qkvh);
    cudaGetSymbolAddress((void**)&xnh, g_xnh);
    cudaGetSymbolAddress((void**)&wqt, g_wqt);
    cudaGetSymbolAddress((void**)&wot, g_wot);
    cudaGetSymbolAddress((void**)&aoh, g_aoh);

    cudaFuncSetAttribute(hf_gemm_kernel<true>,
                         cudaFuncAttributeMaxDynamicSharedMemorySize, HS_SMEM);
    cudaFuncSetAttribute(hf_gemm_kernel<false>,
                         cudaFuncAttributeMaxDynamicSharedMemorySize, HS_SMEM);
    cudaFuncSetAttribute(fa_kernel,
                         cudaFuncAttributeMaxDynamicSharedMemorySize, FAH_SMEM);

    ln_kernel<<<ROWS, 256>>>(x, gamma, beta, xnh);

    transpose_kernel<<<dim3(QKV3 / 32, DIMSZ / 32), dim3(32, 8)>>>(
        Wqkv, wqt, DIMSZ, QKV3);
    transpose_kernel<<<dim3(DIMSZ / 32, DIMSZ / 32), dim3(32, 8)>>>(
        Wout, wot, INNER, DIMSZ);

    hf_gemm_kernel<true><<<dim3(QKV3 / 128, ROWS / 128), 256, HS_SMEM>>>(
        xnh, wqt, nullptr, qkvh, QKV3);

    fa_kernel<<<dim3(SEQ / 128, HEADS, BATCH), 256, FAH_SMEM>>>(qkvh, aoh);

    hf_gemm_kernel<false><<<dim3(DIMSZ / 128, ROWS / 128), 256, HS_SMEM>>>(
        aoh, wot, bout, out, DIMSZ);
}

// round 13
// speedup vs baseline: 2.5942x; 1.0494x over previous
#include <cuda_runtime.h>
#include <cuda_bf16.h>
#include <cuda_fp16.h>
#include <cstdint>

#define BATCH 2
#define SEQ   2048
#define DIMSZ 1024
#define HEADS 16
#define DHEAD 64
#define INNER 1024
#define QKV3  3072
#define ROWS  (BATCH * SEQ)   // 4096

// ---------------- scratch (static device globals; no allocation) -------------
__device__ __half g_qkvh[ROWS * QKV3];    // 25 MB fp16 (Q prescaled by 0.125)
__device__ __half g_xnh[ROWS * DIMSZ];    // LN out fp16
__device__ __half g_wqt[QKV3 * DIMSZ];    // Wqkv^T [3072][1024] fp16
__device__ __half g_wot[DIMSZ * INNER];   // Wout^T [1024][1024] fp16
__device__ __half g_aoh[ROWS * INNER];    // attention out fp16

// ---------------- helpers ----------------------------------------------------
__device__ __forceinline__ uint32_t smem_u32(const void* p) {
    uint32_t a;
    asm("{ .reg .u64 t; cvta.to.shared.u64 t, %1; cvt.u32.u64 %0, t; }"
        : "=r"(a) : "l"(p));
    return a;
}
__device__ __forceinline__ void cp16(uint32_t dst, const void* src) {
    asm volatile("cp.async.cg.shared.global [%0], [%1], 16;"
                 :: "r"(dst), "l"(src) : "memory");
}
__device__ __forceinline__ void ldm4(uint32_t* r, uint32_t addr) {
    asm volatile("ldmatrix.sync.aligned.m8n8.x4.shared.b16 {%0,%1,%2,%3}, [%4];"
        : "=r"(r[0]), "=r"(r[1]), "=r"(r[2]), "=r"(r[3]) : "r"(addr));
}
__device__ __forceinline__ void ldm4t(uint32_t* r, uint32_t addr) {
    asm volatile("ldmatrix.sync.aligned.m8n8.x4.trans.shared.b16 {%0,%1,%2,%3}, [%4];"
        : "=r"(r[0]), "=r"(r[1]), "=r"(r[2]), "=r"(r[3]) : "r"(addr));
}
__device__ __forceinline__ void mma_f16(float* d, const uint32_t* a,
                                        uint32_t b0, uint32_t b1) {
    asm volatile("mma.sync.aligned.m16n8k16.row.col.f32.f16.f16.f32 "
        "{%0,%1,%2,%3}, {%4,%5,%6,%7}, {%8,%9}, {%0,%1,%2,%3};"
        : "+f"(d[0]), "+f"(d[1]), "+f"(d[2]), "+f"(d[3])
        : "r"(a[0]), "r"(a[1]), "r"(a[2]), "r"(a[3]), "r"(b0), "r"(b1));
}
__device__ __forceinline__ uint32_t h2u(float a, float b) {
    __half2 h = __floats2half2_rn(a, b);
    return *reinterpret_cast<uint32_t*>(&h);
}
__device__ __forceinline__ uint32_t ex2_h2(uint32_t packed) {
    uint32_t r;
    asm("ex2.approx.f16x2 %0, %1;" : "=r"(r) : "r"(packed));
    return r;
}

// ---------------- LayerNorm -> fp16 -------------------------------------------
__global__ void __launch_bounds__(256) ln_kernel(
    const float* __restrict__ x, const float* __restrict__ gamma,
    const float* __restrict__ beta, __half* __restrict__ o)
{
    int row = blockIdx.x;
    int t = threadIdx.x;
    const float4* xr = reinterpret_cast<const float4*>(x + (size_t)row * DIMSZ);
    float4 v = xr[t];
    float s  = v.x + v.y + v.z + v.w;
    float ss = v.x*v.x + v.y*v.y + v.z*v.z + v.w*v.w;
    #pragma unroll
    for (int off = 16; off; off >>= 1) {
        s  += __shfl_xor_sync(0xffffffffu, s,  off);
        ss += __shfl_xor_sync(0xffffffffu, ss, off);
    }
    __shared__ float sbuf[8], ssbuf[8];
    __shared__ float s_mu, s_rstd;
    int w = t >> 5, lane = t & 31;
    if (lane == 0) { sbuf[w] = s; ssbuf[w] = ss; }
    __syncthreads();
    if (t == 0) {
        float S = 0.f, SS = 0.f;
        #pragma unroll
        for (int i = 0; i < 8; i++) { S += sbuf[i]; SS += ssbuf[i]; }
        float mu = S * (1.0f / DIMSZ);
        float var = SS * (1.0f / DIMSZ) - mu * mu;
        s_mu = mu; s_rstd = rsqrtf(var + 1e-5f);
    }
    __syncthreads();
    float mu = s_mu, rstd = s_rstd;
    float4 g  = reinterpret_cast<const float4*>(gamma)[t];
    float4 bt = reinterpret_cast<const float4*>(beta)[t];
    float o0 = (v.x - mu) * rstd * g.x + bt.x;
    float o1 = (v.y - mu) * rstd * g.y + bt.y;
    float o2 = (v.z - mu) * rstd * g.z + bt.z;
    float o3 = (v.w - mu) * rstd * g.w + bt.w;
    uint2 pk = {h2u(o0, o1), h2u(o2, o3)};
    *reinterpret_cast<uint2*>(o + (size_t)row * DIMSZ + t * 4) = pk;
}

// ------------- weight transpose: in [K][N] fp32 -> out [N][K] fp16 -----------
__global__ void __launch_bounds__(256) transpose_kernel(
    const float* __restrict__ in, __half* __restrict__ o, int K, int N)
{
    __shared__ float t[32][33];
    int n0 = blockIdx.x * 32, k0 = blockIdx.y * 32;
    int tx = threadIdx.x, ty = threadIdx.y;  // 32 x 8
    #pragma unroll
    for (int i = 0; i < 4; i++)
        t[ty + i*8][tx] = in[(size_t)(k0 + ty + i*8) * N + n0 + tx];
    __syncthreads();
    #pragma unroll
    for (int i = 0; i < 4; i++)
        o[(size_t)(n0 + ty + i*8) * K + k0 + tx] = __float2half_rn(t[tx][ty + i*8]);
}

// ---------------- fp16 warp-mma GEMM, BK=64 ----------------------------------
// C[M,Ntot] = A[M,1024] @ B[Ntot,1024]^T, fp16 in, fp32 accum.
// CTA 128x128, BK=64, 8 warps (2m x 4n), warp tile 64x32.
// 144B-stride rows (phase step 16 mod 128 -> conflict-free ldmatrix).
// 3-stage cp.async ring, wait_group 1, one sync/iter, 2 CTAs/SM.
// Per chunk: 24 LDSM + 64 HMMA.
#define HS_ROWB   144
#define HS_ARR    (128 * HS_ROWB)      // 18432
#define HS_STAGE  (2 * HS_ARR)         // 36864 (A, B)
#define HS_NSTAGE 3
#define HS_SMEM   (HS_NSTAGE * HS_STAGE)   // 110592

template <bool HALF_OUT>
__global__ void __launch_bounds__(256, 2) hf_gemm_kernel(
    const __half* __restrict__ A, const __half* __restrict__ B,
    const float* __restrict__ bias, void* __restrict__ Cv, int Ntot)
{
    extern __shared__ char sm[];
    const int tid = threadIdx.x, lane = tid & 31, wid = tid >> 5;
    const int wm = wid >> 2, wn = wid & 3;
    const int c0 = blockIdx.x * 128, r0 = blockIdx.y * 128;
    const int lr = lane >> 2, lc = lane & 3;
    uint32_t sbase = smem_u32(sm);

    // per stage: 2 arrays * 128 rows * 128B -> 2048 cp16, 8/thread
    auto issue = [&](int c, int st) {
        int k0 = c * 64;
        #pragma unroll
        for (int i = 0; i < 8; i++) {
            int q = tid + i * 256;            // 0..2047
            int arr = q >> 10, rem = q & 1023;
            int row = rem >> 3, seg = rem & 7;
            const __half* s = (arr == 0)
                ? A + (size_t)(r0 + row) * 1024 + k0 + seg * 8
                : B + (size_t)(c0 + row) * 1024 + k0 + seg * 8;
            cp16(sbase + st * HS_STAGE + arr * HS_ARR + row * HS_ROWB + seg * 16, s);
        }
        asm volatile("cp.async.commit_group;" ::: "memory");
    };

    float acc[4][4][4];
    #pragma unroll
    for (int a = 0; a < 4; a++)
        #pragma unroll
        for (int b = 0; b < 4; b++)
            #pragma unroll
            for (int cc = 0; cc < 4; cc++) acc[a][b][cc] = 0.f;

    issue(0, 0);
    issue(1, 1);

    const int mat  = lane >> 3;
    const int roff = (mat & 1) * 8 + (lane & 7);
    const int cofs = (mat >> 1) * 16;

    const int NCHUNK = 1024 / 64;   // 16
    int st = 0;
    for (int c = 0; c < NCHUNK; c++) {
        asm volatile("cp.async.wait_group 1;" ::: "memory");
        __syncthreads();

        int st2 = st + 2; if (st2 >= 3) st2 -= 3;
        if (c + 2 < NCHUNK) issue(c + 2, st2);
        else asm volatile("cp.async.commit_group;" ::: "memory");

        uint32_t base = sbase + st * HS_STAGE;

        #pragma unroll
        for (int ks = 0; ks < 4; ks++) {
            uint32_t ah[4][4], bh[2][4];
            #pragma unroll
            for (int nt2 = 0; nt2 < 2; nt2++)
                ldm4(bh[nt2], base + HS_ARR + (wn*32 + nt2*16 + roff) * HS_ROWB
                               + ks*32 + cofs);
            #pragma unroll
            for (int mt = 0; mt < 4; mt++)
                ldm4(ah[mt], base + (wm*64 + mt*16 + roff) * HS_ROWB + ks*32 + cofs);

            #pragma unroll
            for (int mt = 0; mt < 4; mt++)
                #pragma unroll
                for (int nt = 0; nt < 4; nt++) {
                    int n2 = nt >> 1, hf = nt & 1;
                    mma_f16(acc[mt][nt], ah[mt], bh[n2][hf], bh[n2][2+hf]);
                }
        }
        if (++st >= 3) st = 0;
    }

    #pragma unroll
    for (int mt = 0; mt < 4; mt++) {
        int rbase = r0 + wm*64 + mt*16 + lr;
        #pragma unroll
        for (int nt = 0; nt < 4; nt++) {
            int col = c0 + wn*32 + nt*8 + 2*lc;
            if (HALF_OUT) {
                __half* C = (__half*)Cv;
                float sc = (col < 1024) ? 0.125f : 1.0f;   // Q prescale
                *reinterpret_cast<uint32_t*>(C + (size_t)rbase * Ntot + col) =
                    h2u(acc[mt][nt][0] * sc, acc[mt][nt][1] * sc);
                *reinterpret_cast<uint32_t*>(C + (size_t)(rbase + 8) * Ntot + col) =
                    h2u(acc[mt][nt][2] * sc, acc[mt][nt][3] * sc);
            } else {
                float* C = (float*)Cv;
                float b0v = bias ? bias[col] : 0.f;
                float b1v = bias ? bias[col + 1] : 0.f;
                float2 v0 = {acc[mt][nt][0] + b0v, acc[mt][nt][1] + b1v};
                float2 v1 = {acc[mt][nt][2] + b0v, acc[mt][nt][3] + b1v};
                *reinterpret_cast<float2*>(C + (size_t)rbase * Ntot + col) = v0;
                *reinterpret_cast<float2*>(C + (size_t)(rbase + 8) * Ntot + col) = v1;
            }
        }
    }
}

// ---------------- flash attention: fp16 QK (ldmatrix K) + f16x2 softmax ------
#define FA_QS    18432                    // Q: 128 * 144
#define FA_KB    9216                     // K stage: 64 * 144
#define FA_VB    8192                     // V stage: 64 * 128
#define FA_STAGE (FA_KB + FA_VB)          // 17408
#define FAH_SMEM (FA_QS + 2 * FA_STAGE)   // 53248

__global__ void __launch_bounds__(256, 2) fa_kernel(
    const __half* __restrict__ qkv, __half* __restrict__ outh)
{
    extern __shared__ char sm[];
    const int tid = threadIdx.x, lane = tid & 31, wid = tid >> 5;
    const int qt = blockIdx.x, hd = blockIdx.y, b = blockIdx.z;
    const int n0 = qt * 128;
    const int lr = lane >> 2, lc = lane & 3;
    uint32_t sbase = smem_u32(sm);

    const __half* qb = qkv + (size_t)b * SEQ * QKV3 + hd * DHEAD;
    const __half* kb = qb + 1024;
    const __half* vb = qb + 2048;

    #pragma unroll
    for (int i = 0; i < 4; i++) {
        int q = tid + i * 256;
        int row = q >> 3, ch = q & 7;
        cp16(sbase + row * 144 + ch * 16,
             qb + (size_t)(n0 + row) * QKV3 + ch * 8);
    }
    asm volatile("cp.async.commit_group;" ::: "memory");

    auto issueKV = [&](int kt, int st) {
        int s0 = kt * 64;
        uint32_t kbase = sbase + FA_QS + st * FA_STAGE;
        uint32_t vbase = kbase + FA_KB;
        #pragma unroll
        for (int i = 0; i < 4; i++) {
            int q = tid + i * 256;
            int arr = q >> 9, rem = q & 511;
            int row = rem >> 3, ch = rem & 7;
            if (arr == 0) {
                cp16(kbase + row * 144 + ch * 16,
                     kb + (size_t)(s0 + row) * QKV3 + ch * 8);
            } else {
                uint32_t off = (uint32_t)(row * 128 + ch * 16);
                off ^= ((off >> 7) & 7) << 4;
                cp16(vbase + off, vb + (size_t)(s0 + row) * QKV3 + ch * 8);
            }
        }
        asm volatile("cp.async.commit_group;" ::: "memory");
    };

    issueKV(0, 0);
    asm volatile("cp.async.wait_group 0;" ::: "memory");
    __syncthreads();

    const uint32_t* Qs = reinterpret_cast<const uint32_t*>(sm);
    uint32_t qa[4][4];
    {
        int m0 = wid * 16;
        #pragma unroll
        for (int u = 0; u < 4; u++) {
            qa[u][0] = Qs[(m0 + lr)     * 36 + u*8 + lc];
            qa[u][1] = Qs[(m0 + 8 + lr) * 36 + u*8 + lc];
            qa[u][2] = Qs[(m0 + lr)     * 36 + u*8 + lc + 4];
            qa[u][3] = Qs[(m0 + 8 + lr) * 36 + u*8 + lc + 4];
        }
    }

    const int mat  = lane >> 3;
    const int roff = (mat & 1) * 8 + (lane & 7);
    const int cofs = (mat >> 1) * 16;
    const float LOG2E = 1.44269504f;

    float m_i[2] = {-1e30f, -1e30f}, l_i[2] = {0.f, 0.f};
    float o[8][4];
    #pragma unroll
    for (int v = 0; v < 8; v++)
        #pragma unroll
        for (int j = 0; j < 4; j++) o[v][j] = 0.f;

    const int NT = SEQ / 64;   // 32
    for (int kt = 0; kt < NT; kt++) {
        if (kt > 0) {
            asm volatile("cp.async.wait_group 0;" ::: "memory");
            __syncthreads();
        }
        if (kt + 1 < NT) issueKV(kt + 1, (kt + 1) & 1);

        int st = kt & 1;
        uint32_t kbase = sbase + FA_QS + st * FA_STAGE;
        const uint32_t vsb = kbase + FA_KB;

        float s[8][4];
        #pragma unroll
        for (int v = 0; v < 8; v++)
            #pragma unroll
            for (int j = 0; j < 4; j++) s[v][j] = 0.f;
        #pragma unroll
        for (int u = 0; u < 4; u++) {
            uint32_t bh[4][4];
            #pragma unroll
            for (int g = 0; g < 4; g++)
                ldm4(bh[g], kbase + (g*16 + roff) * 144 + u*32 + cofs);
            #pragma unroll
            for (int v = 0; v < 8; v++) {
                int g = v >> 1, hf = v & 1;
                mma_f16(s[v], qa[u], bh[g][hf], bh[g][2+hf]);
            }
        }

        uint32_t ph[8][2];
        #pragma unroll
        for (int h = 0; h < 2; h++) {
            float mx = -1e30f;
            #pragma unroll
            for (int v = 0; v < 8; v++)
                mx = fmaxf(mx, fmaxf(s[v][2*h], s[v][2*h+1]));
            mx = fmaxf(mx, __shfl_xor_sync(0xffffffffu, mx, 1));
            mx = fmaxf(mx, __shfl_xor_sync(0xffffffffu, mx, 2));
            float mnew = fmaxf(m_i[h], mx);
            float alpha = __expf(m_i[h] - mnew);
            m_i[h] = mnew;
            float cbias = mnew * LOG2E;
            float rs = 0.f;
            #pragma unroll
            for (int v = 0; v < 8; v++) {
                uint32_t arg = h2u(fmaf(s[v][2*h],   LOG2E, -cbias),
                                   fmaf(s[v][2*h+1], LOG2E, -cbias));
                uint32_t pe = ex2_h2(arg);
                ph[v][h] = pe;
                float2 pf = __half22float2(*reinterpret_cast<__half2*>(&pe));
                rs += pf.x + pf.y;
            }
            rs += __shfl_xor_sync(0xffffffffu, rs, 1);
            rs += __shfl_xor_sync(0xffffffffu, rs, 2);
            l_i[h] = l_i[h] * alpha + rs;
            #pragma unroll
            for (int v = 0; v < 8; v++) {
                o[v][2*h]   *= alpha;
                o[v][2*h+1] *= alpha;
            }
        }

        #pragma unroll
        for (int u = 0; u < 4; u++) {
            uint32_t pa[4] = {ph[2*u][0], ph[2*u][1], ph[2*u+1][0], ph[2*u+1][1]};
            #pragma unroll
            for (int w2 = 0; w2 < 4; w2++) {
                int row = u*16 + (mat & 1) * 8 + (lane & 7);
                int colb = w2*32 + (mat >> 1) * 16;
                uint32_t off = (uint32_t)(row * 128 + colb);
                off ^= ((off >> 7) & 7) << 4;
                uint32_t r[4];
                ldm4t(r, vsb + off);
                mma_f16(o[2*w2],     pa, r[0], r[1]);
                mma_f16(o[2*w2 + 1], pa, r[2], r[3]);
            }
        }
    }

    #pragma unroll
    for (int h = 0; h < 2; h++) {
        float inv = 1.f / l_i[h];
        int rowg = b * SEQ + n0 + wid*16 + h*8 + lr;
        #pragma unroll
        for (int v = 0; v < 8; v++) {
            int col = hd * 64 + v*8 + 2*lc;
            uint32_t pk = h2u(o[v][2*h] * inv, o[v][2*h+1] * inv);
            *reinterpret_cast<uint32_t*>(outh + (size_t)rowg * INNER + col) = pk;
        }
    }
}

// ---------------- launcher ---------------------------------------------------
extern "C" void kernel_launch(void* const* d_in, const int* in_sizes, int n_in,
                              void* d_out, int out_size)
{
    const float* x     = (const float*)d_in[0];
    const float* gamma = (const float*)d_in[1];
    const float* beta  = (const float*)d_in[2];
    const float* Wqkv  = (const float*)d_in[3];
    const float* Wout  = (const float*)d_in[4];
    const float* bout  = (const float*)d_in[5];
    float* out = (float*)d_out;

    __half *qkvh, *xnh, *wqt, *wot, *aoh;
    cudaGetSymbolAddress((void**)&qkvh, g_qkvh);
    cudaGetSymbolAddress((void**)&xnh, g_xnh);
    cudaGetSymbolAddress((void**)&wqt, g_wqt);
    cudaGetSymbolAddress((void**)&wot, g_wot);
    cudaGetSymbolAddress((void**)&aoh, g_aoh);

    cudaFuncSetAttribute(hf_gemm_kernel<true>,
                         cudaFuncAttributeMaxDynamicSharedMemorySize, HS_SMEM);
    cudaFuncSetAttribute(hf_gemm_kernel<false>,
                         cudaFuncAttributeMaxDynamicSharedMemorySize, HS_SMEM);
    cudaFuncSetAttribute(fa_kernel,
                         cudaFuncAttributeMaxDynamicSharedMemorySize, FAH_SMEM);

    ln_kernel<<<ROWS, 256>>>(x, gamma, beta, xnh);

    transpose_kernel<<<dim3(QKV3 / 32, DIMSZ / 32), dim3(32, 8)>>>(
        Wqkv, wqt, DIMSZ, QKV3);
    transpose_kernel<<<dim3(DIMSZ / 32, DIMSZ / 32), dim3(32, 8)>>>(
        Wout, wot, INNER, DIMSZ);

    hf_gemm_kernel<true><<<dim3(QKV3 / 128, ROWS / 128), 256, HS_SMEM>>>(
        xnh, wqt, nullptr, qkvh, QKV3);

    fa_kernel<<<dim3(SEQ / 128, HEADS, BATCH), 256, FAH_SMEM>>>(qkvh, aoh);

    hf_gemm_kernel<false><<<dim3(DIMSZ / 128, ROWS / 128), 256, HS_SMEM>>>(
        aoh, wot, bout, out, DIMSZ);
}

// round 14
// speedup vs baseline: 2.8494x; 1.0984x over previous
#include <cuda_runtime.h>
#include <cuda_bf16.h>
#include <cuda_fp16.h>
#include <cstdint>

#define BATCH 2
#define SEQ   2048
#define DIMSZ 1024
#define HEADS 16
#define DHEAD 64
#define INNER 1024
#define QKV3  3072
#define ROWS  (BATCH * SEQ)   // 4096

// ---------------- scratch (static device globals; no allocation) -------------
__device__ __half g_qkvh[ROWS * QKV3];    // 25 MB fp16 (Q prescaled by 0.125)
__device__ __half g_xnh[ROWS * DIMSZ];    // LN out fp16
__device__ __half g_wqh[DIMSZ * QKV3];    // Wqkv fp16, natural [K][N]
__device__ __half g_woh[INNER * DIMSZ];   // Wout fp16, natural [K][N]
__device__ __half g_aoh[ROWS * INNER];    // attention out fp16

// ---------------- helpers ----------------------------------------------------
__device__ __forceinline__ uint32_t smem_u32(const void* p) {
    uint32_t a;
    asm("{ .reg .u64 t; cvta.to.shared.u64 t, %1; cvt.u32.u64 %0, t; }"
        : "=r"(a) : "l"(p));
    return a;
}
__device__ __forceinline__ void cp16(uint32_t dst, const void* src) {
    asm volatile("cp.async.cg.shared.global [%0], [%1], 16;"
                 :: "r"(dst), "l"(src) : "memory");
}
__device__ __forceinline__ void ldm4(uint32_t* r, uint32_t addr) {
    asm volatile("ldmatrix.sync.aligned.m8n8.x4.shared.b16 {%0,%1,%2,%3}, [%4];"
        : "=r"(r[0]), "=r"(r[1]), "=r"(r[2]), "=r"(r[3]) : "r"(addr));
}
__device__ __forceinline__ void ldm4t(uint32_t* r, uint32_t addr) {
    asm volatile("ldmatrix.sync.aligned.m8n8.x4.trans.shared.b16 {%0,%1,%2,%3}, [%4];"
        : "=r"(r[0]), "=r"(r[1]), "=r"(r[2]), "=r"(r[3]) : "r"(addr));
}
__device__ __forceinline__ void mma_f16(float* d, const uint32_t* a,
                                        uint32_t b0, uint32_t b1) {
    asm volatile("mma.sync.aligned.m16n8k16.row.col.f32.f16.f16.f32 "
        "{%0,%1,%2,%3}, {%4,%5,%6,%7}, {%8,%9}, {%0,%1,%2,%3};"
        : "+f"(d[0]), "+f"(d[1]), "+f"(d[2]), "+f"(d[3])
        : "r"(a[0]), "r"(a[1]), "r"(a[2]), "r"(a[3]), "r"(b0), "r"(b1));
}
__device__ __forceinline__ uint32_t h2u(float a, float b) {
    __half2 h = __floats2half2_rn(a, b);
    return *reinterpret_cast<uint32_t*>(&h);
}
__device__ __forceinline__ uint32_t ex2_h2(uint32_t packed) {
    uint32_t r;
    asm("ex2.approx.f16x2 %0, %1;" : "=r"(r) : "r"(packed));
    return r;
}

// ---------------- LayerNorm -> fp16 -------------------------------------------
__global__ void __launch_bounds__(256) ln_kernel(
    const float* __restrict__ x, const float* __restrict__ gamma,
    const float* __restrict__ beta, __half* __restrict__ o)
{
    int row = blockIdx.x;
    int t = threadIdx.x;
    const float4* xr = reinterpret_cast<const float4*>(x + (size_t)row * DIMSZ);
    float4 v = xr[t];
    float s  = v.x + v.y + v.z + v.w;
    float ss = v.x*v.x + v.y*v.y + v.z*v.z + v.w*v.w;
    #pragma unroll
    for (int off = 16; off; off >>= 1) {
        s  += __shfl_xor_sync(0xffffffffu, s,  off);
        ss += __shfl_xor_sync(0xffffffffu, ss, off);
    }
    __shared__ float sbuf[8], ssbuf[8];
    __shared__ float s_mu, s_rstd;
    int w = t >> 5, lane = t & 31;
    if (lane == 0) { sbuf[w] = s; ssbuf[w] = ss; }
    __syncthreads();
    if (t == 0) {
        float S = 0.f, SS = 0.f;
        #pragma unroll
        for (int i = 0; i < 8; i++) { S += sbuf[i]; SS += ssbuf[i]; }
        float mu = S * (1.0f / DIMSZ);
        float var = SS * (1.0f / DIMSZ) - mu * mu;
        s_mu = mu; s_rstd = rsqrtf(var + 1e-5f);
    }
    __syncthreads();
    float mu = s_mu, rstd = s_rstd;
    float4 g  = reinterpret_cast<const float4*>(gamma)[t];
    float4 bt = reinterpret_cast<const float4*>(beta)[t];
    float o0 = (v.x - mu) * rstd * g.x + bt.x;
    float o1 = (v.y - mu) * rstd * g.y + bt.y;
    float o2 = (v.z - mu) * rstd * g.z + bt.z;
    float o3 = (v.w - mu) * rstd * g.w + bt.w;
    uint2 pk = {h2u(o0, o1), h2u(o2, o3)};
    *reinterpret_cast<uint2*>(o + (size_t)row * DIMSZ + t * 4) = pk;
}

// ------------- weight convert: fp32 -> fp16, natural layout (both weights) ---
__global__ void __launch_bounds__(256) convert_kernel(
    const float* __restrict__ w1, const float* __restrict__ w2,
    __half* __restrict__ o1, __half* __restrict__ o2)
{
    int idx = blockIdx.x * 256 + threadIdx.x;   // float4 index
    const int n1 = (QKV3 * DIMSZ) / 4;          // 786432
    const int n2 = (DIMSZ * INNER) / 4;         // 262144
    if (idx < n1) {
        float4 v = reinterpret_cast<const float4*>(w1)[idx];
        uint2 pk = {h2u(v.x, v.y), h2u(v.z, v.w)};
        reinterpret_cast<uint2*>(o1)[idx] = pk;
    } else if (idx < n1 + n2) {
        float4 v = reinterpret_cast<const float4*>(w2)[idx - n1];
        uint2 pk = {h2u(v.x, v.y), h2u(v.z, v.w)};
        reinterpret_cast<uint2*>(o2)[idx - n1] = pk;
    }
}

// ---------------- fp16 warp-mma GEMM, BK=64, natural-layout B ----------------
// C[M,Ntot] = A[M,1024] @ B[1024,Ntot], fp16 in, fp32 accum.
// A row-major (ldm4), B natural [K][N] (ldm4t, XOR-swizzled 256B rows).
// CTA 128x128, 8 warps (2m x 4n), warp tile 64x32. 3-stage cp.async ring,
// wait_group 1, one sync/iter, 2 CTAs/SM. Per chunk: 24 LDSM + 64 HMMA.
#define HS_AROW   144
#define HS_AARR   (128 * HS_AROW)      // 18432
#define HS_BARR   (64 * 256)           // 16384
#define HS_STAGE  (HS_AARR + HS_BARR)  // 34816
#define HS_NSTAGE 3
#define HS_SMEM   (HS_NSTAGE * HS_STAGE)   // 104448

template <bool HALF_OUT>
__global__ void __launch_bounds__(256, 2) hf_gemm_kernel(
    const __half* __restrict__ A, const __half* __restrict__ B,
    const float* __restrict__ bias, void* __restrict__ Cv, int Ntot)
{
    extern __shared__ char sm[];
    const int tid = threadIdx.x, lane = tid & 31, wid = tid >> 5;
    const int wm = wid >> 2, wn = wid & 3;
    const int c0 = blockIdx.x * 128, r0 = blockIdx.y * 128;
    const int lr = lane >> 2, lc = lane & 3;
    uint32_t sbase = smem_u32(sm);

    // per stage: A 128 rows*128B (1024 cp16) + B 64 rows*256B (1024 cp16)
    auto issue = [&](int c, int st) {
        int k0 = c * 64;
        uint32_t sb = sbase + st * HS_STAGE;
        #pragma unroll
        for (int i = 0; i < 8; i++) {
            int q = tid + i * 256;
            if (q < 1024) {                      // A (i = 0..3)
                int row = q >> 3, seg = q & 7;
                cp16(sb + row * HS_AROW + seg * 16,
                     A + (size_t)(r0 + row) * 1024 + k0 + seg * 8);
            } else {                             // B (i = 4..7)
                int rem = q - 1024;
                int row = rem >> 4, seg = rem & 15;
                uint32_t off = (uint32_t)(row * 256 + seg * 16);
                off ^= (uint32_t)(row & 7) << 4;
                cp16(sb + HS_AARR + off,
                     B + (size_t)(k0 + row) * Ntot + c0 + seg * 8);
            }
        }
        asm volatile("cp.async.commit_group;" ::: "memory");
    };

    float acc[4][4][4];
    #pragma unroll
    for (int a = 0; a < 4; a++)
        #pragma unroll
        for (int b = 0; b < 4; b++)
            #pragma unroll
            for (int cc = 0; cc < 4; cc++) acc[a][b][cc] = 0.f;

    issue(0, 0);
    issue(1, 1);

    const int mat  = lane >> 3;
    const int roff = (mat & 1) * 8 + (lane & 7);
    const int cofs = (mat >> 1) * 16;
    const uint32_t swzB = (uint32_t)(lane & 7) << 4;

    const int NCHUNK = 1024 / 64;   // 16
    int st = 0;
    for (int c = 0; c < NCHUNK; c++) {
        asm volatile("cp.async.wait_group 1;" ::: "memory");
        __syncthreads();

        int st2 = st + 2; if (st2 >= 3) st2 -= 3;
        if (c + 2 < NCHUNK) issue(c + 2, st2);
        else asm volatile("cp.async.commit_group;" ::: "memory");

        uint32_t base = sbase + st * HS_STAGE;

        #pragma unroll
        for (int ks = 0; ks < 4; ks++) {
            uint32_t ah[4][4], bh[2][4];
            #pragma unroll
            for (int nt2 = 0; nt2 < 2; nt2++) {
                uint32_t off = (uint32_t)((ks*16 + roff) * 256
                                          + wn*64 + nt2*32 + cofs) ^ swzB;
                ldm4t(bh[nt2], base + HS_AARR + off);
            }
            #pragma unroll
            for (int mt = 0; mt < 4; mt++)
                ldm4(ah[mt], base + (wm*64 + mt*16 + roff) * HS_AROW
                              + ks*32 + cofs);

            #pragma unroll
            for (int mt = 0; mt < 4; mt++)
                #pragma unroll
                for (int nt = 0; nt < 4; nt++) {
                    int n2 = nt >> 1, hf = nt & 1;
                    mma_f16(acc[mt][nt], ah[mt], bh[n2][2*hf], bh[n2][2*hf+1]);
                }
        }
        if (++st >= 3) st = 0;
    }

    #pragma unroll
    for (int mt = 0; mt < 4; mt++) {
        int rbase = r0 + wm*64 + mt*16 + lr;
        #pragma unroll
        for (int nt = 0; nt < 4; nt++) {
            int col = c0 + wn*32 + nt*8 + 2*lc;
            if (HALF_OUT) {
                __half* C = (__half*)Cv;
                float sc = (col < 1024) ? 0.125f : 1.0f;   // Q prescale
                *reinterpret_cast<uint32_t*>(C + (size_t)rbase * Ntot + col) =
                    h2u(acc[mt][nt][0] * sc, acc[mt][nt][1] * sc);
                *reinterpret_cast<uint32_t*>(C + (size_t)(rbase + 8) * Ntot + col) =
                    h2u(acc[mt][nt][2] * sc, acc[mt][nt][3] * sc);
            } else {
                float* C = (float*)Cv;
                float b0v = bias ? bias[col] : 0.f;
                float b1v = bias ? bias[col + 1] : 0.f;
                float2 v0 = {acc[mt][nt][0] + b0v, acc[mt][nt][1] + b1v};
                float2 v1 = {acc[mt][nt][2] + b0v, acc[mt][nt][3] + b1v};
                *reinterpret_cast<float2*>(C + (size_t)rbase * Ntot + col) = v0;
                *reinterpret_cast<float2*>(C + (size_t)(rbase + 8) * Ntot + col) = v1;
            }
        }
    }
}

// ---------------- flash attention: fp16 QK (ldmatrix K) + f16x2 softmax ------
#define FA_QS    18432                    // Q: 128 * 144
#define FA_KB    9216                     // K stage: 64 * 144
#define FA_VB    8192                     // V stage: 64 * 128
#define FA_STAGE (FA_KB + FA_VB)          // 17408
#define FAH_SMEM (FA_QS + 2 * FA_STAGE)   // 53248

__global__ void __launch_bounds__(256, 2) fa_kernel(
    const __half* __restrict__ qkv, __half* __restrict__ outh)
{
    extern __shared__ char sm[];
    const int tid = threadIdx.x, lane = tid & 31, wid = tid >> 5;
    const int qt = blockIdx.x, hd = blockIdx.y, b = blockIdx.z;
    const int n0 = qt * 128;
    const int lr = lane >> 2, lc = lane & 3;
    uint32_t sbase = smem_u32(sm);

    const __half* qb = qkv + (size_t)b * SEQ * QKV3 + hd * DHEAD;
    const __half* kb = qb + 1024;
    const __half* vb = qb + 2048;

    #pragma unroll
    for (int i = 0; i < 4; i++) {
        int q = tid + i * 256;
        int row = q >> 3, ch = q & 7;
        cp16(sbase + row * 144 + ch * 16,
             qb + (size_t)(n0 + row) * QKV3 + ch * 8);
    }
    asm volatile("cp.async.commit_group;" ::: "memory");

    auto issueKV = [&](int kt, int st) {
        int s0 = kt * 64;
        uint32_t kbase = sbase + FA_QS + st * FA_STAGE;
        uint32_t vbase = kbase + FA_KB;
        #pragma unroll
        for (int i = 0; i < 4; i++) {
            int q = tid + i * 256;
            int arr = q >> 9, rem = q & 511;
            int row = rem >> 3, ch = rem & 7;
            if (arr == 0) {
                cp16(kbase + row * 144 + ch * 16,
                     kb + (size_t)(s0 + row) * QKV3 + ch * 8);
            } else {
                uint32_t off = (uint32_t)(row * 128 + ch * 16);
                off ^= ((off >> 7) & 7) << 4;
                cp16(vbase + off, vb + (size_t)(s0 + row) * QKV3 + ch * 8);
            }
        }
        asm volatile("cp.async.commit_group;" ::: "memory");
    };

    issueKV(0, 0);
    asm volatile("cp.async.wait_group 0;" ::: "memory");
    __syncthreads();

    const uint32_t* Qs = reinterpret_cast<const uint32_t*>(sm);
    uint32_t qa[4][4];
    {
        int m0 = wid * 16;
        #pragma unroll
        for (int u = 0; u < 4; u++) {
            qa[u][0] = Qs[(m0 + lr)     * 36 + u*8 + lc];
            qa[u][1] = Qs[(m0 + 8 + lr) * 36 + u*8 + lc];
            qa[u][2] = Qs[(m0 + lr)     * 36 + u*8 + lc + 4];
            qa[u][3] = Qs[(m0 + 8 + lr) * 36 + u*8 + lc + 4];
        }
    }

    const int mat  = lane >> 3;
    const int roff = (mat & 1) * 8 + (lane & 7);
    const int cofs = (mat >> 1) * 16;
    const float LOG2E = 1.44269504f;

    float m_i[2] = {-1e30f, -1e30f}, l_i[2] = {0.f, 0.f};
    float o[8][4];
    #pragma unroll
    for (int v = 0; v < 8; v++)
        #pragma unroll
        for (int j = 0; j < 4; j++) o[v][j] = 0.f;

    const int NT = SEQ / 64;   // 32
    for (int kt = 0; kt < NT; kt++) {
        if (kt > 0) {
            asm volatile("cp.async.wait_group 0;" ::: "memory");
            __syncthreads();
        }
        if (kt + 1 < NT) issueKV(kt + 1, (kt + 1) & 1);

        int st = kt & 1;
        uint32_t kbase = sbase + FA_QS + st * FA_STAGE;
        const uint32_t vsb = kbase + FA_KB;

        float s[8][4];
        #pragma unroll
        for (int v = 0; v < 8; v++)
            #pragma unroll
            for (int j = 0; j < 4; j++) s[v][j] = 0.f;
        #pragma unroll
        for (int u = 0; u < 4; u++) {
            uint32_t bh[4][4];
            #pragma unroll
            for (int g = 0; g < 4; g++)
                ldm4(bh[g], kbase + (g*16 + roff) * 144 + u*32 + cofs);
            #pragma unroll
            for (int v = 0; v < 8; v++) {
                int g = v >> 1, hf = v & 1;
                mma_f16(s[v], qa[u], bh[g][hf], bh[g][2+hf]);
            }
        }

        // online softmax: f16x2 ex2; O-rescale gated on any max update
        uint32_t ph[8][2];
        float alpha[2];
        #pragma unroll
        for (int h = 0; h < 2; h++) {
            float mx = -1e30f;
            #pragma unroll
            for (int v = 0; v < 8; v++)
                mx = fmaxf(mx, fmaxf(s[v][2*h], s[v][2*h+1]));
            mx = fmaxf(mx, __shfl_xor_sync(0xffffffffu, mx, 1));
            mx = fmaxf(mx, __shfl_xor_sync(0xffffffffu, mx, 2));
            float mnew = fmaxf(m_i[h], mx);
            alpha[h] = __expf(m_i[h] - mnew);
            m_i[h] = mnew;
            float cbias = mnew * LOG2E;
            float rs = 0.f;
            #pragma unroll
            for (int v = 0; v < 8; v++) {
                uint32_t arg = h2u(fmaf(s[v][2*h],   LOG2E, -cbias),
                                   fmaf(s[v][2*h+1], LOG2E, -cbias));
                uint32_t pe = ex2_h2(arg);
                ph[v][h] = pe;
                float2 pf = __half22float2(*reinterpret_cast<__half2*>(&pe));
                rs += pf.x + pf.y;
            }
            rs += __shfl_xor_sync(0xffffffffu, rs, 1);
            rs += __shfl_xor_sync(0xffffffffu, rs, 2);
            l_i[h] = l_i[h] * alpha[h] + rs;
        }
        if (__any_sync(0xffffffffu, (alpha[0] != 1.0f) || (alpha[1] != 1.0f))) {
            #pragma unroll
            for (int v = 0; v < 8; v++) {
                o[v][0] *= alpha[0]; o[v][1] *= alpha[0];
                o[v][2] *= alpha[1]; o[v][3] *= alpha[1];
            }
        }

        #pragma unroll
        for (int u = 0; u < 4; u++) {
            uint32_t pa[4] = {ph[2*u][0], ph[2*u][1], ph[2*u+1][0], ph[2*u+1][1]};
            #pragma unroll
            for (int w2 = 0; w2 < 4; w2++) {
                int row = u*16 + (mat & 1) * 8 + (lane & 7);
                int colb = w2*32 + (mat >> 1) * 16;
                uint32_t off = (uint32_t)(row * 128 + colb);
                off ^= ((off >> 7) & 7) << 4;
                uint32_t r[4];
                ldm4t(r, vsb + off);
                mma_f16(o[2*w2],     pa, r[0], r[1]);
                mma_f16(o[2*w2 + 1], pa, r[2], r[3]);
            }
        }
    }

    #pragma unroll
    for (int h = 0; h < 2; h++) {
        float inv = 1.f / l_i[h];
        int rowg = b * SEQ + n0 + wid*16 + h*8 + lr;
        #pragma unroll
        for (int v = 0; v < 8; v++) {
            int col = hd * 64 + v*8 + 2*lc;
            uint32_t pk = h2u(o[v][2*h] * inv, o[v][2*h+1] * inv);
            *reinterpret_cast<uint32_t*>(outh + (size_t)rowg * INNER + col) = pk;
        }
    }
}

// ---------------- launcher ---------------------------------------------------
extern "C" void kernel_launch(void* const* d_in, const int* in_sizes, int n_in,
                              void* d_out, int out_size)
{
    const float* x     = (const float*)d_in[0];
    const float* gamma = (const float*)d_in[1];
    const float* beta  = (const float*)d_in[2];
    const float* Wqkv  = (const float*)d_in[3];
    const float* Wout  = (const float*)d_in[4];
    const float* bout  = (const float*)d_in[5];
    float* out = (float*)d_out;

    __half *qkvh, *xnh, *wqh, *woh, *aoh;
    cudaGetSymbolAddress((void**)&qkvh, g_qkvh);
    cudaGetSymbolAddress((void**)&xnh, g_xnh);
    cudaGetSymbolAddress((void**)&wqh, g_wqh);
    cudaGetSymbolAddress((void**)&woh, g_woh);
    cudaGetSymbolAddress((void**)&aoh, g_aoh);

    cudaFuncSetAttribute(hf_gemm_kernel<true>,
                         cudaFuncAttributeMaxDynamicSharedMemorySize, HS_SMEM);
    cudaFuncSetAttribute(hf_gemm_kernel<false>,
                         cudaFuncAttributeMaxDynamicSharedMemorySize, HS_SMEM);
    cudaFuncSetAttribute(fa_kernel,
                         cudaFuncAttributeMaxDynamicSharedMemorySize, FAH_SMEM);

    ln_kernel<<<ROWS, 256>>>(x, gamma, beta, xnh);

    // fp32 -> fp16 weight convert (natural layout), both weights in one launch
    convert_kernel<<<(QKV3 * DIMSZ + DIMSZ * INNER) / 4 / 256, 256>>>(
        Wqkv, Wout, wqh, woh);

    hf_gemm_kernel<true><<<dim3(QKV3 / 128, ROWS / 128), 256, HS_SMEM>>>(
        xnh, wqh, nullptr, qkvh, QKV3);

    fa_kernel<<<dim3(SEQ / 128, HEADS, BATCH), 256, FAH_SMEM>>>(qkvh, aoh);

    hf_gemm_kernel<false><<<dim3(DIMSZ / 128, ROWS / 128), 256, HS_SMEM>>>(
        aoh, woh, bout, out, DIMSZ);
}

// round 15
// speedup vs baseline: 3.0183x; 1.0593x over previous
#include <cuda_runtime.h>
#include <cuda_bf16.h>
#include <cuda_fp16.h>
#include <cstdint>

#define BATCH 2
#define SEQ   2048
#define DIMSZ 1024
#define HEADS 16
#define DHEAD 64
#define INNER 1024
#define QKV3  3072
#define ROWS  (BATCH * SEQ)   // 4096

// ---------------- scratch (static device globals; no allocation) -------------
__device__ __half g_qkvh[ROWS * QKV3];    // 25 MB fp16 (Q prescaled by 0.125)
__device__ __half g_xnh[ROWS * DIMSZ];    // LN out fp16
__device__ __half g_wqh[DIMSZ * QKV3];    // Wqkv fp16, natural [K][N]
__device__ __half g_woh[INNER * DIMSZ];   // Wout fp16, natural [K][N]
__device__ __half g_aoh[ROWS * INNER];    // attention out fp16

// ---------------- helpers ----------------------------------------------------
__device__ __forceinline__ uint32_t smem_u32(const void* p) {
    uint32_t a;
    asm("{ .reg .u64 t; cvta.to.shared.u64 t, %1; cvt.u32.u64 %0, t; }"
        : "=r"(a) : "l"(p));
    return a;
}
__device__ __forceinline__ void cp16(uint32_t dst, const void* src) {
    asm volatile("cp.async.cg.shared.global [%0], [%1], 16;"
                 :: "r"(dst), "l"(src) : "memory");
}
__device__ __forceinline__ void ldm4(uint32_t* r, uint32_t addr) {
    asm volatile("ldmatrix.sync.aligned.m8n8.x4.shared.b16 {%0,%1,%2,%3}, [%4];"
        : "=r"(r[0]), "=r"(r[1]), "=r"(r[2]), "=r"(r[3]) : "r"(addr));
}
__device__ __forceinline__ void ldm4t(uint32_t* r, uint32_t addr) {
    asm volatile("ldmatrix.sync.aligned.m8n8.x4.trans.shared.b16 {%0,%1,%2,%3}, [%4];"
        : "=r"(r[0]), "=r"(r[1]), "=r"(r[2]), "=r"(r[3]) : "r"(addr));
}
__device__ __forceinline__ void mma_f16(float* d, const uint32_t* a,
                                        uint32_t b0, uint32_t b1) {
    asm volatile("mma.sync.aligned.m16n8k16.row.col.f32.f16.f16.f32 "
        "{%0,%1,%2,%3}, {%4,%5,%6,%7}, {%8,%9}, {%0,%1,%2,%3};"
        : "+f"(d[0]), "+f"(d[1]), "+f"(d[2]), "+f"(d[3])
        : "r"(a[0]), "r"(a[1]), "r"(a[2]), "r"(a[3]), "r"(b0), "r"(b1));
}
__device__ __forceinline__ uint32_t h2u(float a, float b) {
    __half2 h = __floats2half2_rn(a, b);
    return *reinterpret_cast<uint32_t*>(&h);
}
__device__ __forceinline__ uint32_t ex2_h2(uint32_t packed) {
    uint32_t r;
    asm("ex2.approx.f16x2 %0, %1;" : "=r"(r) : "r"(packed));
    return r;
}
__device__ __forceinline__ uint32_t hadd2u(uint32_t a, uint32_t b) {
    uint32_t r;
    asm("add.f16x2 %0, %1, %2;" : "=r"(r) : "r"(a), "r"(b));
    return r;
}

// ------------- fused LayerNorm (blocks < ROWS) + weight convert --------------
#define CONV_N1 ((QKV3 * DIMSZ) / 4)      // 786432 float4
#define CONV_N2 ((DIMSZ * INNER) / 4)     // 262144 float4
#define CONV_BLOCKS ((CONV_N1 + CONV_N2) / 256)   // 4096

__global__ void __launch_bounds__(256) ln_conv_kernel(
    const float* __restrict__ x, const float* __restrict__ gamma,
    const float* __restrict__ beta, __half* __restrict__ o,
    const float* __restrict__ w1, const float* __restrict__ w2,
    __half* __restrict__ o1, __half* __restrict__ o2)
{
    int t = threadIdx.x;
    if (blockIdx.x >= ROWS) {
        int idx = (blockIdx.x - ROWS) * 256 + t;
        if (idx < CONV_N1) {
            float4 v = reinterpret_cast<const float4*>(w1)[idx];
            uint2 pk = {h2u(v.x, v.y), h2u(v.z, v.w)};
            reinterpret_cast<uint2*>(o1)[idx] = pk;
        } else {
            float4 v = reinterpret_cast<const float4*>(w2)[idx - CONV_N1];
            uint2 pk = {h2u(v.x, v.y), h2u(v.z, v.w)};
            reinterpret_cast<uint2*>(o2)[idx - CONV_N1] = pk;
        }
        return;
    }
    int row = blockIdx.x;
    const float4* xr = reinterpret_cast<const float4*>(x + (size_t)row * DIMSZ);
    float4 v = xr[t];
    float s  = v.x + v.y + v.z + v.w;
    float ss = v.x*v.x + v.y*v.y + v.z*v.z + v.w*v.w;
    #pragma unroll
    for (int off = 16; off; off >>= 1) {
        s  += __shfl_xor_sync(0xffffffffu, s,  off);
        ss += __shfl_xor_sync(0xffffffffu, ss, off);
    }
    __shared__ float sbuf[8], ssbuf[8];
    __shared__ float s_mu, s_rstd;
    int w = t >> 5, lane = t & 31;
    if (lane == 0) { sbuf[w] = s; ssbuf[w] = ss; }
    __syncthreads();
    if (t == 0) {
        float S = 0.f, SS = 0.f;
        #pragma unroll
        for (int i = 0; i < 8; i++) { S += sbuf[i]; SS += ssbuf[i]; }
        float mu = S * (1.0f / DIMSZ);
        float var = SS * (1.0f / DIMSZ) - mu * mu;
        s_mu = mu; s_rstd = rsqrtf(var + 1e-5f);
    }
    __syncthreads();
    float mu = s_mu, rstd = s_rstd;
    float4 g  = reinterpret_cast<const float4*>(gamma)[t];
    float4 bt = reinterpret_cast<const float4*>(beta)[t];
    float o0 = (v.x - mu) * rstd * g.x + bt.x;
    float o1v = (v.y - mu) * rstd * g.y + bt.y;
    float o2v = (v.z - mu) * rstd * g.z + bt.z;
    float o3 = (v.w - mu) * rstd * g.w + bt.w;
    uint2 pk = {h2u(o0, o1v), h2u(o2v, o3)};
    *reinterpret_cast<uint2*>(o + (size_t)row * DIMSZ + t * 4) = pk;
}

// ---------------- fp16 warp-mma GEMM, BK=64, natural-layout B ----------------
#define HS_AROW   144
#define HS_AARR   (128 * HS_AROW)      // 18432
#define HS_BARR   (64 * 256)           // 16384
#define HS_STAGE  (HS_AARR + HS_BARR)  // 34816
#define HS_NSTAGE 3
#define HS_SMEM   (HS_NSTAGE * HS_STAGE)   // 104448

template <bool HALF_OUT>
__global__ void __launch_bounds__(256, 2) hf_gemm_kernel(
    const __half* __restrict__ A, const __half* __restrict__ B,
    const float* __restrict__ bias, void* __restrict__ Cv, int Ntot)
{
    extern __shared__ char sm[];
    const int tid = threadIdx.x, lane = tid & 31, wid = tid >> 5;
    const int wm = wid >> 2, wn = wid & 3;
    const int c0 = blockIdx.x * 128, r0 = blockIdx.y * 128;
    const int lr = lane >> 2, lc = lane & 3;
    uint32_t sbase = smem_u32(sm);

    auto issue = [&](int c, int st) {
        int k0 = c * 64;
        uint32_t sb = sbase + st * HS_STAGE;
        #pragma unroll
        for (int i = 0; i < 8; i++) {
            int q = tid + i * 256;
            if (q < 1024) {
                int row = q >> 3, seg = q & 7;
                cp16(sb + row * HS_AROW + seg * 16,
                     A + (size_t)(r0 + row) * 1024 + k0 + seg * 8);
            } else {
                int rem = q - 1024;
                int row = rem >> 4, seg = rem & 15;
                uint32_t off = (uint32_t)(row * 256 + seg * 16);
                off ^= (uint32_t)(row & 7) << 4;
                cp16(sb + HS_AARR + off,
                     B + (size_t)(k0 + row) * Ntot + c0 + seg * 8);
            }
        }
        asm volatile("cp.async.commit_group;" ::: "memory");
    };

    float acc[4][4][4];
    #pragma unroll
    for (int a = 0; a < 4; a++)
        #pragma unroll
        for (int b = 0; b < 4; b++)
            #pragma unroll
            for (int cc = 0; cc < 4; cc++) acc[a][b][cc] = 0.f;

    issue(0, 0);
    issue(1, 1);

    const int mat  = lane >> 3;
    const int roff = (mat & 1) * 8 + (lane & 7);
    const int cofs = (mat >> 1) * 16;
    const uint32_t swzB = (uint32_t)(lane & 7) << 4;

    const int NCHUNK = 1024 / 64;   // 16
    int st = 0;
    for (int c = 0; c < NCHUNK; c++) {
        asm volatile("cp.async.wait_group 1;" ::: "memory");
        __syncthreads();

        int st2 = st + 2; if (st2 >= 3) st2 -= 3;
        if (c + 2 < NCHUNK) issue(c + 2, st2);
        else asm volatile("cp.async.commit_group;" ::: "memory");

        uint32_t base = sbase + st * HS_STAGE;

        #pragma unroll
        for (int ks = 0; ks < 4; ks++) {
            uint32_t ah[4][4], bh[2][4];
            #pragma unroll
            for (int nt2 = 0; nt2 < 2; nt2++) {
                uint32_t off = (uint32_t)((ks*16 + roff) * 256
                                          + wn*64 + nt2*32 + cofs) ^ swzB;
                ldm4t(bh[nt2], base + HS_AARR + off);
            }
            #pragma unroll
            for (int mt = 0; mt < 4; mt++)
                ldm4(ah[mt], base + (wm*64 + mt*16 + roff) * HS_AROW
                              + ks*32 + cofs);

            #pragma unroll
            for (int mt = 0; mt < 4; mt++)
                #pragma unroll
                for (int nt = 0; nt < 4; nt++) {
                    int n2 = nt >> 1, hf = nt & 1;
                    mma_f16(acc[mt][nt], ah[mt], bh[n2][2*hf], bh[n2][2*hf+1]);
                }
        }
        if (++st >= 3) st = 0;
    }

    #pragma unroll
    for (int mt = 0; mt < 4; mt++) {
        int rbase = r0 + wm*64 + mt*16 + lr;
        #pragma unroll
        for (int nt = 0; nt < 4; nt++) {
            int col = c0 + wn*32 + nt*8 + 2*lc;
            if (HALF_OUT) {
                __half* C = (__half*)Cv;
                float sc = (col < 1024) ? 0.125f : 1.0f;   // Q prescale
                *reinterpret_cast<uint32_t*>(C + (size_t)rbase * Ntot + col) =
                    h2u(acc[mt][nt][0] * sc, acc[mt][nt][1] * sc);
                *reinterpret_cast<uint32_t*>(C + (size_t)(rbase + 8) * Ntot + col) =
                    h2u(acc[mt][nt][2] * sc, acc[mt][nt][3] * sc);
            } else {
                float* C = (float*)Cv;
                float b0v = bias ? bias[col] : 0.f;
                float b1v = bias ? bias[col + 1] : 0.f;
                float2 v0 = {acc[mt][nt][0] + b0v, acc[mt][nt][1] + b1v};
                float2 v1 = {acc[mt][nt][2] + b0v, acc[mt][nt][3] + b1v};
                *reinterpret_cast<float2*>(C + (size_t)rbase * Ntot + col) = v0;
                *reinterpret_cast<float2*>(C + (size_t)(rbase + 8) * Ntot + col) = v1;
            }
        }
    }
}

// ---------------- flash attention: fp16 QK + f16x2 softmax -------------------
// Deferred l quad-reduction (epilogue) + half2 partial-sum tree.
#define FA_QS    18432                    // Q: 128 * 144
#define FA_KB    9216                     // K stage: 64 * 144
#define FA_VB    8192                     // V stage: 64 * 128
#define FA_STAGE (FA_KB + FA_VB)          // 17408
#define FAH_SMEM (FA_QS + 2 * FA_STAGE)   // 53248

__global__ void __launch_bounds__(256, 2) fa_kernel(
    const __half* __restrict__ qkv, __half* __restrict__ outh)
{
    extern __shared__ char sm[];
    const int tid = threadIdx.x, lane = tid & 31, wid = tid >> 5;
    const int qt = blockIdx.x, hd = blockIdx.y, b = blockIdx.z;
    const int n0 = qt * 128;
    const int lr = lane >> 2, lc = lane & 3;
    uint32_t sbase = smem_u32(sm);

    const __half* qb = qkv + (size_t)b * SEQ * QKV3 + hd * DHEAD;
    const __half* kb = qb + 1024;
    const __half* vb = qb + 2048;

    #pragma unroll
    for (int i = 0; i < 4; i++) {
        int q = tid + i * 256;
        int row = q >> 3, ch = q & 7;
        cp16(sbase + row * 144 + ch * 16,
             qb + (size_t)(n0 + row) * QKV3 + ch * 8);
    }
    asm volatile("cp.async.commit_group;" ::: "memory");

    auto issueKV = [&](int kt, int st) {
        int s0 = kt * 64;
        uint32_t kbase = sbase + FA_QS + st * FA_STAGE;
        uint32_t vbase = kbase + FA_KB;
        #pragma unroll
        for (int i = 0; i < 4; i++) {
            int q = tid + i * 256;
            int arr = q >> 9, rem = q & 511;
            int row = rem >> 3, ch = rem & 7;
            if (arr == 0) {
                cp16(kbase + row * 144 + ch * 16,
                     kb + (size_t)(s0 + row) * QKV3 + ch * 8);
            } else {
                uint32_t off = (uint32_t)(row * 128 + ch * 16);
                off ^= ((off >> 7) & 7) << 4;
                cp16(vbase + off, vb + (size_t)(s0 + row) * QKV3 + ch * 8);
            }
        }
        asm volatile("cp.async.commit_group;" ::: "memory");
    };

    issueKV(0, 0);
    asm volatile("cp.async.wait_group 0;" ::: "memory");
    __syncthreads();

    const uint32_t* Qs = reinterpret_cast<const uint32_t*>(sm);
    uint32_t qa[4][4];
    {
        int m0 = wid * 16;
        #pragma unroll
        for (int u = 0; u < 4; u++) {
            qa[u][0] = Qs[(m0 + lr)     * 36 + u*8 + lc];
            qa[u][1] = Qs[(m0 + 8 + lr) * 36 + u*8 + lc];
            qa[u][2] = Qs[(m0 + lr)     * 36 + u*8 + lc + 4];
            qa[u][3] = Qs[(m0 + 8 + lr) * 36 + u*8 + lc + 4];
        }
    }

    const int mat  = lane >> 3;
    const int roff = (mat & 1) * 8 + (lane & 7);
    const int cofs = (mat >> 1) * 16;
    const float LOG2E = 1.44269504f;

    float m_i[2] = {-1e30f, -1e30f};
    float l_p[2] = {0.f, 0.f};        // per-thread partial row sums
    float o[8][4];
    #pragma unroll
    for (int v = 0; v < 8; v++)
        #pragma unroll
        for (int j = 0; j < 4; j++) o[v][j] = 0.f;

    const int NT = SEQ / 64;   // 32
    for (int kt = 0; kt < NT; kt++) {
        if (kt > 0) {
            asm volatile("cp.async.wait_group 0;" ::: "memory");
            __syncthreads();
        }
        if (kt + 1 < NT) issueKV(kt + 1, (kt + 1) & 1);

        int st = kt & 1;
        uint32_t kbase = sbase + FA_QS + st * FA_STAGE;
        const uint32_t vsb = kbase + FA_KB;

        float s[8][4];
        #pragma unroll
        for (int v = 0; v < 8; v++)
            #pragma unroll
            for (int j = 0; j < 4; j++) s[v][j] = 0.f;
        #pragma unroll
        for (int u = 0; u < 4; u++) {
            uint32_t bh[4][4];
            #pragma unroll
            for (int g = 0; g < 4; g++)
                ldm4(bh[g], kbase + (g*16 + roff) * 144 + u*32 + cofs);
            #pragma unroll
            for (int v = 0; v < 8; v++) {
                int g = v >> 1, hf = v & 1;
                mma_f16(s[v], qa[u], bh[g][hf], bh[g][2+hf]);
            }
        }

        // online softmax; deferred l reduction, half2 sum tree
        uint32_t ph[8][2];
        float alpha[2];
        #pragma unroll
        for (int h = 0; h < 2; h++) {
            float mx = -1e30f;
            #pragma unroll
            for (int v = 0; v < 8; v++)
                mx = fmaxf(mx, fmaxf(s[v][2*h], s[v][2*h+1]));
            mx = fmaxf(mx, __shfl_xor_sync(0xffffffffu, mx, 1));
            mx = fmaxf(mx, __shfl_xor_sync(0xffffffffu, mx, 2));
            float mnew = fmaxf(m_i[h], mx);
            alpha[h] = __expf(m_i[h] - mnew);
            m_i[h] = mnew;
            float cbias = mnew * LOG2E;
            #pragma unroll
            for (int v = 0; v < 8; v++) {
                uint32_t arg = h2u(fmaf(s[v][2*h],   LOG2E, -cbias),
                                   fmaf(s[v][2*h+1], LOG2E, -cbias));
                ph[v][h] = ex2_h2(arg);
            }
            // two-level half2 tree (magnitude <= 4, error ~2^-10 rel)
            uint32_t t0 = hadd2u(ph[0][h], ph[1][h]);
            uint32_t t1 = hadd2u(ph[2][h], ph[3][h]);
            uint32_t t2 = hadd2u(ph[4][h], ph[5][h]);
            uint32_t t3 = hadd2u(ph[6][h], ph[7][h]);
            uint32_t q0 = hadd2u(t0, t1);
            uint32_t q1 = hadd2u(t2, t3);
            float2 f0 = __half22float2(*reinterpret_cast<__half2*>(&q0));
            float2 f1 = __half22float2(*reinterpret_cast<__half2*>(&q1));
            float rs = (f0.x + f0.y) + (f1.x + f1.y);
            l_p[h] = l_p[h] * alpha[h] + rs;
        }
        if (__any_sync(0xffffffffu, (alpha[0] != 1.0f) || (alpha[1] != 1.0f))) {
            #pragma unroll
            for (int v = 0; v < 8; v++) {
                o[v][0] *= alpha[0]; o[v][1] *= alpha[0];
                o[v][2] *= alpha[1]; o[v][3] *= alpha[1];
            }
        }

        #pragma unroll
        for (int u = 0; u < 4; u++) {
            uint32_t pa[4] = {ph[2*u][0], ph[2*u][1], ph[2*u+1][0], ph[2*u+1][1]};
            #pragma unroll
            for (int w2 = 0; w2 < 4; w2++) {
                int row = u*16 + (mat & 1) * 8 + (lane & 7);
                int colb = w2*32 + (mat >> 1) * 16;
                uint32_t off = (uint32_t)(row * 128 + colb);
                off ^= ((off >> 7) & 7) << 4;
                uint32_t r[4];
                ldm4t(r, vsb + off);
                mma_f16(o[2*w2],     pa, r[0], r[1]);
                mma_f16(o[2*w2 + 1], pa, r[2], r[3]);
            }
        }
    }

    // epilogue: quad-reduce l, normalize + fp16 store
    #pragma unroll
    for (int h = 0; h < 2; h++) {
        float lsum = l_p[h];
        lsum += __shfl_xor_sync(0xffffffffu, lsum, 1);
        lsum += __shfl_xor_sync(0xffffffffu, lsum, 2);
        float inv = 1.f / lsum;
        int rowg = b * SEQ + n0 + wid*16 + h*8 + lr;
        #pragma unroll
        for (int v = 0; v < 8; v++) {
            int col = hd * 64 + v*8 + 2*lc;
            uint32_t pk = h2u(o[v][2*h] * inv, o[v][2*h+1] * inv);
            *reinterpret_cast<uint32_t*>(outh + (size_t)rowg * INNER + col) = pk;
        }
    }
}

// ---------------- launcher ---------------------------------------------------
extern "C" void kernel_launch(void* const* d_in, const int* in_sizes, int n_in,
                              void* d_out, int out_size)
{
    const float* x     = (const float*)d_in[0];
    const float* gamma = (const float*)d_in[1];
    const float* beta  = (const float*)d_in[2];
    const float* Wqkv  = (const float*)d_in[3];
    const float* Wout  = (const float*)d_in[4];
    const float* bout  = (const float*)d_in[5];
    float* out = (float*)d_out;

    __half *qkvh, *xnh, *wqh, *woh, *aoh;
    cudaGetSymbolAddress((void**)&qkvh, g_qkvh);
    cudaGetSymbolAddress((void**)&xnh, g_xnh);
    cudaGetSymbolAddress((void**)&wqh, g_wqh);
    cudaGetSymbolAddress((void**)&woh, g_woh);
    cudaGetSymbolAddress((void**)&aoh, g_aoh);

    cudaFuncSetAttribute(hf_gemm_kernel<true>,
                         cudaFuncAttributeMaxDynamicSharedMemorySize, HS_SMEM);
    cudaFuncSetAttribute(hf_gemm_kernel<false>,
                         cudaFuncAttributeMaxDynamicSharedMemorySize, HS_SMEM);
    cudaFuncSetAttribute(fa_kernel,
                         cudaFuncAttributeMaxDynamicSharedMemorySize, FAH_SMEM);

    // fused LayerNorm + weight convert (one launch)
    ln_conv_kernel<<<ROWS + CONV_BLOCKS, 256>>>(
        x, gamma, beta, xnh, Wqkv, Wout, wqh, woh);

    hf_gemm_kernel<true><<<dim3(QKV3 / 128, ROWS / 128), 256, HS_SMEM>>>(
        xnh, wqh, nullptr, qkvh, QKV3);

    fa_kernel<<<dim3(SEQ / 128, HEADS, BATCH), 256, FAH_SMEM>>>(qkvh, aoh);

    hf_gemm_kernel<false><<<dim3(DIMSZ / 128, ROWS / 128), 256, HS_SMEM>>>(
        aoh, woh, bout, out, DIMSZ);
}